// round 10
// baseline (speedup 1.0000x reference)
#include <cuda_runtime.h>
#include <cuda_bf16.h>
#include <cuda_fp16.h>
#include <math.h>
#include <stdint.h>

// ---------------------------------------------------------------------------
// Problem constants
// ---------------------------------------------------------------------------
#define NBATCH   4
#define HDIM     128
#define WDIM     128
#define DM       768
#define NHEADS   12
#define DHEAD    64
#define DFF      2048
#define DC       768
#define WS       8
#define SHIFT    4
#define TOKENS   (NBATCH * HDIM * WDIM)          // 65536
#define NWIN     (NBATCH * NHEADS * 16 * 16)     // 12288
#define EPSV     1e-6f

// ---------------------------------------------------------------------------
// Scratch
// ---------------------------------------------------------------------------
#define W_QKV_SZ (3 * DM * DM)
#define W_OUT_SZ (DM * DM)
#define W_UP_SZ  (2 * DFF * DM)
#define W_DN_SZ  (DM * DFF)
#define W_TOTAL  (W_QKV_SZ + W_OUT_SZ + W_UP_SZ + W_DN_SZ)

__device__ float g_scale1[NBATCH * DM];
__device__ float g_scale2[NBATCH * DM];
__device__ float g_qkv [(size_t)TOKENS * 2 * DM];     // q,k fp32 (ldc=1536)
__device__ float g_vw  [(size_t)NWIN * 64 * 64];      // v windowed fp32
__device__ float g_x2  [(size_t)TOKENS * DM];

__device__ __half g_h  [(size_t)TOKENS * DM];         // activations fp16
__device__ __half g_oi [(size_t)TOKENS * DM];
__device__ __half g_a  [(size_t)TOKENS * DFF];
__device__ __half g_w  [W_TOTAL];                     // weights fp16 (single)

// ---------------------------------------------------------------------------
// PTX helpers
// ---------------------------------------------------------------------------
__device__ __forceinline__ uint32_t smem_to_u32(const void* p) {
    uint32_t a;
    asm("{ .reg .u64 t; cvta.to.shared.u64 t, %1; cvt.u32.u64 %0, t; }" : "=r"(a) : "l"(p));
    return a;
}
#define CP_ASYNC16(sa, gp) \
    asm volatile("cp.async.cg.shared.global [%0], [%1], 16;" :: "r"(sa), "l"(gp))
#define CP_COMMIT() asm volatile("cp.async.commit_group;" ::: "memory")
#define CP_WAIT1()  asm volatile("cp.async.wait_group 1;" ::: "memory")
#define CP_WAIT0()  asm volatile("cp.async.wait_group 0;" ::: "memory")

__device__ __forceinline__ void ldsm_x4(uint32_t& r0, uint32_t& r1, uint32_t& r2,
                                        uint32_t& r3, uint32_t addr) {
    asm volatile("ldmatrix.sync.aligned.m8n8.x4.shared.b16 {%0,%1,%2,%3}, [%4];"
                 : "=r"(r0), "=r"(r1), "=r"(r2), "=r"(r3) : "r"(addr));
}
__device__ __forceinline__ void mma_f16(float c[4], const uint32_t a[4],
                                        const uint32_t b[2]) {
    asm volatile("mma.sync.aligned.m16n8k16.row.col.f32.f16.f16.f32 "
                 "{%0,%1,%2,%3},{%4,%5,%6,%7},{%8,%9},{%0,%1,%2,%3};"
                 : "+f"(c[0]), "+f"(c[1]), "+f"(c[2]), "+f"(c[3])
                 : "r"(a[0]), "r"(a[1]), "r"(a[2]), "r"(a[3]),
                   "r"(b[0]), "r"(b[1]));
}

// packed 2xfp32 FMA (sm_100+; HW FFMA2 path)
typedef unsigned long long u64t;
__device__ __forceinline__ void ffma2(u64t& d, u64t a, u64t b) {
    asm("fma.rn.f32x2 %0, %1, %2, %0;" : "+l"(d) : "l"(a), "l"(b));
}
__device__ __forceinline__ u64t pack2(float x, float y) {
    u64t r;
    asm("mov.b64 %0, {%1, %2};" : "=l"(r) : "f"(x), "f"(y));
    return r;
}
__device__ __forceinline__ void unpack2(u64t v, float& x, float& y) {
    asm("mov.b64 {%0, %1}, %2;" : "=f"(x), "=f"(y) : "l"(v));
}

// window-scatter address helper (roll +4,+4 then 8x8 windows)
__device__ __forceinline__ size_t win_addr(int t, int h, int e) {
    int n = t >> 14;
    int y = (t >> 7) & 127;
    int x = t & 127;
    int Y = (y + SHIFT) & 127, X = (x + SHIFT) & 127;
    int wyx  = ((Y >> 3) << 4) + (X >> 3);
    int spos = ((Y & 7) << 3) + (X & 7);
    return ((size_t)((n * NHEADS + h) * 256 + wyx)) * 4096 + (size_t)spos * 64 + e;
}

// inverse: window b, slot r -> token index
__device__ __forceinline__ int win_token(int b, int r) {
    int n   = b / (NHEADS * 256);
    int rem = b % (NHEADS * 256);
    int w   = rem & 255;
    int Y = ((w >> 4) << 3) + (r >> 3);
    int X = ((w & 15) << 3) + (r & 7);
    int y = (Y - SHIFT) & 127, x = (X - SHIFT) & 127;
    return (n << 14) + (y << 7) + x;
}

// ---------------------------------------------------------------------------
// GEMM (R8 config, proven): C = (D?D:0) + A @ B^T. fp16 x fp16, fp32 accum.
// CTA tile 128x256x32, 8 warps (2m x 4n), warp tile 64x64, 2-stage cp.async.
// ---------------------------------------------------------------------------
#define BKC      32
#define PADK     40
#define TILE_A_E (128 * PADK)
#define TILE_B_E (256 * PADK)
#define STAGE_E  (TILE_A_E + TILE_B_E)       // 15360 elems
#define GEMM_SMEM (2 * STAGE_E * 2)          // 61440 bytes

__global__ __launch_bounds__(256) void hgemm_kernel(
    const __half* __restrict__ A, const __half* __restrict__ B,
    const float* __restrict__ Dres, float* __restrict__ C,
    int M, int N, int K, int ldc, int mode)
{
    extern __shared__ __align__(128) char smem[];
    const uint32_t sbase = smem_to_u32(smem);
    const int tid = threadIdx.x, lane = tid & 31, wid = tid >> 5;
    const int wm = wid >> 2, wn = wid & 3;
    const size_t bm = (size_t)blockIdx.y * 128;
    const size_t bn = (size_t)blockIdx.x * 256;

    const __half* Ab = A + bm * (size_t)K;
    const __half* Bb = B + bn * (size_t)K;

    float acc[4][8][4];
    #pragma unroll
    for (int i = 0; i < 4; i++)
        #pragma unroll
        for (int j = 0; j < 8; j++)
            #pragma unroll
            for (int l = 0; l < 4; l++) acc[i][j][l] = 0.f;

    const int nstage = K / BKC;

    auto issue = [&](int st) {
        const int k0 = st * BKC;
        const uint32_t sb = sbase + (uint32_t)((st & 1) * STAGE_E * 2);
        #pragma unroll
        for (int i = 0; i < 2; i++) {
            int idx = tid + i * 256;
            int row = idx >> 2, seg = (idx & 3) << 3;
            const __half* gp = Ab + (size_t)row * K + k0 + seg;
            uint32_t sa = sb + (uint32_t)((row * PADK + seg) * 2);
            CP_ASYNC16(sa, gp);
        }
        #pragma unroll
        for (int i = 0; i < 4; i++) {
            int idx = tid + i * 256;
            int row = idx >> 2, seg = (idx & 3) << 3;
            const __half* gp = Bb + (size_t)row * K + k0 + seg;
            uint32_t sa = sb + (uint32_t)((TILE_A_E + row * PADK + seg) * 2);
            CP_ASYNC16(sa, gp);
        }
        CP_COMMIT();
    };

    issue(0);
    if (nstage > 1) issue(1);

    const int a_r = lane & 15, a_h = (lane >> 4) << 3;
    const int b_r = (lane & 7) + ((lane & 16) >> 1);
    const int b_k = lane & 8;

    for (int st = 0; st < nstage; st++) {
        if (st + 1 < nstage) { CP_WAIT1(); } else { CP_WAIT0(); }
        __syncthreads();

        const uint32_t sb = sbase + (uint32_t)((st & 1) * STAGE_E * 2);
        const uint32_t sA = sb;
        const uint32_t sB = sb + TILE_A_E * 2;

        #pragma unroll
        for (int kk = 0; kk < BKC; kk += 16) {
            uint32_t a[4][4], bh[8][2];
            #pragma unroll
            for (int mt = 0; mt < 4; mt++)
                ldsm_x4(a[mt][0], a[mt][1], a[mt][2], a[mt][3],
                        sA + (uint32_t)(((wm * 64 + mt * 16 + a_r) * PADK + kk + a_h) * 2));
            #pragma unroll
            for (int p = 0; p < 4; p++) {
                uint32_t r0, r1, r2, r3;
                ldsm_x4(r0, r1, r2, r3,
                        sB + (uint32_t)(((wn * 64 + p * 16 + b_r) * PADK + kk + b_k) * 2));
                bh[p * 2][0] = r0; bh[p * 2][1] = r1;
                bh[p * 2 + 1][0] = r2; bh[p * 2 + 1][1] = r3;
            }
            #pragma unroll
            for (int mt = 0; mt < 4; mt++)
                #pragma unroll
                for (int nt = 0; nt < 8; nt++)
                    mma_f16(acc[mt][nt], a[mt], bh[nt]);
        }
        __syncthreads();
        if (st + 2 < nstage) issue(st + 2);
    }

    const int er = lane >> 2, ec = (lane & 3) * 2;

    if (mode == 1) {
        #pragma unroll
        for (int mt = 0; mt < 4; mt++) {
            size_t r0 = bm + wm * 64 + mt * 16 + er;
            size_t r1 = r0 + 8;
            #pragma unroll
            for (int nt = 0; nt < 8; nt++) {
                int col = (int)bn + wn * 64 + nt * 8 + ec;
                int j = col >> 1;
                float a0 = acc[mt][nt][0], gg0 = acc[mt][nt][1];
                float a1 = acc[mt][nt][2], gg1 = acc[mt][nt][3];
                float v0 = a0 * (gg0 * 0.5f * (1.0f + erff(gg0 * 0.70710678118654752f)));
                float v1 = a1 * (gg1 * 0.5f * (1.0f + erff(gg1 * 0.70710678118654752f)));
                g_a[r0 * DFF + j] = __float2half(v0);
                g_a[r1 * DFF + j] = __float2half(v1);
            }
        }
        return;
    }

    if (mode == 2 && bn >= 1536) {
        #pragma unroll
        for (int mt = 0; mt < 4; mt++) {
            int t0 = (int)bm + wm * 64 + mt * 16 + er;
            int t1 = t0 + 8;
            #pragma unroll
            for (int nt = 0; nt < 8; nt++) {
                int col = (int)bn + wn * 64 + nt * 8 + ec;
                int h = (col - 1536) >> 6;
                int e = col & 63;
                float2 v0 = make_float2(acc[mt][nt][0], acc[mt][nt][1]);
                float2 v1 = make_float2(acc[mt][nt][2], acc[mt][nt][3]);
                *(float2*)&g_vw[win_addr(t0, h, e)] = v0;
                *(float2*)&g_vw[win_addr(t1, h, e)] = v1;
            }
        }
        return;
    }

    #pragma unroll
    for (int mt = 0; mt < 4; mt++) {
        size_t row0 = bm + wm * 64 + mt * 16 + er;
        #pragma unroll
        for (int nt = 0; nt < 8; nt++) {
            size_t col = bn + wn * 64 + nt * 8 + ec;
            float* p0 = C + row0 * (size_t)ldc + col;
            float* p1 = C + (row0 + 8) * (size_t)ldc + col;
            float2 v0 = make_float2(acc[mt][nt][0], acc[mt][nt][1]);
            float2 v1 = make_float2(acc[mt][nt][2], acc[mt][nt][3]);
            if (Dres) {
                const float2 d0 = *(const float2*)(Dres + row0 * (size_t)ldc + col);
                const float2 d1 = *(const float2*)(Dres + (row0 + 8) * (size_t)ldc + col);
                v0.x += d0.x; v0.y += d0.y; v1.x += d1.x; v1.y += d1.y;
            }
            *(float2*)p0 = v0;
            *(float2*)p1 = v1;
        }
    }
}

// ---------------------------------------------------------------------------
// K0: ada scales
// ---------------------------------------------------------------------------
__global__ void ada_kernel(const float* __restrict__ cond,
                           const float* __restrict__ w1,
                           const float* __restrict__ w2)
{
    int gw   = (blockIdx.x * blockDim.x + threadIdx.x) >> 5;
    int lane = threadIdx.x & 31;
    if (gw >= 2 * NBATCH * DM) return;
    int which = gw / (NBATCH * DM);
    int rem   = gw % (NBATCH * DM);
    int n = rem / DM, d = rem % DM;
    const float* w  = which ? w2 : w1;
    const float* cr = cond + n * DC;
    const float* wr = w + (size_t)d * DC;
    float s = 0.f;
    for (int i = lane; i < DC; i += 32) s += cr[i] * wr[i];
    #pragma unroll
    for (int o = 16; o; o >>= 1) s += __shfl_xor_sync(0xffffffffu, s, o);
    if (lane == 0) (which ? g_scale2 : g_scale1)[rem] = s + 1.0f;
}

// ---------------------------------------------------------------------------
// K1: RMSNorm * ada -> fp16
// ---------------------------------------------------------------------------
__global__ __launch_bounds__(256) void rmsnorm_kernel(const float* __restrict__ x,
                                                      const float* __restrict__ scale)
{
    int t = blockIdx.x;
    int n = t >> 14;
    const float* xr = x + (size_t)t * DM;
    float v[3]; float ss = 0.f;
    #pragma unroll
    for (int i = 0; i < 3; i++) { v[i] = xr[threadIdx.x + 256 * i]; ss += v[i] * v[i]; }
    __shared__ float red[8];
    #pragma unroll
    for (int o = 16; o; o >>= 1) ss += __shfl_xor_sync(0xffffffffu, ss, o);
    if ((threadIdx.x & 31) == 0) red[threadIdx.x >> 5] = ss;
    __syncthreads();
    if (threadIdx.x == 0) {
        float r = 0.f;
        #pragma unroll
        for (int i = 0; i < 8; i++) r += red[i];
        red[0] = r;
    }
    __syncthreads();
    float inv = rsqrtf(red[0] * (1.0f / DM) + EPSV);
    const float* sc = scale + (size_t)n * DM;
    #pragma unroll
    for (int i = 0; i < 3; i++) {
        int c = threadIdx.x + 256 * i;
        g_h[(size_t)t * DM + c] = __float2half(v[i] * sc[c] * inv);
    }
}

// ---------------------------------------------------------------------------
// K2: weight convert fp32 -> fp16 (optional row interleave for ff_up)
// ---------------------------------------------------------------------------
__global__ __launch_bounds__(256) void wconv_kernel(const float* __restrict__ w,
                                                    __half* __restrict__ dsth,
                                                    int n, int rowlen, int perm)
{
    int i = blockIdx.x * 256 + threadIdx.x;
    if (i >= n) return;
    int dst = i;
    if (perm) {
        int r = i / rowlen, c = i % rowlen;
        int dr = (r < DFF) ? (2 * r) : (2 * (r - DFF) + 1);
        dst = dr * rowlen + c;
    }
    dsth[dst] = __float2half(w[i]);
}

// ---------------------------------------------------------------------------
// K3: fused attention, f32x2 packed inner loops.
// ---------------------------------------------------------------------------
#define ATT_PAD  68
#define ATT_SMEM (2 * 64 * ATT_PAD * 4 + 64 * 64 * 4)   // 51200

__global__ __launch_bounds__(64) void attn_kernel(const float* __restrict__ pos,
                                                  const float* __restrict__ attn_scale,
                                                  const float* __restrict__ rope_freqs)
{
    extern __shared__ __align__(16) float sm[];
    float* qR = sm;
    float* kR = sm + 64 * ATT_PAD;
    float* vs = sm + 2 * 64 * ATT_PAD;

    const int b   = blockIdx.x;
    const int rem = b % (NHEADS * 256);
    const int h   = rem >> 8;
    const int w   = rem & 255;
    const bool left = ((w & 15) == 0), top = ((w >> 4) == 0);
    const int tid = threadIdx.x;

    const float* vb = g_vw + (size_t)b * 4096;
    #pragma unroll
    for (int i = tid; i < 1024; i += 64) {
        int r = i >> 4, c4 = (i & 15) << 2;
        int t = win_token(b, r);
        const float* qk = g_qkv + (size_t)t * (2 * DM) + h * DHEAD + c4;
        float4 qv = *(const float4*)qk;
        float4 kv = *(const float4*)(qk + DM);
        float4 vv = *(const float4*)(vb + (i << 2));
        *(float4*)(qR + r * ATT_PAD + c4) = qv;
        *(float4*)(kR + r * ATT_PAD + c4) = kv;
        *(float4*)(vs + r * 64 + c4)      = vv;
    }
    __syncthreads();

    {
        float* qrow = qR + tid * ATT_PAD;
        float* krow = kR + tid * ATT_PAD;
        float sq = 0.f, sk = 0.f;
        #pragma unroll
        for (int e = 0; e < 64; e++) { float a = qrow[e], c = krow[e]; sq += a * a; sk += c * c; }
        float ssh = sqrtf(attn_scale[h]);
        float rq = ssh * rsqrtf(sq + EPSV);
        float rk = ssh * rsqrtf(sk + EPSV);

        int t = win_token(b, tid);
        float p0 = pos[(size_t)t * 2 + 0];
        float p1 = pos[(size_t)t * 2 + 1];
        #pragma unroll
        for (int e = 0; e < 16; e++) {
            float freq = rope_freqs[h * 8 + (e & 7)];
            float th = (e < 8 ? p0 : p1) * freq;
            float c = cosf(th), s = sinf(th);
            float q1 = qrow[e] * rq, q2 = qrow[e + 16] * rq;
            float k1 = krow[e] * rk, k2 = krow[e + 16] * rk;
            qrow[e]      = q1 * c - q2 * s;
            qrow[e + 16] = q2 * c + q1 * s;
            krow[e]      = k1 * c - k2 * s;
            krow[e + 16] = k2 * c + k1 * s;
        }
        #pragma unroll
        for (int e = 32; e < 64; e++) { qrow[e] *= rq; krow[e] *= rk; }
    }
    __syncthreads();

    // ---- scores via f32x2: two halves of 32 k each ----
    float sarr[64];
    const float* qrow = qR + tid * ATT_PAD;
    #pragma unroll
    for (int half = 0; half < 2; half++) {
        u64t acc2[32];
        #pragma unroll
        for (int k = 0; k < 32; k++) acc2[k] = 0ull;
        for (int e = 0; e < 64; e += 4) {
            u64t q01 = pack2(qrow[e],     qrow[e + 1]);
            u64t q23 = pack2(qrow[e + 2], qrow[e + 3]);
            #pragma unroll 8
            for (int k = 0; k < 32; k++) {
                union { float4 f4; u64t u2[2]; } kv;
                kv.f4 = *(const float4*)(kR + (half * 32 + k) * ATT_PAD + e);
                ffma2(acc2[k], q01, kv.u2[0]);
                ffma2(acc2[k], q23, kv.u2[1]);
            }
        }
        #pragma unroll
        for (int k = 0; k < 32; k++) {
            float lo, hi;
            unpack2(acc2[k], lo, hi);
            sarr[half * 32 + k] = lo + hi;
        }
    }

    // mask + softmax
    int qh = tid >> 3, qw_ = tid & 7;
    bool qa = qh < SHIFT, ql = qw_ < SHIFT;
    float mx = -3.402823466e38f;
    #pragma unroll
    for (int k = 0; k < 64; k++) {
        int kh = k >> 3, kw = k & 7;
        bool ka = kh < SHIFT, kl = kw < SHIFT;
        bool m = (!left && !top)
               || (left && top && (ql == kl) && (qa == ka))
               || (left && !top && (ql == kl))
               || (!left && top && (qa == ka));
        if (!m) sarr[k] = -3.402823466e38f;
        mx = fmaxf(mx, sarr[k]);
    }
    float sum = 0.f;
    #pragma unroll
    for (int k = 0; k < 64; k++) {
        float p = __expf(sarr[k] - mx);
        sarr[k] = p;
        sum += p;
    }
    float inv = 1.0f / sum;

    // ---- PV via f32x2: o accumulated as 32 packed pairs ----
    u64t o2[32];
    #pragma unroll
    for (int j = 0; j < 32; j++) o2[j] = 0ull;
    for (int k = 0; k < 64; k++) {
        float p = sarr[k];
        u64t p2 = pack2(p, p);
        const float* vrow = vs + k * 64;
        #pragma unroll 8
        for (int e = 0; e < 64; e += 4) {
            union { float4 f4; u64t u2[2]; } vv;
            vv.f4 = *(const float4*)(vrow + e);
            ffma2(o2[e >> 1], p2, vv.u2[0]);
            ffma2(o2[(e >> 1) + 1], p2, vv.u2[1]);
        }
    }
    float* orow = qR + tid * ATT_PAD;
    #pragma unroll
    for (int j = 0; j < 32; j++) {
        float lo, hi;
        unpack2(o2[j], lo, hi);
        orow[2 * j]     = lo * inv;
        orow[2 * j + 1] = hi * inv;
    }
    __syncthreads();

    #pragma unroll
    for (int i = tid; i < 1024; i += 64) {
        int r = i >> 4, c4 = (i & 15) << 2;
        int t = win_token(b, r);
        size_t dst = (size_t)t * DM + h * DHEAD + c4;
        const float* src = qR + r * ATT_PAD + c4;
        __half h4[4];
        #pragma unroll
        for (int j = 0; j < 4; j++) h4[j] = __float2half(src[j]);
        *(uint2*)&g_oi[dst] = *(uint2*)h4;
    }
}

// ---------------------------------------------------------------------------
// host
// ---------------------------------------------------------------------------
static void launch_hgemm(const __half* A, const __half* B,
                         const float* D, float* C, int M, int N, int K,
                         int ldc, int mode)
{
    dim3 grid(N / 256, M / 128);
    hgemm_kernel<<<grid, 256, GEMM_SMEM>>>(A, B, D, C, M, N, K, ldc, mode);
}

extern "C" void kernel_launch(void* const* d_in, const int* in_sizes, int n_in,
                              void* d_out, int out_size)
{
    const float* x          = (const float*)d_in[0];
    const float* pos        = (const float*)d_in[1];
    const float* cond       = (const float*)d_in[2];
    const float* ada1_w     = (const float*)d_in[3];
    const float* qkv_w      = (const float*)d_in[4];
    const float* attn_scale = (const float*)d_in[5];
    const float* rope_freqs = (const float*)d_in[6];
    const float* out_w      = (const float*)d_in[7];
    const float* ada2_w     = (const float*)d_in[8];
    const float* ff_up_w    = (const float*)d_in[9];
    const float* ff_down_w  = (const float*)d_in[10];
    float* out = (float*)d_out;

    cudaFuncSetAttribute(hgemm_kernel, cudaFuncAttributeMaxDynamicSharedMemorySize, GEMM_SMEM);
    cudaFuncSetAttribute(attn_kernel, cudaFuncAttributeMaxDynamicSharedMemorySize, ATT_SMEM);

    float *p_scale1, *p_scale2, *p_qkv, *p_x2;
    __half *p_h, *p_oi, *p_a, *p_w;
    cudaGetSymbolAddress((void**)&p_scale1, g_scale1);
    cudaGetSymbolAddress((void**)&p_scale2, g_scale2);
    cudaGetSymbolAddress((void**)&p_qkv,    g_qkv);
    cudaGetSymbolAddress((void**)&p_x2,     g_x2);
    cudaGetSymbolAddress((void**)&p_h,      g_h);
    cudaGetSymbolAddress((void**)&p_oi,     g_oi);
    cudaGetSymbolAddress((void**)&p_a,      g_a);
    cudaGetSymbolAddress((void**)&p_w,      g_w);

    const int OQKV = 0;
    const int OOUT = OQKV + W_QKV_SZ;
    const int OUP  = OOUT + W_OUT_SZ;
    const int ODN  = OUP + W_UP_SZ;

    wconv_kernel<<<(W_QKV_SZ + 255) / 256, 256>>>(qkv_w,     p_w + OQKV, W_QKV_SZ, DM, 0);
    wconv_kernel<<<(W_OUT_SZ + 255) / 256, 256>>>(out_w,     p_w + OOUT, W_OUT_SZ, DM, 0);
    wconv_kernel<<<(W_UP_SZ  + 255) / 256, 256>>>(ff_up_w,   p_w + OUP,  W_UP_SZ,  DM, 1);
    wconv_kernel<<<(W_DN_SZ  + 255) / 256, 256>>>(ff_down_w, p_w + ODN,  W_DN_SZ,  DFF, 0);

    ada_kernel<<<768, 256>>>(cond, ada1_w, ada2_w);
    rmsnorm_kernel<<<TOKENS, 256>>>(x, p_scale1);
    launch_hgemm(p_h, p_w + OQKV, nullptr, p_qkv, TOKENS, 3 * DM, DM, 2 * DM, 2);
    attn_kernel<<<NWIN, 64, ATT_SMEM>>>(pos, attn_scale, rope_freqs);
    launch_hgemm(p_oi, p_w + OOUT, x, p_x2, TOKENS, DM, DM, DM, 0);
    rmsnorm_kernel<<<TOKENS, 256>>>(p_x2, p_scale2);
    launch_hgemm(p_h, p_w + OUP, nullptr, nullptr, TOKENS, 2 * DFF, DM, 2 * DFF, 1);
    launch_hgemm(p_a, p_w + ODN, p_x2, out, TOKENS, DM, DFF, DM, 0);
}

// round 11
// speedup vs baseline: 2.2114x; 2.2114x over previous
#include <cuda_runtime.h>
#include <cuda_bf16.h>
#include <cuda_fp16.h>
#include <math.h>
#include <stdint.h>

// ---------------------------------------------------------------------------
// Problem constants
// ---------------------------------------------------------------------------
#define NBATCH   4
#define HDIM     128
#define WDIM     128
#define DM       768
#define NHEADS   12
#define DHEAD    64
#define DFF      2048
#define DC       768
#define WS       8
#define SHIFT    4
#define TOKENS   (NBATCH * HDIM * WDIM)          // 65536
#define NWIN     (NBATCH * NHEADS * 16 * 16)     // 12288
#define EPSV     1e-6f

// ---------------------------------------------------------------------------
// Scratch
// ---------------------------------------------------------------------------
#define W_QKV_SZ (3 * DM * DM)
#define W_OUT_SZ (DM * DM)
#define W_UP_SZ  (2 * DFF * DM)
#define W_DN_SZ  (DM * DFF)
#define W_TOTAL  (W_QKV_SZ + W_OUT_SZ + W_UP_SZ + W_DN_SZ)

__device__ float g_scale1[NBATCH * DM];
__device__ float g_scale2[NBATCH * DM];
__device__ float g_qkv [(size_t)TOKENS * 2 * DM];     // q,k fp32 (ldc=1536)
__device__ float g_vw  [(size_t)NWIN * 64 * 64];      // v windowed fp32
__device__ float g_x2  [(size_t)TOKENS * DM];

__device__ __half g_h  [(size_t)TOKENS * DM];         // activations fp16
__device__ __half g_oi [(size_t)TOKENS * DM];
__device__ __half g_a  [(size_t)TOKENS * DFF];
__device__ __half g_w  [W_TOTAL];                     // weights fp16 (single)

// ---------------------------------------------------------------------------
// PTX helpers (sm_80+ features only; legal under compute_103)
// ---------------------------------------------------------------------------
__device__ __forceinline__ uint32_t smem_to_u32(const void* p) {
    uint32_t a;
    asm("{ .reg .u64 t; cvta.to.shared.u64 t, %1; cvt.u32.u64 %0, t; }" : "=r"(a) : "l"(p));
    return a;
}
#define CP_ASYNC16(sa, gp) \
    asm volatile("cp.async.cg.shared.global [%0], [%1], 16;" :: "r"(sa), "l"(gp))
#define CP_COMMIT() asm volatile("cp.async.commit_group;" ::: "memory")
#define CP_WAIT1()  asm volatile("cp.async.wait_group 1;" ::: "memory")
#define CP_WAIT0()  asm volatile("cp.async.wait_group 0;" ::: "memory")

__device__ __forceinline__ void ldsm_x4(uint32_t& r0, uint32_t& r1, uint32_t& r2,
                                        uint32_t& r3, uint32_t addr) {
    asm volatile("ldmatrix.sync.aligned.m8n8.x4.shared.b16 {%0,%1,%2,%3}, [%4];"
                 : "=r"(r0), "=r"(r1), "=r"(r2), "=r"(r3) : "r"(addr));
}
__device__ __forceinline__ void mma_f16(float c[4], const uint32_t a[4],
                                        const uint32_t b[2]) {
    asm volatile("mma.sync.aligned.m16n8k16.row.col.f32.f16.f16.f32 "
                 "{%0,%1,%2,%3},{%4,%5,%6,%7},{%8,%9},{%0,%1,%2,%3};"
                 : "+f"(c[0]), "+f"(c[1]), "+f"(c[2]), "+f"(c[3])
                 : "r"(a[0]), "r"(a[1]), "r"(a[2]), "r"(a[3]),
                   "r"(b[0]), "r"(b[1]));
}

// window-scatter address helper (roll +4,+4 then 8x8 windows)
__device__ __forceinline__ size_t win_addr(int t, int h, int e) {
    int n = t >> 14;
    int y = (t >> 7) & 127;
    int x = t & 127;
    int Y = (y + SHIFT) & 127, X = (x + SHIFT) & 127;
    int wyx  = ((Y >> 3) << 4) + (X >> 3);
    int spos = ((Y & 7) << 3) + (X & 7);
    return ((size_t)((n * NHEADS + h) * 256 + wyx)) * 4096 + (size_t)spos * 64 + e;
}

// inverse: window b, slot r -> token index
__device__ __forceinline__ int win_token(int b, int r) {
    int n   = b / (NHEADS * 256);
    int rem = b % (NHEADS * 256);
    int w   = rem & 255;
    int Y = ((w >> 4) << 3) + (r >> 3);
    int X = ((w & 15) << 3) + (r & 7);
    int y = (Y - SHIFT) & 127, x = (X - SHIFT) & 127;
    return (n << 14) + (y << 7) + x;
}

// ---------------------------------------------------------------------------
// GEMM: C = (D?D:0) + A @ B^T. fp16 x fp16, fp32 accum.
// CTA tile 128x256x64, 8 warps (2m x 4n), warp tile 64x64, 2-stage cp.async.
// mode 0: plain (+residual)   mode 1: fused gated-GELU -> g_a
// mode 2: qkv (cols<1536 -> C fp32; cols>=1536 -> scatter V to g_vw)
// ---------------------------------------------------------------------------
#define BKC      64
#define PADK     72
#define TILE_A_E (128 * PADK)
#define TILE_B_E (256 * PADK)
#define STAGE_E  (TILE_A_E + TILE_B_E)       // 27648 elems = 55296 B
#define GEMM_SMEM (2 * STAGE_E * 2)          // 110592 bytes

__global__ __launch_bounds__(256) void hgemm_kernel(
    const __half* __restrict__ A, const __half* __restrict__ B,
    const float* __restrict__ Dres, float* __restrict__ C,
    int M, int N, int K, int ldc, int mode)
{
    extern __shared__ __align__(128) char smem[];
    const uint32_t sbase = smem_to_u32(smem);
    const int tid = threadIdx.x, lane = tid & 31, wid = tid >> 5;
    const int wm = wid >> 2, wn = wid & 3;
    const size_t bm = (size_t)blockIdx.y * 128;
    const size_t bn = (size_t)blockIdx.x * 256;

    const __half* Ab = A + bm * (size_t)K;
    const __half* Bb = B + bn * (size_t)K;

    float acc[4][8][4];
    #pragma unroll
    for (int i = 0; i < 4; i++)
        #pragma unroll
        for (int j = 0; j < 8; j++)
            #pragma unroll
            for (int l = 0; l < 4; l++) acc[i][j][l] = 0.f;

    const int nstage = K / BKC;

    // 8 chunks (16B) per row; A: 1024 chunks (4 iters), B: 2048 chunks (8 iters)
    auto issue = [&](int st) {
        const int k0 = st * BKC;
        const uint32_t sb = sbase + (uint32_t)((st & 1) * STAGE_E * 2);
        #pragma unroll
        for (int i = 0; i < 4; i++) {
            int idx = tid + i * 256;
            int row = idx >> 3, seg = (idx & 7) << 3;
            const __half* gp = Ab + (size_t)row * K + k0 + seg;
            uint32_t sa = sb + (uint32_t)((row * PADK + seg) * 2);
            CP_ASYNC16(sa, gp);
        }
        #pragma unroll
        for (int i = 0; i < 8; i++) {
            int idx = tid + i * 256;
            int row = idx >> 3, seg = (idx & 7) << 3;
            const __half* gp = Bb + (size_t)row * K + k0 + seg;
            uint32_t sa = sb + (uint32_t)((TILE_A_E + row * PADK + seg) * 2);
            CP_ASYNC16(sa, gp);
        }
        CP_COMMIT();
    };

    issue(0);
    if (nstage > 1) issue(1);

    const int a_r = lane & 15, a_h = (lane >> 4) << 3;
    const int b_r = (lane & 7) + ((lane & 16) >> 1);
    const int b_k = lane & 8;

    for (int st = 0; st < nstage; st++) {
        if (st + 1 < nstage) { CP_WAIT1(); } else { CP_WAIT0(); }
        __syncthreads();

        const uint32_t sb = sbase + (uint32_t)((st & 1) * STAGE_E * 2);
        const uint32_t sA = sb;
        const uint32_t sB = sb + TILE_A_E * 2;

        #pragma unroll
        for (int kk = 0; kk < BKC; kk += 16) {
            uint32_t a[4][4], bh[8][2];
            #pragma unroll
            for (int mt = 0; mt < 4; mt++)
                ldsm_x4(a[mt][0], a[mt][1], a[mt][2], a[mt][3],
                        sA + (uint32_t)(((wm * 64 + mt * 16 + a_r) * PADK + kk + a_h) * 2));
            #pragma unroll
            for (int p = 0; p < 4; p++) {
                uint32_t r0, r1, r2, r3;
                ldsm_x4(r0, r1, r2, r3,
                        sB + (uint32_t)(((wn * 64 + p * 16 + b_r) * PADK + kk + b_k) * 2));
                bh[p * 2][0] = r0; bh[p * 2][1] = r1;
                bh[p * 2 + 1][0] = r2; bh[p * 2 + 1][1] = r3;
            }
            #pragma unroll
            for (int mt = 0; mt < 4; mt++)
                #pragma unroll
                for (int nt = 0; nt < 8; nt++)
                    mma_f16(acc[mt][nt], a[mt], bh[nt]);
        }
        __syncthreads();
        if (st + 2 < nstage) issue(st + 2);
    }

    const int er = lane >> 2, ec = (lane & 3) * 2;

    if (mode == 1) {
        // fused gated GELU: col pair (even,odd) = (a_j, g_j); j = col/2
        #pragma unroll
        for (int mt = 0; mt < 4; mt++) {
            size_t r0 = bm + wm * 64 + mt * 16 + er;
            size_t r1 = r0 + 8;
            #pragma unroll
            for (int nt = 0; nt < 8; nt++) {
                int col = (int)bn + wn * 64 + nt * 8 + ec;
                int j = col >> 1;
                float a0 = acc[mt][nt][0], gg0 = acc[mt][nt][1];
                float a1 = acc[mt][nt][2], gg1 = acc[mt][nt][3];
                float v0 = a0 * (gg0 * 0.5f * (1.0f + erff(gg0 * 0.70710678118654752f)));
                float v1 = a1 * (gg1 * 0.5f * (1.0f + erff(gg1 * 0.70710678118654752f)));
                g_a[r0 * DFF + j] = __float2half(v0);
                g_a[r1 * DFF + j] = __float2half(v1);
            }
        }
        return;
    }

    if (mode == 2 && bn >= 1536) {
        // V region: scatter straight into windowed layout
        #pragma unroll
        for (int mt = 0; mt < 4; mt++) {
            int t0 = (int)bm + wm * 64 + mt * 16 + er;
            int t1 = t0 + 8;
            #pragma unroll
            for (int nt = 0; nt < 8; nt++) {
                int col = (int)bn + wn * 64 + nt * 8 + ec;
                int h = (col - 1536) >> 6;
                int e = col & 63;
                float2 v0 = make_float2(acc[mt][nt][0], acc[mt][nt][1]);
                float2 v1 = make_float2(acc[mt][nt][2], acc[mt][nt][3]);
                *(float2*)&g_vw[win_addr(t0, h, e)] = v0;
                *(float2*)&g_vw[win_addr(t1, h, e)] = v1;
            }
        }
        return;
    }

    #pragma unroll
    for (int mt = 0; mt < 4; mt++) {
        size_t row0 = bm + wm * 64 + mt * 16 + er;
        #pragma unroll
        for (int nt = 0; nt < 8; nt++) {
            size_t col = bn + wn * 64 + nt * 8 + ec;
            float* p0 = C + row0 * (size_t)ldc + col;
            float* p1 = C + (row0 + 8) * (size_t)ldc + col;
            float2 v0 = make_float2(acc[mt][nt][0], acc[mt][nt][1]);
            float2 v1 = make_float2(acc[mt][nt][2], acc[mt][nt][3]);
            if (Dres) {
                const float2 d0 = *(const float2*)(Dres + row0 * (size_t)ldc + col);
                const float2 d1 = *(const float2*)(Dres + (row0 + 8) * (size_t)ldc + col);
                v0.x += d0.x; v0.y += d0.y; v1.x += d1.x; v1.y += d1.y;
            }
            *(float2*)p0 = v0;
            *(float2*)p1 = v1;
        }
    }
}

// ---------------------------------------------------------------------------
// K0: ada scales
// ---------------------------------------------------------------------------
__global__ void ada_kernel(const float* __restrict__ cond,
                           const float* __restrict__ w1,
                           const float* __restrict__ w2)
{
    int gw   = (blockIdx.x * blockDim.x + threadIdx.x) >> 5;
    int lane = threadIdx.x & 31;
    if (gw >= 2 * NBATCH * DM) return;
    int which = gw / (NBATCH * DM);
    int rem   = gw % (NBATCH * DM);
    int n = rem / DM, d = rem % DM;
    const float* w  = which ? w2 : w1;
    const float* cr = cond + n * DC;
    const float* wr = w + (size_t)d * DC;
    float s = 0.f;
    for (int i = lane; i < DC; i += 32) s += cr[i] * wr[i];
    #pragma unroll
    for (int o = 16; o; o >>= 1) s += __shfl_xor_sync(0xffffffffu, s, o);
    if (lane == 0) (which ? g_scale2 : g_scale1)[rem] = s + 1.0f;
}

// ---------------------------------------------------------------------------
// K1: RMSNorm * ada -> fp16
// ---------------------------------------------------------------------------
__global__ __launch_bounds__(256) void rmsnorm_kernel(const float* __restrict__ x,
                                                      const float* __restrict__ scale)
{
    int t = blockIdx.x;
    int n = t >> 14;
    const float* xr = x + (size_t)t * DM;
    float v[3]; float ss = 0.f;
    #pragma unroll
    for (int i = 0; i < 3; i++) { v[i] = xr[threadIdx.x + 256 * i]; ss += v[i] * v[i]; }
    __shared__ float red[8];
    #pragma unroll
    for (int o = 16; o; o >>= 1) ss += __shfl_xor_sync(0xffffffffu, ss, o);
    if ((threadIdx.x & 31) == 0) red[threadIdx.x >> 5] = ss;
    __syncthreads();
    if (threadIdx.x == 0) {
        float r = 0.f;
        #pragma unroll
        for (int i = 0; i < 8; i++) r += red[i];
        red[0] = r;
    }
    __syncthreads();
    float inv = rsqrtf(red[0] * (1.0f / DM) + EPSV);
    const float* sc = scale + (size_t)n * DM;
    #pragma unroll
    for (int i = 0; i < 3; i++) {
        int c = threadIdx.x + 256 * i;
        g_h[(size_t)t * DM + c] = __float2half(v[i] * sc[c] * inv);
    }
}

// ---------------------------------------------------------------------------
// K2: weight convert fp32 -> fp16 (optional row interleave for ff_up)
// ---------------------------------------------------------------------------
__global__ __launch_bounds__(256) void wconv_kernel(const float* __restrict__ w,
                                                    __half* __restrict__ dsth,
                                                    int n, int rowlen, int perm)
{
    int i = blockIdx.x * 256 + threadIdx.x;
    if (i >= n) return;
    int dst = i;
    if (perm) {
        int r = i / rowlen, c = i % rowlen;
        int dr = (r < DFF) ? (2 * r) : (2 * (r - DFF) + 1);
        dst = dr * rowlen + c;
    }
    dsth[dst] = __float2half(w[i]);
}

// ---------------------------------------------------------------------------
// K3: fused attention (R8 proven version: gather q,k + norm + RoPE +
// softmax + PV + fp16 store)
// ---------------------------------------------------------------------------
#define ATT_PAD  68
#define ATT_SMEM (2 * 64 * ATT_PAD * 4 + 64 * 64 * 4)   // 51200

__global__ __launch_bounds__(64) void attn_kernel(const float* __restrict__ pos,
                                                  const float* __restrict__ attn_scale,
                                                  const float* __restrict__ rope_freqs)
{
    extern __shared__ __align__(16) float sm[];
    float* qR = sm;
    float* kR = sm + 64 * ATT_PAD;
    float* vs = sm + 2 * 64 * ATT_PAD;

    const int b   = blockIdx.x;
    const int rem = b % (NHEADS * 256);
    const int h   = rem >> 8;
    const int w   = rem & 255;
    const bool left = ((w & 15) == 0), top = ((w >> 4) == 0);
    const int tid = threadIdx.x;

    const float* vb = g_vw + (size_t)b * 4096;
    #pragma unroll
    for (int i = tid; i < 1024; i += 64) {
        int r = i >> 4, c4 = (i & 15) << 2;
        int t = win_token(b, r);
        const float* qk = g_qkv + (size_t)t * (2 * DM) + h * DHEAD + c4;
        float4 qv = *(const float4*)qk;
        float4 kv = *(const float4*)(qk + DM);
        float4 vv = *(const float4*)(vb + (i << 2));
        *(float4*)(qR + r * ATT_PAD + c4) = qv;
        *(float4*)(kR + r * ATT_PAD + c4) = kv;
        *(float4*)(vs + r * 64 + c4)      = vv;
    }
    __syncthreads();

    {
        float* qrow = qR + tid * ATT_PAD;
        float* krow = kR + tid * ATT_PAD;
        float sq = 0.f, sk = 0.f;
        #pragma unroll
        for (int e = 0; e < 64; e++) { float a = qrow[e], c = krow[e]; sq += a * a; sk += c * c; }
        float ssh = sqrtf(attn_scale[h]);
        float rq = ssh * rsqrtf(sq + EPSV);
        float rk = ssh * rsqrtf(sk + EPSV);

        int t = win_token(b, tid);
        float p0 = pos[(size_t)t * 2 + 0];
        float p1 = pos[(size_t)t * 2 + 1];
        #pragma unroll
        for (int e = 0; e < 16; e++) {
            float freq = rope_freqs[h * 8 + (e & 7)];
            float th = (e < 8 ? p0 : p1) * freq;
            float c = cosf(th), s = sinf(th);
            float q1 = qrow[e] * rq, q2 = qrow[e + 16] * rq;
            float k1 = krow[e] * rk, k2 = krow[e + 16] * rk;
            qrow[e]      = q1 * c - q2 * s;
            qrow[e + 16] = q2 * c + q1 * s;
            krow[e]      = k1 * c - k2 * s;
            krow[e + 16] = k2 * c + k1 * s;
        }
        #pragma unroll
        for (int e = 32; e < 64; e++) { qrow[e] *= rq; krow[e] *= rk; }
    }
    __syncthreads();

    float sarr[64];
    #pragma unroll
    for (int k = 0; k < 64; k++) sarr[k] = 0.f;
    const float* qrow = qR + tid * ATT_PAD;
    for (int e = 0; e < 64; e += 4) {
        float q0 = qrow[e], q1 = qrow[e + 1], q2 = qrow[e + 2], q3 = qrow[e + 3];
        #pragma unroll
        for (int k = 0; k < 64; k++) {
            float4 kv = *(const float4*)(kR + k * ATT_PAD + e);
            sarr[k] += q0 * kv.x + q1 * kv.y + q2 * kv.z + q3 * kv.w;
        }
    }

    int qh = tid >> 3, qw_ = tid & 7;
    bool qa = qh < SHIFT, ql = qw_ < SHIFT;
    float mx = -3.402823466e38f;
    #pragma unroll
    for (int k = 0; k < 64; k++) {
        int kh = k >> 3, kw = k & 7;
        bool ka = kh < SHIFT, kl = kw < SHIFT;
        bool m = (!left && !top)
               || (left && top && (ql == kl) && (qa == ka))
               || (left && !top && (ql == kl))
               || (!left && top && (qa == ka));
        if (!m) sarr[k] = -3.402823466e38f;
        mx = fmaxf(mx, sarr[k]);
    }
    float sum = 0.f;
    #pragma unroll
    for (int k = 0; k < 64; k++) {
        float p = __expf(sarr[k] - mx);
        sarr[k] = p;
        sum += p;
    }
    float inv = 1.0f / sum;

    float* orow = qR + tid * ATT_PAD;
    for (int e = 0; e < 64; e += 4) {
        float ax = 0.f, ay = 0.f, az = 0.f, aw = 0.f;
        #pragma unroll
        for (int k = 0; k < 64; k++) {
            float4 vv = *(const float4*)(vs + k * 64 + e);
            float p = sarr[k];
            ax += p * vv.x; ay += p * vv.y; az += p * vv.z; aw += p * vv.w;
        }
        orow[e] = ax * inv; orow[e + 1] = ay * inv;
        orow[e + 2] = az * inv; orow[e + 3] = aw * inv;
    }
    __syncthreads();

    #pragma unroll
    for (int i = tid; i < 1024; i += 64) {
        int r = i >> 4, c4 = (i & 15) << 2;
        int t = win_token(b, r);
        size_t dst = (size_t)t * DM + h * DHEAD + c4;
        const float* src = qR + r * ATT_PAD + c4;
        __half h4[4];
        #pragma unroll
        for (int j = 0; j < 4; j++) h4[j] = __float2half(src[j]);
        *(uint2*)&g_oi[dst] = *(uint2*)h4;
    }
}

// ---------------------------------------------------------------------------
// host
// ---------------------------------------------------------------------------
static void launch_hgemm(const __half* A, const __half* B,
                         const float* D, float* C, int M, int N, int K,
                         int ldc, int mode)
{
    dim3 grid(N / 256, M / 128);
    hgemm_kernel<<<grid, 256, GEMM_SMEM>>>(A, B, D, C, M, N, K, ldc, mode);
}

extern "C" void kernel_launch(void* const* d_in, const int* in_sizes, int n_in,
                              void* d_out, int out_size)
{
    const float* x          = (const float*)d_in[0];
    const float* pos        = (const float*)d_in[1];
    const float* cond       = (const float*)d_in[2];
    const float* ada1_w     = (const float*)d_in[3];
    const float* qkv_w      = (const float*)d_in[4];
    const float* attn_scale = (const float*)d_in[5];
    const float* rope_freqs = (const float*)d_in[6];
    const float* out_w      = (const float*)d_in[7];
    const float* ada2_w     = (const float*)d_in[8];
    const float* ff_up_w    = (const float*)d_in[9];
    const float* ff_down_w  = (const float*)d_in[10];
    float* out = (float*)d_out;

    cudaFuncSetAttribute(hgemm_kernel, cudaFuncAttributeMaxDynamicSharedMemorySize, GEMM_SMEM);
    cudaFuncSetAttribute(attn_kernel, cudaFuncAttributeMaxDynamicSharedMemorySize, ATT_SMEM);

    float *p_scale1, *p_scale2, *p_qkv, *p_x2;
    __half *p_h, *p_oi, *p_a, *p_w;
    cudaGetSymbolAddress((void**)&p_scale1, g_scale1);
    cudaGetSymbolAddress((void**)&p_scale2, g_scale2);
    cudaGetSymbolAddress((void**)&p_qkv,    g_qkv);
    cudaGetSymbolAddress((void**)&p_x2,     g_x2);
    cudaGetSymbolAddress((void**)&p_h,      g_h);
    cudaGetSymbolAddress((void**)&p_oi,     g_oi);
    cudaGetSymbolAddress((void**)&p_a,      g_a);
    cudaGetSymbolAddress((void**)&p_w,      g_w);

    const int OQKV = 0;
    const int OOUT = OQKV + W_QKV_SZ;
    const int OUP  = OOUT + W_OUT_SZ;
    const int ODN  = OUP + W_UP_SZ;

    wconv_kernel<<<(W_QKV_SZ + 255) / 256, 256>>>(qkv_w,     p_w + OQKV, W_QKV_SZ, DM, 0);
    wconv_kernel<<<(W_OUT_SZ + 255) / 256, 256>>>(out_w,     p_w + OOUT, W_OUT_SZ, DM, 0);
    wconv_kernel<<<(W_UP_SZ  + 255) / 256, 256>>>(ff_up_w,   p_w + OUP,  W_UP_SZ,  DM, 1);
    wconv_kernel<<<(W_DN_SZ  + 255) / 256, 256>>>(ff_down_w, p_w + ODN,  W_DN_SZ,  DFF, 0);

    ada_kernel<<<768, 256>>>(cond, ada1_w, ada2_w);
    rmsnorm_kernel<<<TOKENS, 256>>>(x, p_scale1);
    // qkv: q,k -> g_qkv (ldc=1536); v -> scatter to g_vw
    launch_hgemm(p_h, p_w + OQKV, nullptr, p_qkv, TOKENS, 3 * DM, DM, 2 * DM, 2);
    // fused qk-transform + attention + unwindow
    attn_kernel<<<NWIN, 64, ATT_SMEM>>>(pos, attn_scale, rope_freqs);
    launch_hgemm(p_oi, p_w + OOUT, x, p_x2, TOKENS, DM, DM, DM, 0);
    rmsnorm_kernel<<<TOKENS, 256>>>(p_x2, p_scale2);
    // ff_up with fused gated GELU (interleaved weights) -> g_a
    launch_hgemm(p_h, p_w + OUP, nullptr, nullptr, TOKENS, 2 * DFF, DM, 2 * DFF, 1);
    launch_hgemm(p_a, p_w + ODN, p_x2, out, TOKENS, DM, DFF, DM, 0);
}

// round 12
// speedup vs baseline: 2.3802x; 1.0764x over previous
#include <cuda_runtime.h>
#include <cuda_bf16.h>
#include <cuda_fp16.h>
#include <math.h>
#include <stdint.h>

// ---------------------------------------------------------------------------
// Problem constants
// ---------------------------------------------------------------------------
#define NBATCH   4
#define HDIM     128
#define WDIM     128
#define DM       768
#define NHEADS   12
#define DHEAD    64
#define DFF      2048
#define DC       768
#define WS       8
#define SHIFT    4
#define TOKENS   (NBATCH * HDIM * WDIM)          // 65536
#define NWIN     (NBATCH * NHEADS * 16 * 16)     // 12288
#define EPSV     1e-6f

// ---------------------------------------------------------------------------
// Scratch
// ---------------------------------------------------------------------------
#define W_QKV_SZ (3 * DM * DM)
#define W_OUT_SZ (DM * DM)
#define W_UP_SZ  (2 * DFF * DM)
#define W_DN_SZ  (DM * DFF)
#define W_TOTAL  (W_QKV_SZ + W_OUT_SZ + W_UP_SZ + W_DN_SZ)

__device__ float g_scale1[NBATCH * DM];
__device__ float g_scale2[NBATCH * DM];
__device__ float g_qkv [(size_t)TOKENS * 2 * DM];     // q,k fp32 (ldc=1536)
__device__ float g_vw  [(size_t)NWIN * 64 * 64];      // v windowed fp32
__device__ float g_x2  [(size_t)TOKENS * DM];

__device__ __half g_h  [(size_t)TOKENS * DM];         // activations fp16
__device__ __half g_oi [(size_t)TOKENS * DM];
__device__ __half g_a  [(size_t)TOKENS * DFF];
__device__ __half g_w  [W_TOTAL];                     // weights fp16 (single)

// ---------------------------------------------------------------------------
// PTX helpers (sm_80+ features only; legal under compute_103)
// ---------------------------------------------------------------------------
__device__ __forceinline__ uint32_t smem_to_u32(const void* p) {
    uint32_t a;
    asm("{ .reg .u64 t; cvta.to.shared.u64 t, %1; cvt.u32.u64 %0, t; }" : "=r"(a) : "l"(p));
    return a;
}
#define CP_ASYNC16(sa, gp) \
    asm volatile("cp.async.cg.shared.global [%0], [%1], 16;" :: "r"(sa), "l"(gp))
#define CP_COMMIT() asm volatile("cp.async.commit_group;" ::: "memory")
#define CP_WAIT2()  asm volatile("cp.async.wait_group 2;" ::: "memory")
#define CP_WAIT1()  asm volatile("cp.async.wait_group 1;" ::: "memory")
#define CP_WAIT0()  asm volatile("cp.async.wait_group 0;" ::: "memory")

__device__ __forceinline__ void ldsm_x4(uint32_t& r0, uint32_t& r1, uint32_t& r2,
                                        uint32_t& r3, uint32_t addr) {
    asm volatile("ldmatrix.sync.aligned.m8n8.x4.shared.b16 {%0,%1,%2,%3}, [%4];"
                 : "=r"(r0), "=r"(r1), "=r"(r2), "=r"(r3) : "r"(addr));
}
__device__ __forceinline__ void mma_f16(float c[4], const uint32_t a[4],
                                        const uint32_t b[2]) {
    asm volatile("mma.sync.aligned.m16n8k16.row.col.f32.f16.f16.f32 "
                 "{%0,%1,%2,%3},{%4,%5,%6,%7},{%8,%9},{%0,%1,%2,%3};"
                 : "+f"(c[0]), "+f"(c[1]), "+f"(c[2]), "+f"(c[3])
                 : "r"(a[0]), "r"(a[1]), "r"(a[2]), "r"(a[3]),
                   "r"(b[0]), "r"(b[1]));
}

// window-scatter address helper (roll +4,+4 then 8x8 windows)
__device__ __forceinline__ size_t win_addr(int t, int h, int e) {
    int n = t >> 14;
    int y = (t >> 7) & 127;
    int x = t & 127;
    int Y = (y + SHIFT) & 127, X = (x + SHIFT) & 127;
    int wyx  = ((Y >> 3) << 4) + (X >> 3);
    int spos = ((Y & 7) << 3) + (X & 7);
    return ((size_t)((n * NHEADS + h) * 256 + wyx)) * 4096 + (size_t)spos * 64 + e;
}

// inverse: window b, slot r -> token index
__device__ __forceinline__ int win_token(int b, int r) {
    int n   = b / (NHEADS * 256);
    int rem = b % (NHEADS * 256);
    int w   = rem & 255;
    int Y = ((w >> 4) << 3) + (r >> 3);
    int X = ((w & 15) << 3) + (r & 7);
    int y = (Y - SHIFT) & 127, x = (X - SHIFT) & 127;
    return (n << 14) + (y << 7) + x;
}

// ---------------------------------------------------------------------------
// GEMM: C = (D?D:0) + A @ B^T. fp16 x fp16, fp32 accum.
// CTA tile 128x256x64, 8 warps (2m x 4n), warp tile 64x64.
// 4-stage cp.async ring, ONE __syncthreads per stage:
//   issue(st+3) at end of compute writes buf (st-1)&3, which every thread
//   finished reading before the collective sync at the top of stage st.
// mode 0: plain (+residual)   mode 1: fused gated-GELU -> g_a
// mode 2: qkv (cols<1536 -> C fp32; cols>=1536 -> scatter V to g_vw)
// ---------------------------------------------------------------------------
#define BKC      64
#define PADK     72
#define TILE_A_E (128 * PADK)
#define TILE_B_E (256 * PADK)
#define STAGE_E  (TILE_A_E + TILE_B_E)       // 27648 elems = 55296 B
#define NSTG     4
#define GEMM_SMEM (NSTG * STAGE_E * 2)       // 221184 bytes

__global__ __launch_bounds__(256) void hgemm_kernel(
    const __half* __restrict__ A, const __half* __restrict__ B,
    const float* __restrict__ Dres, float* __restrict__ C,
    int M, int N, int K, int ldc, int mode)
{
    extern __shared__ __align__(128) char smem[];
    const uint32_t sbase = smem_to_u32(smem);
    const int tid = threadIdx.x, lane = tid & 31, wid = tid >> 5;
    const int wm = wid >> 2, wn = wid & 3;
    const size_t bm = (size_t)blockIdx.y * 128;
    const size_t bn = (size_t)blockIdx.x * 256;

    const __half* Ab = A + bm * (size_t)K;
    const __half* Bb = B + bn * (size_t)K;

    float acc[4][8][4];
    #pragma unroll
    for (int i = 0; i < 4; i++)
        #pragma unroll
        for (int j = 0; j < 8; j++)
            #pragma unroll
            for (int l = 0; l < 4; l++) acc[i][j][l] = 0.f;

    const int nstage = K / BKC;

    // 8 chunks (16B) per row; A: 1024 chunks (4 iters), B: 2048 chunks (8 iters)
    auto issue = [&](int st) {
        const int k0 = st * BKC;
        const uint32_t sb = sbase + (uint32_t)((st & (NSTG - 1)) * STAGE_E * 2);
        #pragma unroll
        for (int i = 0; i < 4; i++) {
            int idx = tid + i * 256;
            int row = idx >> 3, seg = (idx & 7) << 3;
            const __half* gp = Ab + (size_t)row * K + k0 + seg;
            uint32_t sa = sb + (uint32_t)((row * PADK + seg) * 2);
            CP_ASYNC16(sa, gp);
        }
        #pragma unroll
        for (int i = 0; i < 8; i++) {
            int idx = tid + i * 256;
            int row = idx >> 3, seg = (idx & 7) << 3;
            const __half* gp = Bb + (size_t)row * K + k0 + seg;
            uint32_t sa = sb + (uint32_t)((TILE_A_E + row * PADK + seg) * 2);
            CP_ASYNC16(sa, gp);
        }
        CP_COMMIT();
    };

    issue(0);
    if (nstage > 1) issue(1);
    if (nstage > 2) issue(2);

    const int a_r = lane & 15, a_h = (lane >> 4) << 3;
    const int b_r = (lane & 7) + ((lane & 16) >> 1);
    const int b_k = lane & 8;

    for (int st = 0; st < nstage; st++) {
        if (st < nstage - 2)       { CP_WAIT2(); }
        else if (st == nstage - 2) { CP_WAIT1(); }
        else                       { CP_WAIT0(); }
        __syncthreads();

        const uint32_t sb = sbase + (uint32_t)((st & (NSTG - 1)) * STAGE_E * 2);
        const uint32_t sA = sb;
        const uint32_t sB = sb + TILE_A_E * 2;

        #pragma unroll
        for (int kk = 0; kk < BKC; kk += 16) {
            uint32_t a[4][4], bh[8][2];
            #pragma unroll
            for (int mt = 0; mt < 4; mt++)
                ldsm_x4(a[mt][0], a[mt][1], a[mt][2], a[mt][3],
                        sA + (uint32_t)(((wm * 64 + mt * 16 + a_r) * PADK + kk + a_h) * 2));
            #pragma unroll
            for (int p = 0; p < 4; p++) {
                uint32_t r0, r1, r2, r3;
                ldsm_x4(r0, r1, r2, r3,
                        sB + (uint32_t)(((wn * 64 + p * 16 + b_r) * PADK + kk + b_k) * 2));
                bh[p * 2][0] = r0; bh[p * 2][1] = r1;
                bh[p * 2 + 1][0] = r2; bh[p * 2 + 1][1] = r3;
            }
            #pragma unroll
            for (int mt = 0; mt < 4; mt++)
                #pragma unroll
                for (int nt = 0; nt < 8; nt++)
                    mma_f16(acc[mt][nt], a[mt], bh[nt]);
        }
        // no trailing sync: issue into buf (st+3)&3 == (st-1)&3, already safe
        if (st + 3 < nstage) issue(st + 3);
    }

    const int er = lane >> 2, ec = (lane & 3) * 2;

    if (mode == 1) {
        // fused gated GELU: col pair (even,odd) = (a_j, g_j); j = col/2
        #pragma unroll
        for (int mt = 0; mt < 4; mt++) {
            size_t r0 = bm + wm * 64 + mt * 16 + er;
            size_t r1 = r0 + 8;
            #pragma unroll
            for (int nt = 0; nt < 8; nt++) {
                int col = (int)bn + wn * 64 + nt * 8 + ec;
                int j = col >> 1;
                float a0 = acc[mt][nt][0], gg0 = acc[mt][nt][1];
                float a1 = acc[mt][nt][2], gg1 = acc[mt][nt][3];
                float v0 = a0 * (gg0 * 0.5f * (1.0f + erff(gg0 * 0.70710678118654752f)));
                float v1 = a1 * (gg1 * 0.5f * (1.0f + erff(gg1 * 0.70710678118654752f)));
                g_a[r0 * DFF + j] = __float2half(v0);
                g_a[r1 * DFF + j] = __float2half(v1);
            }
        }
        return;
    }

    if (mode == 2 && bn >= 1536) {
        // V region: scatter straight into windowed layout
        #pragma unroll
        for (int mt = 0; mt < 4; mt++) {
            int t0 = (int)bm + wm * 64 + mt * 16 + er;
            int t1 = t0 + 8;
            #pragma unroll
            for (int nt = 0; nt < 8; nt++) {
                int col = (int)bn + wn * 64 + nt * 8 + ec;
                int h = (col - 1536) >> 6;
                int e = col & 63;
                float2 v0 = make_float2(acc[mt][nt][0], acc[mt][nt][1]);
                float2 v1 = make_float2(acc[mt][nt][2], acc[mt][nt][3]);
                *(float2*)&g_vw[win_addr(t0, h, e)] = v0;
                *(float2*)&g_vw[win_addr(t1, h, e)] = v1;
            }
        }
        return;
    }

    #pragma unroll
    for (int mt = 0; mt < 4; mt++) {
        size_t row0 = bm + wm * 64 + mt * 16 + er;
        #pragma unroll
        for (int nt = 0; nt < 8; nt++) {
            size_t col = bn + wn * 64 + nt * 8 + ec;
            float* p0 = C + row0 * (size_t)ldc + col;
            float* p1 = C + (row0 + 8) * (size_t)ldc + col;
            float2 v0 = make_float2(acc[mt][nt][0], acc[mt][nt][1]);
            float2 v1 = make_float2(acc[mt][nt][2], acc[mt][nt][3]);
            if (Dres) {
                const float2 d0 = *(const float2*)(Dres + row0 * (size_t)ldc + col);
                const float2 d1 = *(const float2*)(Dres + (row0 + 8) * (size_t)ldc + col);
                v0.x += d0.x; v0.y += d0.y; v1.x += d1.x; v1.y += d1.y;
            }
            *(float2*)p0 = v0;
            *(float2*)p1 = v1;
        }
    }
}

// ---------------------------------------------------------------------------
// K0: ada scales
// ---------------------------------------------------------------------------
__global__ void ada_kernel(const float* __restrict__ cond,
                           const float* __restrict__ w1,
                           const float* __restrict__ w2)
{
    int gw   = (blockIdx.x * blockDim.x + threadIdx.x) >> 5;
    int lane = threadIdx.x & 31;
    if (gw >= 2 * NBATCH * DM) return;
    int which = gw / (NBATCH * DM);
    int rem   = gw % (NBATCH * DM);
    int n = rem / DM, d = rem % DM;
    const float* w  = which ? w2 : w1;
    const float* cr = cond + n * DC;
    const float* wr = w + (size_t)d * DC;
    float s = 0.f;
    for (int i = lane; i < DC; i += 32) s += cr[i] * wr[i];
    #pragma unroll
    for (int o = 16; o; o >>= 1) s += __shfl_xor_sync(0xffffffffu, s, o);
    if (lane == 0) (which ? g_scale2 : g_scale1)[rem] = s + 1.0f;
}

// ---------------------------------------------------------------------------
// K1: RMSNorm * ada -> fp16
// ---------------------------------------------------------------------------
__global__ __launch_bounds__(256) void rmsnorm_kernel(const float* __restrict__ x,
                                                      const float* __restrict__ scale)
{
    int t = blockIdx.x;
    int n = t >> 14;
    const float* xr = x + (size_t)t * DM;
    float v[3]; float ss = 0.f;
    #pragma unroll
    for (int i = 0; i < 3; i++) { v[i] = xr[threadIdx.x + 256 * i]; ss += v[i] * v[i]; }
    __shared__ float red[8];
    #pragma unroll
    for (int o = 16; o; o >>= 1) ss += __shfl_xor_sync(0xffffffffu, ss, o);
    if ((threadIdx.x & 31) == 0) red[threadIdx.x >> 5] = ss;
    __syncthreads();
    if (threadIdx.x == 0) {
        float r = 0.f;
        #pragma unroll
        for (int i = 0; i < 8; i++) r += red[i];
        red[0] = r;
    }
    __syncthreads();
    float inv = rsqrtf(red[0] * (1.0f / DM) + EPSV);
    const float* sc = scale + (size_t)n * DM;
    #pragma unroll
    for (int i = 0; i < 3; i++) {
        int c = threadIdx.x + 256 * i;
        g_h[(size_t)t * DM + c] = __float2half(v[i] * sc[c] * inv);
    }
}

// ---------------------------------------------------------------------------
// K2: weight convert fp32 -> fp16 (optional row interleave for ff_up)
// ---------------------------------------------------------------------------
__global__ __launch_bounds__(256) void wconv_kernel(const float* __restrict__ w,
                                                    __half* __restrict__ dsth,
                                                    int n, int rowlen, int perm)
{
    int i = blockIdx.x * 256 + threadIdx.x;
    if (i >= n) return;
    int dst = i;
    if (perm) {
        int r = i / rowlen, c = i % rowlen;
        int dr = (r < DFF) ? (2 * r) : (2 * (r - DFF) + 1);
        dst = dr * rowlen + c;
    }
    dsth[dst] = __float2half(w[i]);
}

// ---------------------------------------------------------------------------
// K3: fused attention (R8 proven version)
// ---------------------------------------------------------------------------
#define ATT_PAD  68
#define ATT_SMEM (2 * 64 * ATT_PAD * 4 + 64 * 64 * 4)   // 51200

__global__ __launch_bounds__(64) void attn_kernel(const float* __restrict__ pos,
                                                  const float* __restrict__ attn_scale,
                                                  const float* __restrict__ rope_freqs)
{
    extern __shared__ __align__(16) float sm[];
    float* qR = sm;
    float* kR = sm + 64 * ATT_PAD;
    float* vs = sm + 2 * 64 * ATT_PAD;

    const int b   = blockIdx.x;
    const int rem = b % (NHEADS * 256);
    const int h   = rem >> 8;
    const int w   = rem & 255;
    const bool left = ((w & 15) == 0), top = ((w >> 4) == 0);
    const int tid = threadIdx.x;

    const float* vb = g_vw + (size_t)b * 4096;
    #pragma unroll
    for (int i = tid; i < 1024; i += 64) {
        int r = i >> 4, c4 = (i & 15) << 2;
        int t = win_token(b, r);
        const float* qk = g_qkv + (size_t)t * (2 * DM) + h * DHEAD + c4;
        float4 qv = *(const float4*)qk;
        float4 kv = *(const float4*)(qk + DM);
        float4 vv = *(const float4*)(vb + (i << 2));
        *(float4*)(qR + r * ATT_PAD + c4) = qv;
        *(float4*)(kR + r * ATT_PAD + c4) = kv;
        *(float4*)(vs + r * 64 + c4)      = vv;
    }
    __syncthreads();

    {
        float* qrow = qR + tid * ATT_PAD;
        float* krow = kR + tid * ATT_PAD;
        float sq = 0.f, sk = 0.f;
        #pragma unroll
        for (int e = 0; e < 64; e++) { float a = qrow[e], c = krow[e]; sq += a * a; sk += c * c; }
        float ssh = sqrtf(attn_scale[h]);
        float rq = ssh * rsqrtf(sq + EPSV);
        float rk = ssh * rsqrtf(sk + EPSV);

        int t = win_token(b, tid);
        float p0 = pos[(size_t)t * 2 + 0];
        float p1 = pos[(size_t)t * 2 + 1];
        #pragma unroll
        for (int e = 0; e < 16; e++) {
            float freq = rope_freqs[h * 8 + (e & 7)];
            float th = (e < 8 ? p0 : p1) * freq;
            float c = cosf(th), s = sinf(th);
            float q1 = qrow[e] * rq, q2 = qrow[e + 16] * rq;
            float k1 = krow[e] * rk, k2 = krow[e + 16] * rk;
            qrow[e]      = q1 * c - q2 * s;
            qrow[e + 16] = q2 * c + q1 * s;
            krow[e]      = k1 * c - k2 * s;
            krow[e + 16] = k2 * c + k1 * s;
        }
        #pragma unroll
        for (int e = 32; e < 64; e++) { qrow[e] *= rq; krow[e] *= rk; }
    }
    __syncthreads();

    float sarr[64];
    #pragma unroll
    for (int k = 0; k < 64; k++) sarr[k] = 0.f;
    const float* qrow = qR + tid * ATT_PAD;
    for (int e = 0; e < 64; e += 4) {
        float q0 = qrow[e], q1 = qrow[e + 1], q2 = qrow[e + 2], q3 = qrow[e + 3];
        #pragma unroll
        for (int k = 0; k < 64; k++) {
            float4 kv = *(const float4*)(kR + k * ATT_PAD + e);
            sarr[k] += q0 * kv.x + q1 * kv.y + q2 * kv.z + q3 * kv.w;
        }
    }

    int qh = tid >> 3, qw_ = tid & 7;
    bool qa = qh < SHIFT, ql = qw_ < SHIFT;
    float mx = -3.402823466e38f;
    #pragma unroll
    for (int k = 0; k < 64; k++) {
        int kh = k >> 3, kw = k & 7;
        bool ka = kh < SHIFT, kl = kw < SHIFT;
        bool m = (!left && !top)
               || (left && top && (ql == kl) && (qa == ka))
               || (left && !top && (ql == kl))
               || (!left && top && (qa == ka));
        if (!m) sarr[k] = -3.402823466e38f;
        mx = fmaxf(mx, sarr[k]);
    }
    float sum = 0.f;
    #pragma unroll
    for (int k = 0; k < 64; k++) {
        float p = __expf(sarr[k] - mx);
        sarr[k] = p;
        sum += p;
    }
    float inv = 1.0f / sum;

    float* orow = qR + tid * ATT_PAD;
    for (int e = 0; e < 64; e += 4) {
        float ax = 0.f, ay = 0.f, az = 0.f, aw = 0.f;
        #pragma unroll
        for (int k = 0; k < 64; k++) {
            float4 vv = *(const float4*)(vs + k * 64 + e);
            float p = sarr[k];
            ax += p * vv.x; ay += p * vv.y; az += p * vv.z; aw += p * vv.w;
        }
        orow[e] = ax * inv; orow[e + 1] = ay * inv;
        orow[e + 2] = az * inv; orow[e + 3] = aw * inv;
    }
    __syncthreads();

    #pragma unroll
    for (int i = tid; i < 1024; i += 64) {
        int r = i >> 4, c4 = (i & 15) << 2;
        int t = win_token(b, r);
        size_t dst = (size_t)t * DM + h * DHEAD + c4;
        const float* src = qR + r * ATT_PAD + c4;
        __half h4[4];
        #pragma unroll
        for (int j = 0; j < 4; j++) h4[j] = __float2half(src[j]);
        *(uint2*)&g_oi[dst] = *(uint2*)h4;
    }
}

// ---------------------------------------------------------------------------
// host
// ---------------------------------------------------------------------------
static void launch_hgemm(const __half* A, const __half* B,
                         const float* D, float* C, int M, int N, int K,
                         int ldc, int mode)
{
    dim3 grid(N / 256, M / 128);
    hgemm_kernel<<<grid, 256, GEMM_SMEM>>>(A, B, D, C, M, N, K, ldc, mode);
}

extern "C" void kernel_launch(void* const* d_in, const int* in_sizes, int n_in,
                              void* d_out, int out_size)
{
    const float* x          = (const float*)d_in[0];
    const float* pos        = (const float*)d_in[1];
    const float* cond       = (const float*)d_in[2];
    const float* ada1_w     = (const float*)d_in[3];
    const float* qkv_w      = (const float*)d_in[4];
    const float* attn_scale = (const float*)d_in[5];
    const float* rope_freqs = (const float*)d_in[6];
    const float* out_w      = (const float*)d_in[7];
    const float* ada2_w     = (const float*)d_in[8];
    const float* ff_up_w    = (const float*)d_in[9];
    const float* ff_down_w  = (const float*)d_in[10];
    float* out = (float*)d_out;

    cudaFuncSetAttribute(hgemm_kernel, cudaFuncAttributeMaxDynamicSharedMemorySize, GEMM_SMEM);
    cudaFuncSetAttribute(attn_kernel, cudaFuncAttributeMaxDynamicSharedMemorySize, ATT_SMEM);

    float *p_scale1, *p_scale2, *p_qkv, *p_x2;
    __half *p_h, *p_oi, *p_a, *p_w;
    cudaGetSymbolAddress((void**)&p_scale1, g_scale1);
    cudaGetSymbolAddress((void**)&p_scale2, g_scale2);
    cudaGetSymbolAddress((void**)&p_qkv,    g_qkv);
    cudaGetSymbolAddress((void**)&p_x2,     g_x2);
    cudaGetSymbolAddress((void**)&p_h,      g_h);
    cudaGetSymbolAddress((void**)&p_oi,     g_oi);
    cudaGetSymbolAddress((void**)&p_a,      g_a);
    cudaGetSymbolAddress((void**)&p_w,      g_w);

    const int OQKV = 0;
    const int OOUT = OQKV + W_QKV_SZ;
    const int OUP  = OOUT + W_OUT_SZ;
    const int ODN  = OUP + W_UP_SZ;

    wconv_kernel<<<(W_QKV_SZ + 255) / 256, 256>>>(qkv_w,     p_w + OQKV, W_QKV_SZ, DM, 0);
    wconv_kernel<<<(W_OUT_SZ + 255) / 256, 256>>>(out_w,     p_w + OOUT, W_OUT_SZ, DM, 0);
    wconv_kernel<<<(W_UP_SZ  + 255) / 256, 256>>>(ff_up_w,   p_w + OUP,  W_UP_SZ,  DM, 1);
    wconv_kernel<<<(W_DN_SZ  + 255) / 256, 256>>>(ff_down_w, p_w + ODN,  W_DN_SZ,  DFF, 0);

    ada_kernel<<<768, 256>>>(cond, ada1_w, ada2_w);
    rmsnorm_kernel<<<TOKENS, 256>>>(x, p_scale1);
    // qkv: q,k -> g_qkv (ldc=1536); v -> scatter to g_vw
    launch_hgemm(p_h, p_w + OQKV, nullptr, p_qkv, TOKENS, 3 * DM, DM, 2 * DM, 2);
    // fused qk-transform + attention + unwindow
    attn_kernel<<<NWIN, 64, ATT_SMEM>>>(pos, attn_scale, rope_freqs);
    launch_hgemm(p_oi, p_w + OOUT, x, p_x2, TOKENS, DM, DM, DM, 0);
    rmsnorm_kernel<<<TOKENS, 256>>>(p_x2, p_scale2);
    // ff_up with fused gated GELU (interleaved weights) -> g_a
    launch_hgemm(p_h, p_w + OUP, nullptr, nullptr, TOKENS, 2 * DFF, DM, 2 * DFF, 1);
    launch_hgemm(p_a, p_w + ODN, p_x2, out, TOKENS, DM, DFF, DM, 0);
}

// round 13
// speedup vs baseline: 2.5561x; 1.0739x over previous
#include <cuda_runtime.h>
#include <cuda_bf16.h>
#include <cuda_fp16.h>
#include <math.h>
#include <stdint.h>

// ---------------------------------------------------------------------------
// Problem constants
// ---------------------------------------------------------------------------
#define NBATCH   4
#define HDIM     128
#define WDIM     128
#define DM       768
#define NHEADS   12
#define DHEAD    64
#define DFF      2048
#define DC       768
#define WS       8
#define SHIFT    4
#define TOKENS   (NBATCH * HDIM * WDIM)          // 65536
#define NWIN     (NBATCH * NHEADS * 16 * 16)     // 12288
#define EPSV     1e-6f

// ---------------------------------------------------------------------------
// Scratch
// ---------------------------------------------------------------------------
#define W_QKV_SZ (3 * DM * DM)
#define W_OUT_SZ (DM * DM)
#define W_UP_SZ  (2 * DFF * DM)
#define W_DN_SZ  (DM * DFF)
#define W_TOTAL  (W_QKV_SZ + W_OUT_SZ + W_UP_SZ + W_DN_SZ)

__device__ float g_scale1[NBATCH * DM];
__device__ float g_scale2[NBATCH * DM];
__device__ float g_qkv [(size_t)TOKENS * 2 * DM];     // q,k fp32 (ldc=1536)
__device__ float g_vw  [(size_t)NWIN * 64 * 64];      // v windowed fp32
__device__ float g_x2  [(size_t)TOKENS * DM];

__device__ __half g_h  [(size_t)TOKENS * DM];         // activations fp16
__device__ __half g_oi [(size_t)TOKENS * DM];
__device__ __half g_a  [(size_t)TOKENS * DFF];
__device__ __half g_w  [W_TOTAL];                     // weights fp16 (single)

// ---------------------------------------------------------------------------
// PTX helpers (sm_80+ features only; legal under compute_103)
// ---------------------------------------------------------------------------
__device__ __forceinline__ uint32_t smem_to_u32(const void* p) {
    uint32_t a;
    asm("{ .reg .u64 t; cvta.to.shared.u64 t, %1; cvt.u32.u64 %0, t; }" : "=r"(a) : "l"(p));
    return a;
}
#define CP_ASYNC16(sa, gp) \
    asm volatile("cp.async.cg.shared.global [%0], [%1], 16;" :: "r"(sa), "l"(gp))
#define CP_COMMIT() asm volatile("cp.async.commit_group;" ::: "memory")
#define CP_WAIT2()  asm volatile("cp.async.wait_group 2;" ::: "memory")
#define CP_WAIT1()  asm volatile("cp.async.wait_group 1;" ::: "memory")
#define CP_WAIT0()  asm volatile("cp.async.wait_group 0;" ::: "memory")

__device__ __forceinline__ void ldsm_x4(uint32_t& r0, uint32_t& r1, uint32_t& r2,
                                        uint32_t& r3, uint32_t addr) {
    asm volatile("ldmatrix.sync.aligned.m8n8.x4.shared.b16 {%0,%1,%2,%3}, [%4];"
                 : "=r"(r0), "=r"(r1), "=r"(r2), "=r"(r3) : "r"(addr));
}
__device__ __forceinline__ void ldsm_x4_t(uint32_t& r0, uint32_t& r1, uint32_t& r2,
                                          uint32_t& r3, uint32_t addr) {
    asm volatile("ldmatrix.sync.aligned.m8n8.x4.trans.shared.b16 {%0,%1,%2,%3}, [%4];"
                 : "=r"(r0), "=r"(r1), "=r"(r2), "=r"(r3) : "r"(addr));
}
__device__ __forceinline__ void mma_f16(float c[4], const uint32_t a[4],
                                        const uint32_t b[2]) {
    asm volatile("mma.sync.aligned.m16n8k16.row.col.f32.f16.f16.f32 "
                 "{%0,%1,%2,%3},{%4,%5,%6,%7},{%8,%9},{%0,%1,%2,%3};"
                 : "+f"(c[0]), "+f"(c[1]), "+f"(c[2]), "+f"(c[3])
                 : "r"(a[0]), "r"(a[1]), "r"(a[2]), "r"(a[3]),
                   "r"(b[0]), "r"(b[1]));
}
__device__ __forceinline__ uint32_t pack_h2(float a, float b) {
    __half2 h = __floats2half2_rn(a, b);
    return *(uint32_t*)&h;
}

// window-scatter address helper (roll +4,+4 then 8x8 windows)
__device__ __forceinline__ size_t win_addr(int t, int h, int e) {
    int n = t >> 14;
    int y = (t >> 7) & 127;
    int x = t & 127;
    int Y = (y + SHIFT) & 127, X = (x + SHIFT) & 127;
    int wyx  = ((Y >> 3) << 4) + (X >> 3);
    int spos = ((Y & 7) << 3) + (X & 7);
    return ((size_t)((n * NHEADS + h) * 256 + wyx)) * 4096 + (size_t)spos * 64 + e;
}

// inverse: window b, slot r -> token index
__device__ __forceinline__ int win_token(int b, int r) {
    int n   = b / (NHEADS * 256);
    int rem = b % (NHEADS * 256);
    int w   = rem & 255;
    int Y = ((w >> 4) << 3) + (r >> 3);
    int X = ((w & 15) << 3) + (r & 7);
    int y = (Y - SHIFT) & 127, x = (X - SHIFT) & 127;
    return (n << 14) + (y << 7) + x;
}

// ---------------------------------------------------------------------------
// GEMM (R12 proven): 128x256x64 tile, 8 warps, 4-stage ring, 1 sync/stage.
// ---------------------------------------------------------------------------
#define BKC      64
#define PADK     72
#define TILE_A_E (128 * PADK)
#define TILE_B_E (256 * PADK)
#define STAGE_E  (TILE_A_E + TILE_B_E)
#define NSTG     4
#define GEMM_SMEM (NSTG * STAGE_E * 2)       // 221184 bytes

__global__ __launch_bounds__(256) void hgemm_kernel(
    const __half* __restrict__ A, const __half* __restrict__ B,
    const float* __restrict__ Dres, float* __restrict__ C,
    int M, int N, int K, int ldc, int mode)
{
    extern __shared__ __align__(128) char smem[];
    const uint32_t sbase = smem_to_u32(smem);
    const int tid = threadIdx.x, lane = tid & 31, wid = tid >> 5;
    const int wm = wid >> 2, wn = wid & 3;
    const size_t bm = (size_t)blockIdx.y * 128;
    const size_t bn = (size_t)blockIdx.x * 256;

    const __half* Ab = A + bm * (size_t)K;
    const __half* Bb = B + bn * (size_t)K;

    float acc[4][8][4];
    #pragma unroll
    for (int i = 0; i < 4; i++)
        #pragma unroll
        for (int j = 0; j < 8; j++)
            #pragma unroll
            for (int l = 0; l < 4; l++) acc[i][j][l] = 0.f;

    const int nstage = K / BKC;

    auto issue = [&](int st) {
        const int k0 = st * BKC;
        const uint32_t sb = sbase + (uint32_t)((st & (NSTG - 1)) * STAGE_E * 2);
        #pragma unroll
        for (int i = 0; i < 4; i++) {
            int idx = tid + i * 256;
            int row = idx >> 3, seg = (idx & 7) << 3;
            const __half* gp = Ab + (size_t)row * K + k0 + seg;
            uint32_t sa = sb + (uint32_t)((row * PADK + seg) * 2);
            CP_ASYNC16(sa, gp);
        }
        #pragma unroll
        for (int i = 0; i < 8; i++) {
            int idx = tid + i * 256;
            int row = idx >> 3, seg = (idx & 7) << 3;
            const __half* gp = Bb + (size_t)row * K + k0 + seg;
            uint32_t sa = sb + (uint32_t)((TILE_A_E + row * PADK + seg) * 2);
            CP_ASYNC16(sa, gp);
        }
        CP_COMMIT();
    };

    issue(0);
    if (nstage > 1) issue(1);
    if (nstage > 2) issue(2);

    const int a_r = lane & 15, a_h = (lane >> 4) << 3;
    const int b_r = (lane & 7) + ((lane & 16) >> 1);
    const int b_k = lane & 8;

    for (int st = 0; st < nstage; st++) {
        if (st < nstage - 2)       { CP_WAIT2(); }
        else if (st == nstage - 2) { CP_WAIT1(); }
        else                       { CP_WAIT0(); }
        __syncthreads();

        const uint32_t sb = sbase + (uint32_t)((st & (NSTG - 1)) * STAGE_E * 2);
        const uint32_t sA = sb;
        const uint32_t sB = sb + TILE_A_E * 2;

        #pragma unroll
        for (int kk = 0; kk < BKC; kk += 16) {
            uint32_t a[4][4], bh[8][2];
            #pragma unroll
            for (int mt = 0; mt < 4; mt++)
                ldsm_x4(a[mt][0], a[mt][1], a[mt][2], a[mt][3],
                        sA + (uint32_t)(((wm * 64 + mt * 16 + a_r) * PADK + kk + a_h) * 2));
            #pragma unroll
            for (int p = 0; p < 4; p++) {
                uint32_t r0, r1, r2, r3;
                ldsm_x4(r0, r1, r2, r3,
                        sB + (uint32_t)(((wn * 64 + p * 16 + b_r) * PADK + kk + b_k) * 2));
                bh[p * 2][0] = r0; bh[p * 2][1] = r1;
                bh[p * 2 + 1][0] = r2; bh[p * 2 + 1][1] = r3;
            }
            #pragma unroll
            for (int mt = 0; mt < 4; mt++)
                #pragma unroll
                for (int nt = 0; nt < 8; nt++)
                    mma_f16(acc[mt][nt], a[mt], bh[nt]);
        }
        if (st + 3 < nstage) issue(st + 3);
    }

    const int er = lane >> 2, ec = (lane & 3) * 2;

    if (mode == 1) {
        #pragma unroll
        for (int mt = 0; mt < 4; mt++) {
            size_t r0 = bm + wm * 64 + mt * 16 + er;
            size_t r1 = r0 + 8;
            #pragma unroll
            for (int nt = 0; nt < 8; nt++) {
                int col = (int)bn + wn * 64 + nt * 8 + ec;
                int j = col >> 1;
                float a0 = acc[mt][nt][0], gg0 = acc[mt][nt][1];
                float a1 = acc[mt][nt][2], gg1 = acc[mt][nt][3];
                float v0 = a0 * (gg0 * 0.5f * (1.0f + erff(gg0 * 0.70710678118654752f)));
                float v1 = a1 * (gg1 * 0.5f * (1.0f + erff(gg1 * 0.70710678118654752f)));
                g_a[r0 * DFF + j] = __float2half(v0);
                g_a[r1 * DFF + j] = __float2half(v1);
            }
        }
        return;
    }

    if (mode == 2 && bn >= 1536) {
        #pragma unroll
        for (int mt = 0; mt < 4; mt++) {
            int t0 = (int)bm + wm * 64 + mt * 16 + er;
            int t1 = t0 + 8;
            #pragma unroll
            for (int nt = 0; nt < 8; nt++) {
                int col = (int)bn + wn * 64 + nt * 8 + ec;
                int h = (col - 1536) >> 6;
                int e = col & 63;
                float2 v0 = make_float2(acc[mt][nt][0], acc[mt][nt][1]);
                float2 v1 = make_float2(acc[mt][nt][2], acc[mt][nt][3]);
                *(float2*)&g_vw[win_addr(t0, h, e)] = v0;
                *(float2*)&g_vw[win_addr(t1, h, e)] = v1;
            }
        }
        return;
    }

    #pragma unroll
    for (int mt = 0; mt < 4; mt++) {
        size_t row0 = bm + wm * 64 + mt * 16 + er;
        #pragma unroll
        for (int nt = 0; nt < 8; nt++) {
            size_t col = bn + wn * 64 + nt * 8 + ec;
            float* p0 = C + row0 * (size_t)ldc + col;
            float* p1 = C + (row0 + 8) * (size_t)ldc + col;
            float2 v0 = make_float2(acc[mt][nt][0], acc[mt][nt][1]);
            float2 v1 = make_float2(acc[mt][nt][2], acc[mt][nt][3]);
            if (Dres) {
                const float2 d0 = *(const float2*)(Dres + row0 * (size_t)ldc + col);
                const float2 d1 = *(const float2*)(Dres + (row0 + 8) * (size_t)ldc + col);
                v0.x += d0.x; v0.y += d0.y; v1.x += d1.x; v1.y += d1.y;
            }
            *(float2*)p0 = v0;
            *(float2*)p1 = v1;
        }
    }
}

// ---------------------------------------------------------------------------
// K0: ada scales
// ---------------------------------------------------------------------------
__global__ void ada_kernel(const float* __restrict__ cond,
                           const float* __restrict__ w1,
                           const float* __restrict__ w2)
{
    int gw   = (blockIdx.x * blockDim.x + threadIdx.x) >> 5;
    int lane = threadIdx.x & 31;
    if (gw >= 2 * NBATCH * DM) return;
    int which = gw / (NBATCH * DM);
    int rem   = gw % (NBATCH * DM);
    int n = rem / DM, d = rem % DM;
    const float* w  = which ? w2 : w1;
    const float* cr = cond + n * DC;
    const float* wr = w + (size_t)d * DC;
    float s = 0.f;
    for (int i = lane; i < DC; i += 32) s += cr[i] * wr[i];
    #pragma unroll
    for (int o = 16; o; o >>= 1) s += __shfl_xor_sync(0xffffffffu, s, o);
    if (lane == 0) (which ? g_scale2 : g_scale1)[rem] = s + 1.0f;
}

// ---------------------------------------------------------------------------
// K1: RMSNorm * ada -> fp16
// ---------------------------------------------------------------------------
__global__ __launch_bounds__(256) void rmsnorm_kernel(const float* __restrict__ x,
                                                      const float* __restrict__ scale)
{
    int t = blockIdx.x;
    int n = t >> 14;
    const float* xr = x + (size_t)t * DM;
    float v[3]; float ss = 0.f;
    #pragma unroll
    for (int i = 0; i < 3; i++) { v[i] = xr[threadIdx.x + 256 * i]; ss += v[i] * v[i]; }
    __shared__ float red[8];
    #pragma unroll
    for (int o = 16; o; o >>= 1) ss += __shfl_xor_sync(0xffffffffu, ss, o);
    if ((threadIdx.x & 31) == 0) red[threadIdx.x >> 5] = ss;
    __syncthreads();
    if (threadIdx.x == 0) {
        float r = 0.f;
        #pragma unroll
        for (int i = 0; i < 8; i++) r += red[i];
        red[0] = r;
    }
    __syncthreads();
    float inv = rsqrtf(red[0] * (1.0f / DM) + EPSV);
    const float* sc = scale + (size_t)n * DM;
    #pragma unroll
    for (int i = 0; i < 3; i++) {
        int c = threadIdx.x + 256 * i;
        g_h[(size_t)t * DM + c] = __float2half(v[i] * sc[c] * inv);
    }
}

// ---------------------------------------------------------------------------
// K2: weight convert fp32 -> fp16 (optional row interleave for ff_up)
// ---------------------------------------------------------------------------
__global__ __launch_bounds__(256) void wconv_kernel(const float* __restrict__ w,
                                                    __half* __restrict__ dsth,
                                                    int n, int rowlen, int perm)
{
    int i = blockIdx.x * 256 + threadIdx.x;
    if (i >= n) return;
    int dst = i;
    if (perm) {
        int r = i / rowlen, c = i % rowlen;
        int dr = (r < DFF) ? (2 * r) : (2 * (r - DFF) + 1);
        dst = dr * rowlen + c;
    }
    dsth[dst] = __float2half(w[i]);
}

// ---------------------------------------------------------------------------
// K3: fused attention on tensor cores.
// 128 threads = 4 warps; warp w owns query rows 16w..16w+15.
// fp32 gather+norm+RoPE -> fp16 smem -> HMMA scores -> fragment softmax ->
// HMMA PV -> fragment-direct fp16 store to g_oi.
// ---------------------------------------------------------------------------
#define AFP  68                                // fp32 row pad (floats)
#define AHP  72                                // fp16 row pad (halfs)
#define AQF  0
#define AKF  (64 * AFP * 4)
#define AQH  (2 * 64 * AFP * 4)                // 34816
#define AKH  (AQH + 64 * AHP * 2)              // 44032
#define AVH  (AKH + 64 * AHP * 2)              // 53248
#define ATT_SMEM (AVH + 64 * AHP * 2)          // 62464

__global__ __launch_bounds__(128) void attn_kernel(const float* __restrict__ pos,
                                                   const float* __restrict__ attn_scale,
                                                   const float* __restrict__ rope_freqs)
{
    extern __shared__ __align__(16) char smc[];
    float* qf = (float*)(smc + AQF);
    float* kf = (float*)(smc + AKF);
    const uint32_t sb = smem_to_u32(smc);
    const uint32_t qh_b = sb + AQH, kh_b = sb + AKH, vh_b = sb + AVH;

    const int b   = blockIdx.x;
    const int rem = b % (NHEADS * 256);
    const int h   = rem >> 8;
    const int w   = rem & 255;
    const bool left = ((w & 15) == 0), top = ((w >> 4) == 0);
    const int tid = threadIdx.x, warp = tid >> 5, lane = tid & 31;

    // gather: q,k fp32; v fp32->fp16 direct
    const float* vb = g_vw + (size_t)b * 4096;
    for (int i = tid; i < 1024; i += 128) {
        int r = i >> 4, c4 = (i & 15) << 2;
        int t = win_token(b, r);
        const float* qk = g_qkv + (size_t)t * (2 * DM) + h * DHEAD + c4;
        float4 qv = *(const float4*)qk;
        float4 kv = *(const float4*)(qk + DM);
        *(float4*)(qf + r * AFP + c4) = qv;
        *(float4*)(kf + r * AFP + c4) = kv;
        float4 vv = *(const float4*)(vb + (i << 2));
        uint2 pk;
        pk.x = pack_h2(vv.x, vv.y);
        pk.y = pack_h2(vv.z, vv.w);
        *(uint2*)(smc + AVH + (r * AHP + c4) * 2) = pk;
    }
    __syncthreads();

    // per-row transform in fp32 (threads 0..63)
    if (tid < 64) {
        float* qrow = qf + tid * AFP;
        float* krow = kf + tid * AFP;
        float sq = 0.f, sk = 0.f;
        #pragma unroll
        for (int e = 0; e < 64; e++) { float a = qrow[e], c = krow[e]; sq += a * a; sk += c * c; }
        float ssh = sqrtf(attn_scale[h]);
        float rq = ssh * rsqrtf(sq + EPSV);
        float rk = ssh * rsqrtf(sk + EPSV);

        int t = win_token(b, tid);
        float p0 = pos[(size_t)t * 2 + 0];
        float p1 = pos[(size_t)t * 2 + 1];
        #pragma unroll
        for (int e = 0; e < 16; e++) {
            float freq = rope_freqs[h * 8 + (e & 7)];
            float th = (e < 8 ? p0 : p1) * freq;
            float c = cosf(th), s = sinf(th);
            float q1 = qrow[e] * rq, q2 = qrow[e + 16] * rq;
            float k1 = krow[e] * rk, k2 = krow[e + 16] * rk;
            qrow[e]      = q1 * c - q2 * s;
            qrow[e + 16] = q2 * c + q1 * s;
            krow[e]      = k1 * c - k2 * s;
            krow[e + 16] = k2 * c + k1 * s;
        }
        #pragma unroll
        for (int e = 32; e < 64; e++) { qrow[e] *= rq; krow[e] *= rk; }
    }
    __syncthreads();

    // convert q,k fp32 -> fp16 (all threads)
    for (int i = tid; i < 1024; i += 128) {
        int r = i >> 4, c4 = (i & 15) << 2;
        float4 qv = *(const float4*)(qf + r * AFP + c4);
        float4 kv = *(const float4*)(kf + r * AFP + c4);
        uint2 pq, pk;
        pq.x = pack_h2(qv.x, qv.y); pq.y = pack_h2(qv.z, qv.w);
        pk.x = pack_h2(kv.x, kv.y); pk.y = pack_h2(kv.z, kv.w);
        *(uint2*)(smc + AQH + (r * AHP + c4) * 2) = pq;
        *(uint2*)(smc + AKH + (r * AHP + c4) * 2) = pk;
    }
    __syncthreads();

    // ---- scores: S = Q K^T (m16 x n64 x k64 per warp) ----
    const int a_r = lane & 15, a_h2 = (lane >> 4) << 3;
    const int b_r = (lane & 7) + ((lane & 16) >> 1);
    const int b_k = lane & 8;

    float sc[8][4];
    #pragma unroll
    for (int nt = 0; nt < 8; nt++)
        #pragma unroll
        for (int j = 0; j < 4; j++) sc[nt][j] = 0.f;

    uint32_t afr[4][4];
    #pragma unroll
    for (int kt = 0; kt < 4; kt++)
        ldsm_x4(afr[kt][0], afr[kt][1], afr[kt][2], afr[kt][3],
                qh_b + (uint32_t)(((warp * 16 + a_r) * AHP + kt * 16 + a_h2) * 2));

    #pragma unroll
    for (int kt = 0; kt < 4; kt++) {
        uint32_t bh[8][2];
        #pragma unroll
        for (int p = 0; p < 4; p++) {
            uint32_t r0, r1, r2, r3;
            ldsm_x4(r0, r1, r2, r3,
                    kh_b + (uint32_t)(((p * 16 + b_r) * AHP + kt * 16 + b_k) * 2));
            bh[p * 2][0] = r0; bh[p * 2][1] = r1;
            bh[p * 2 + 1][0] = r2; bh[p * 2 + 1][1] = r3;
        }
        #pragma unroll
        for (int nt = 0; nt < 8; nt++)
            mma_f16(sc[nt], afr[kt], bh[nt]);
    }

    // ---- fragment mask + softmax ----
    const int er = lane >> 2, ec = (lane & 3) * 2;
    const int r0 = warp * 16 + er, r1 = r0 + 8;
    const bool qa0 = ((r0 >> 3) < SHIFT), ql0 = ((r0 & 7) < SHIFT);
    const bool qa1 = ((r1 >> 3) < SHIFT), ql1 = ((r1 & 7) < SHIFT);

    float mx0 = -3.402823466e38f, mx1 = -3.402823466e38f;
    #pragma unroll
    for (int nt = 0; nt < 8; nt++) {
        bool ka = nt < SHIFT;
        #pragma unroll
        for (int j = 0; j < 2; j++) {
            bool kl = (ec + j) < SHIFT;
            bool m0 = (!left && !top)
                    || (left && top && (ql0 == kl) && (qa0 == ka))
                    || (left && !top && (ql0 == kl))
                    || (!left && top && (qa0 == ka));
            bool m1 = (!left && !top)
                    || (left && top && (ql1 == kl) && (qa1 == ka))
                    || (left && !top && (ql1 == kl))
                    || (!left && top && (qa1 == ka));
            if (!m0) sc[nt][j]     = -3.402823466e38f;
            if (!m1) sc[nt][2 + j] = -3.402823466e38f;
            mx0 = fmaxf(mx0, sc[nt][j]);
            mx1 = fmaxf(mx1, sc[nt][2 + j]);
        }
    }
    mx0 = fmaxf(mx0, __shfl_xor_sync(0xffffffffu, mx0, 1));
    mx0 = fmaxf(mx0, __shfl_xor_sync(0xffffffffu, mx0, 2));
    mx1 = fmaxf(mx1, __shfl_xor_sync(0xffffffffu, mx1, 1));
    mx1 = fmaxf(mx1, __shfl_xor_sync(0xffffffffu, mx1, 2));

    float s0 = 0.f, s1 = 0.f;
    #pragma unroll
    for (int nt = 0; nt < 8; nt++) {
        #pragma unroll
        for (int j = 0; j < 2; j++) {
            float p0v = __expf(sc[nt][j] - mx0);
            float p1v = __expf(sc[nt][2 + j] - mx1);
            sc[nt][j] = p0v; sc[nt][2 + j] = p1v;
            s0 += p0v; s1 += p1v;
        }
    }
    s0 += __shfl_xor_sync(0xffffffffu, s0, 1);
    s0 += __shfl_xor_sync(0xffffffffu, s0, 2);
    s1 += __shfl_xor_sync(0xffffffffu, s1, 1);
    s1 += __shfl_xor_sync(0xffffffffu, s1, 2);
    float inv0 = 1.0f / s0, inv1 = 1.0f / s1;

    // ---- pack P to fp16 A-fragments (C-frag -> A-frag identity) ----
    uint32_t pf[4][4];
    #pragma unroll
    for (int kt = 0; kt < 4; kt++) {
        pf[kt][0] = pack_h2(sc[2 * kt][0],     sc[2 * kt][1]);
        pf[kt][1] = pack_h2(sc[2 * kt][2],     sc[2 * kt][3]);
        pf[kt][2] = pack_h2(sc[2 * kt + 1][0], sc[2 * kt + 1][1]);
        pf[kt][3] = pack_h2(sc[2 * kt + 1][2], sc[2 * kt + 1][3]);
    }

    // ---- O = P V (m16 x n64 x k64) ----
    float oo[8][4];
    #pragma unroll
    for (int nt = 0; nt < 8; nt++)
        #pragma unroll
        for (int j = 0; j < 4; j++) oo[nt][j] = 0.f;

    const int v_r = lane & 15, v_c = (lane >> 4) << 3;
    #pragma unroll
    for (int kt = 0; kt < 4; kt++) {
        uint32_t bv[8][2];
        #pragma unroll
        for (int p = 0; p < 4; p++) {
            uint32_t r0v, r1v, r2v, r3v;
            ldsm_x4_t(r0v, r1v, r2v, r3v,
                      vh_b + (uint32_t)(((kt * 16 + v_r) * AHP + p * 16 + v_c) * 2));
            bv[p * 2][0] = r0v; bv[p * 2][1] = r1v;
            bv[p * 2 + 1][0] = r2v; bv[p * 2 + 1][1] = r3v;
        }
        #pragma unroll
        for (int nt = 0; nt < 8; nt++)
            mma_f16(oo[nt], pf[kt], bv[nt]);
    }

    // ---- fragment-direct store ----
    int t0 = win_token(b, r0), t1 = win_token(b, r1);
    #pragma unroll
    for (int nt = 0; nt < 8; nt++) {
        int col = h * DHEAD + nt * 8 + ec;
        uint32_t w0 = pack_h2(oo[nt][0] * inv0, oo[nt][1] * inv0);
        uint32_t w1 = pack_h2(oo[nt][2] * inv1, oo[nt][3] * inv1);
        *(uint32_t*)&g_oi[(size_t)t0 * DM + col] = w0;
        *(uint32_t*)&g_oi[(size_t)t1 * DM + col] = w1;
    }
}

// ---------------------------------------------------------------------------
// host
// ---------------------------------------------------------------------------
static void launch_hgemm(const __half* A, const __half* B,
                         const float* D, float* C, int M, int N, int K,
                         int ldc, int mode)
{
    dim3 grid(N / 256, M / 128);
    hgemm_kernel<<<grid, 256, GEMM_SMEM>>>(A, B, D, C, M, N, K, ldc, mode);
}

extern "C" void kernel_launch(void* const* d_in, const int* in_sizes, int n_in,
                              void* d_out, int out_size)
{
    const float* x          = (const float*)d_in[0];
    const float* pos        = (const float*)d_in[1];
    const float* cond       = (const float*)d_in[2];
    const float* ada1_w     = (const float*)d_in[3];
    const float* qkv_w      = (const float*)d_in[4];
    const float* attn_scale = (const float*)d_in[5];
    const float* rope_freqs = (const float*)d_in[6];
    const float* out_w      = (const float*)d_in[7];
    const float* ada2_w     = (const float*)d_in[8];
    const float* ff_up_w    = (const float*)d_in[9];
    const float* ff_down_w  = (const float*)d_in[10];
    float* out = (float*)d_out;

    cudaFuncSetAttribute(hgemm_kernel, cudaFuncAttributeMaxDynamicSharedMemorySize, GEMM_SMEM);
    cudaFuncSetAttribute(attn_kernel, cudaFuncAttributeMaxDynamicSharedMemorySize, ATT_SMEM);

    float *p_scale1, *p_scale2, *p_qkv, *p_x2;
    __half *p_h, *p_oi, *p_a, *p_w;
    cudaGetSymbolAddress((void**)&p_scale1, g_scale1);
    cudaGetSymbolAddress((void**)&p_scale2, g_scale2);
    cudaGetSymbolAddress((void**)&p_qkv,    g_qkv);
    cudaGetSymbolAddress((void**)&p_x2,     g_x2);
    cudaGetSymbolAddress((void**)&p_h,      g_h);
    cudaGetSymbolAddress((void**)&p_oi,     g_oi);
    cudaGetSymbolAddress((void**)&p_a,      g_a);
    cudaGetSymbolAddress((void**)&p_w,      g_w);

    const int OQKV = 0;
    const int OOUT = OQKV + W_QKV_SZ;
    const int OUP  = OOUT + W_OUT_SZ;
    const int ODN  = OUP + W_UP_SZ;

    wconv_kernel<<<(W_QKV_SZ + 255) / 256, 256>>>(qkv_w,     p_w + OQKV, W_QKV_SZ, DM, 0);
    wconv_kernel<<<(W_OUT_SZ + 255) / 256, 256>>>(out_w,     p_w + OOUT, W_OUT_SZ, DM, 0);
    wconv_kernel<<<(W_UP_SZ  + 255) / 256, 256>>>(ff_up_w,   p_w + OUP,  W_UP_SZ,  DM, 1);
    wconv_kernel<<<(W_DN_SZ  + 255) / 256, 256>>>(ff_down_w, p_w + ODN,  W_DN_SZ,  DFF, 0);

    ada_kernel<<<768, 256>>>(cond, ada1_w, ada2_w);
    rmsnorm_kernel<<<TOKENS, 256>>>(x, p_scale1);
    // qkv: q,k -> g_qkv (ldc=1536); v -> scatter to g_vw
    launch_hgemm(p_h, p_w + OQKV, nullptr, p_qkv, TOKENS, 3 * DM, DM, 2 * DM, 2);
    // fused qk-transform + tensor-core attention + unwindow
    attn_kernel<<<NWIN, 128, ATT_SMEM>>>(pos, attn_scale, rope_freqs);
    launch_hgemm(p_oi, p_w + OOUT, x, p_x2, TOKENS, DM, DM, DM, 0);
    rmsnorm_kernel<<<TOKENS, 256>>>(p_x2, p_scale2);
    // ff_up with fused gated GELU (interleaved weights) -> g_a
    launch_hgemm(p_h, p_w + OUP, nullptr, nullptr, TOKENS, 2 * DFF, DM, 2 * DFF, 1);
    launch_hgemm(p_a, p_w + ODN, p_x2, out, TOKENS, DM, DFF, DM, 0);
}

// round 14
// speedup vs baseline: 2.5761x; 1.0078x over previous
#include <cuda_runtime.h>
#include <cuda_bf16.h>
#include <cuda_fp16.h>
#include <math.h>
#include <stdint.h>

// ---------------------------------------------------------------------------
// Problem constants
// ---------------------------------------------------------------------------
#define NBATCH   4
#define HDIM     128
#define WDIM     128
#define DM       768
#define NHEADS   12
#define DHEAD    64
#define DFF      2048
#define DC       768
#define WS       8
#define SHIFT    4
#define TOKENS   (NBATCH * HDIM * WDIM)          // 65536
#define NWIN     (NBATCH * NHEADS * 16 * 16)     // 12288
#define EPSV     1e-6f

// ---------------------------------------------------------------------------
// Scratch
// ---------------------------------------------------------------------------
#define W_QKV_SZ (3 * DM * DM)
#define W_OUT_SZ (DM * DM)
#define W_UP_SZ  (2 * DFF * DM)
#define W_DN_SZ  (DM * DFF)
#define W_TOTAL  (W_QKV_SZ + W_OUT_SZ + W_UP_SZ + W_DN_SZ)

__device__ float g_scale1[NBATCH * DM];
__device__ float g_scale2[NBATCH * DM];
__device__ float g_x2  [(size_t)TOKENS * DM];

__device__ __half g_qkvh[(size_t)TOKENS * 2 * DM];    // q,k fp16 (ld=1536)
__device__ __half g_vwh [(size_t)NWIN * 64 * 64];     // v windowed fp16
__device__ __half g_h   [(size_t)TOKENS * DM];        // activations fp16
__device__ __half g_oi  [(size_t)TOKENS * DM];
__device__ __half g_a   [(size_t)TOKENS * DFF];
__device__ __half g_w   [W_TOTAL];                    // weights fp16

// ---------------------------------------------------------------------------
// PTX helpers (sm_80+ features only; legal under compute_103)
// ---------------------------------------------------------------------------
__device__ __forceinline__ uint32_t smem_to_u32(const void* p) {
    uint32_t a;
    asm("{ .reg .u64 t; cvta.to.shared.u64 t, %1; cvt.u32.u64 %0, t; }" : "=r"(a) : "l"(p));
    return a;
}
#define CP_ASYNC16(sa, gp) \
    asm volatile("cp.async.cg.shared.global [%0], [%1], 16;" :: "r"(sa), "l"(gp))
#define CP_COMMIT() asm volatile("cp.async.commit_group;" ::: "memory")
#define CP_WAIT2()  asm volatile("cp.async.wait_group 2;" ::: "memory")
#define CP_WAIT1()  asm volatile("cp.async.wait_group 1;" ::: "memory")
#define CP_WAIT0()  asm volatile("cp.async.wait_group 0;" ::: "memory")

__device__ __forceinline__ void ldsm_x4(uint32_t& r0, uint32_t& r1, uint32_t& r2,
                                        uint32_t& r3, uint32_t addr) {
    asm volatile("ldmatrix.sync.aligned.m8n8.x4.shared.b16 {%0,%1,%2,%3}, [%4];"
                 : "=r"(r0), "=r"(r1), "=r"(r2), "=r"(r3) : "r"(addr));
}
__device__ __forceinline__ void ldsm_x4_t(uint32_t& r0, uint32_t& r1, uint32_t& r2,
                                          uint32_t& r3, uint32_t addr) {
    asm volatile("ldmatrix.sync.aligned.m8n8.x4.trans.shared.b16 {%0,%1,%2,%3}, [%4];"
                 : "=r"(r0), "=r"(r1), "=r"(r2), "=r"(r3) : "r"(addr));
}
__device__ __forceinline__ void mma_f16(float c[4], const uint32_t a[4],
                                        const uint32_t b[2]) {
    asm volatile("mma.sync.aligned.m16n8k16.row.col.f32.f16.f16.f32 "
                 "{%0,%1,%2,%3},{%4,%5,%6,%7},{%8,%9},{%0,%1,%2,%3};"
                 : "+f"(c[0]), "+f"(c[1]), "+f"(c[2]), "+f"(c[3])
                 : "r"(a[0]), "r"(a[1]), "r"(a[2]), "r"(a[3]),
                   "r"(b[0]), "r"(b[1]));
}
__device__ __forceinline__ uint32_t pack_h2(float a, float b) {
    __half2 h = __floats2half2_rn(a, b);
    return *(uint32_t*)&h;
}

// window-scatter address helper (roll +4,+4 then 8x8 windows)
__device__ __forceinline__ size_t win_addr(int t, int h, int e) {
    int n = t >> 14;
    int y = (t >> 7) & 127;
    int x = t & 127;
    int Y = (y + SHIFT) & 127, X = (x + SHIFT) & 127;
    int wyx  = ((Y >> 3) << 4) + (X >> 3);
    int spos = ((Y & 7) << 3) + (X & 7);
    return ((size_t)((n * NHEADS + h) * 256 + wyx)) * 4096 + (size_t)spos * 64 + e;
}

// inverse: window b, slot r -> token index
__device__ __forceinline__ int win_token(int b, int r) {
    int n   = b / (NHEADS * 256);
    int rem = b % (NHEADS * 256);
    int w   = rem & 255;
    int Y = ((w >> 4) << 3) + (r >> 3);
    int X = ((w & 15) << 3) + (r & 7);
    int y = (Y - SHIFT) & 127, x = (X - SHIFT) & 127;
    return (n << 14) + (y << 7) + x;
}

// ---------------------------------------------------------------------------
// GEMM (R12 proven): 128x256x64 tile, 8 warps, 4-stage ring, 1 sync/stage.
// mode 0: C fp32 = (D?D:0) + A@B^T
// mode 1: fused gated-GELU -> g_a (fp16)
// mode 2: qkv: cols<1536 -> g_qkvh fp16; cols>=1536 -> windowed V fp16
// ---------------------------------------------------------------------------
#define BKC      64
#define PADK     72
#define TILE_A_E (128 * PADK)
#define TILE_B_E (256 * PADK)
#define STAGE_E  (TILE_A_E + TILE_B_E)
#define NSTG     4
#define GEMM_SMEM (NSTG * STAGE_E * 2)       // 221184 bytes

__global__ __launch_bounds__(256) void hgemm_kernel(
    const __half* __restrict__ A, const __half* __restrict__ B,
    const float* __restrict__ Dres, float* __restrict__ C,
    int M, int N, int K, int ldc, int mode)
{
    extern __shared__ __align__(128) char smem[];
    const uint32_t sbase = smem_to_u32(smem);
    const int tid = threadIdx.x, lane = tid & 31, wid = tid >> 5;
    const int wm = wid >> 2, wn = wid & 3;
    const size_t bm = (size_t)blockIdx.y * 128;
    const size_t bn = (size_t)blockIdx.x * 256;

    const __half* Ab = A + bm * (size_t)K;
    const __half* Bb = B + bn * (size_t)K;

    float acc[4][8][4];
    #pragma unroll
    for (int i = 0; i < 4; i++)
        #pragma unroll
        for (int j = 0; j < 8; j++)
            #pragma unroll
            for (int l = 0; l < 4; l++) acc[i][j][l] = 0.f;

    const int nstage = K / BKC;

    auto issue = [&](int st) {
        const int k0 = st * BKC;
        const uint32_t sb = sbase + (uint32_t)((st & (NSTG - 1)) * STAGE_E * 2);
        #pragma unroll
        for (int i = 0; i < 4; i++) {
            int idx = tid + i * 256;
            int row = idx >> 3, seg = (idx & 7) << 3;
            const __half* gp = Ab + (size_t)row * K + k0 + seg;
            uint32_t sa = sb + (uint32_t)((row * PADK + seg) * 2);
            CP_ASYNC16(sa, gp);
        }
        #pragma unroll
        for (int i = 0; i < 8; i++) {
            int idx = tid + i * 256;
            int row = idx >> 3, seg = (idx & 7) << 3;
            const __half* gp = Bb + (size_t)row * K + k0 + seg;
            uint32_t sa = sb + (uint32_t)((TILE_A_E + row * PADK + seg) * 2);
            CP_ASYNC16(sa, gp);
        }
        CP_COMMIT();
    };

    issue(0);
    if (nstage > 1) issue(1);
    if (nstage > 2) issue(2);

    const int a_r = lane & 15, a_h = (lane >> 4) << 3;
    const int b_r = (lane & 7) + ((lane & 16) >> 1);
    const int b_k = lane & 8;

    for (int st = 0; st < nstage; st++) {
        if (st < nstage - 2)       { CP_WAIT2(); }
        else if (st == nstage - 2) { CP_WAIT1(); }
        else                       { CP_WAIT0(); }
        __syncthreads();

        const uint32_t sb = sbase + (uint32_t)((st & (NSTG - 1)) * STAGE_E * 2);
        const uint32_t sA = sb;
        const uint32_t sB = sb + TILE_A_E * 2;

        #pragma unroll
        for (int kk = 0; kk < BKC; kk += 16) {
            uint32_t a[4][4], bh[8][2];
            #pragma unroll
            for (int mt = 0; mt < 4; mt++)
                ldsm_x4(a[mt][0], a[mt][1], a[mt][2], a[mt][3],
                        sA + (uint32_t)(((wm * 64 + mt * 16 + a_r) * PADK + kk + a_h) * 2));
            #pragma unroll
            for (int p = 0; p < 4; p++) {
                uint32_t r0, r1, r2, r3;
                ldsm_x4(r0, r1, r2, r3,
                        sB + (uint32_t)(((wn * 64 + p * 16 + b_r) * PADK + kk + b_k) * 2));
                bh[p * 2][0] = r0; bh[p * 2][1] = r1;
                bh[p * 2 + 1][0] = r2; bh[p * 2 + 1][1] = r3;
            }
            #pragma unroll
            for (int mt = 0; mt < 4; mt++)
                #pragma unroll
                for (int nt = 0; nt < 8; nt++)
                    mma_f16(acc[mt][nt], a[mt], bh[nt]);
        }
        if (st + 3 < nstage) issue(st + 3);
    }

    const int er = lane >> 2, ec = (lane & 3) * 2;

    if (mode == 1) {
        #pragma unroll
        for (int mt = 0; mt < 4; mt++) {
            size_t r0 = bm + wm * 64 + mt * 16 + er;
            size_t r1 = r0 + 8;
            #pragma unroll
            for (int nt = 0; nt < 8; nt++) {
                int col = (int)bn + wn * 64 + nt * 8 + ec;
                int j = col >> 1;
                float a0 = acc[mt][nt][0], gg0 = acc[mt][nt][1];
                float a1 = acc[mt][nt][2], gg1 = acc[mt][nt][3];
                float v0 = a0 * (gg0 * 0.5f * (1.0f + erff(gg0 * 0.70710678118654752f)));
                float v1 = a1 * (gg1 * 0.5f * (1.0f + erff(gg1 * 0.70710678118654752f)));
                g_a[r0 * DFF + j] = __float2half(v0);
                g_a[r1 * DFF + j] = __float2half(v1);
            }
        }
        return;
    }

    if (mode == 2) {
        #pragma unroll
        for (int mt = 0; mt < 4; mt++) {
            int t0 = (int)bm + wm * 64 + mt * 16 + er;
            int t1 = t0 + 8;
            #pragma unroll
            for (int nt = 0; nt < 8; nt++) {
                int col = (int)bn + wn * 64 + nt * 8 + ec;
                uint32_t w0 = pack_h2(acc[mt][nt][0], acc[mt][nt][1]);
                uint32_t w1 = pack_h2(acc[mt][nt][2], acc[mt][nt][3]);
                if (col < 1536) {
                    *(uint32_t*)&g_qkvh[(size_t)t0 * 1536 + col] = w0;
                    *(uint32_t*)&g_qkvh[(size_t)t1 * 1536 + col] = w1;
                } else {
                    int h = (col - 1536) >> 6;
                    int e = col & 63;
                    *(uint32_t*)&g_vwh[win_addr(t0, h, e)] = w0;
                    *(uint32_t*)&g_vwh[win_addr(t1, h, e)] = w1;
                }
            }
        }
        return;
    }

    #pragma unroll
    for (int mt = 0; mt < 4; mt++) {
        size_t row0 = bm + wm * 64 + mt * 16 + er;
        #pragma unroll
        for (int nt = 0; nt < 8; nt++) {
            size_t col = bn + wn * 64 + nt * 8 + ec;
            float* p0 = C + row0 * (size_t)ldc + col;
            float* p1 = C + (row0 + 8) * (size_t)ldc + col;
            float2 v0 = make_float2(acc[mt][nt][0], acc[mt][nt][1]);
            float2 v1 = make_float2(acc[mt][nt][2], acc[mt][nt][3]);
            if (Dres) {
                const float2 d0 = *(const float2*)(Dres + row0 * (size_t)ldc + col);
                const float2 d1 = *(const float2*)(Dres + (row0 + 8) * (size_t)ldc + col);
                v0.x += d0.x; v0.y += d0.y; v1.x += d1.x; v1.y += d1.y;
            }
            *(float2*)p0 = v0;
            *(float2*)p1 = v1;
        }
    }
}

// ---------------------------------------------------------------------------
// K0: ada scales
// ---------------------------------------------------------------------------
__global__ void ada_kernel(const float* __restrict__ cond,
                           const float* __restrict__ w1,
                           const float* __restrict__ w2)
{
    int gw   = (blockIdx.x * blockDim.x + threadIdx.x) >> 5;
    int lane = threadIdx.x & 31;
    if (gw >= 2 * NBATCH * DM) return;
    int which = gw / (NBATCH * DM);
    int rem   = gw % (NBATCH * DM);
    int n = rem / DM, d = rem % DM;
    const float* w  = which ? w2 : w1;
    const float* cr = cond + n * DC;
    const float* wr = w + (size_t)d * DC;
    float s = 0.f;
    for (int i = lane; i < DC; i += 32) s += cr[i] * wr[i];
    #pragma unroll
    for (int o = 16; o; o >>= 1) s += __shfl_xor_sync(0xffffffffu, s, o);
    if (lane == 0) (which ? g_scale2 : g_scale1)[rem] = s + 1.0f;
}

// ---------------------------------------------------------------------------
// K1: RMSNorm * ada -> fp16
// ---------------------------------------------------------------------------
__global__ __launch_bounds__(256) void rmsnorm_kernel(const float* __restrict__ x,
                                                      const float* __restrict__ scale)
{
    int t = blockIdx.x;
    int n = t >> 14;
    const float* xr = x + (size_t)t * DM;
    float v[3]; float ss = 0.f;
    #pragma unroll
    for (int i = 0; i < 3; i++) { v[i] = xr[threadIdx.x + 256 * i]; ss += v[i] * v[i]; }
    __shared__ float red[8];
    #pragma unroll
    for (int o = 16; o; o >>= 1) ss += __shfl_xor_sync(0xffffffffu, ss, o);
    if ((threadIdx.x & 31) == 0) red[threadIdx.x >> 5] = ss;
    __syncthreads();
    if (threadIdx.x == 0) {
        float r = 0.f;
        #pragma unroll
        for (int i = 0; i < 8; i++) r += red[i];
        red[0] = r;
    }
    __syncthreads();
    float inv = rsqrtf(red[0] * (1.0f / DM) + EPSV);
    const float* sc = scale + (size_t)n * DM;
    #pragma unroll
    for (int i = 0; i < 3; i++) {
        int c = threadIdx.x + 256 * i;
        g_h[(size_t)t * DM + c] = __float2half(v[i] * sc[c] * inv);
    }
}

// ---------------------------------------------------------------------------
// K2: weight convert fp32 -> fp16 (optional row interleave for ff_up)
// ---------------------------------------------------------------------------
__global__ __launch_bounds__(256) void wconv_kernel(const float* __restrict__ w,
                                                    __half* __restrict__ dsth,
                                                    int n, int rowlen, int perm)
{
    int i = blockIdx.x * 256 + threadIdx.x;
    if (i >= n) return;
    int dst = i;
    if (perm) {
        int r = i / rowlen, c = i % rowlen;
        int dr = (r < DFF) ? (2 * r) : (2 * (r - DFF) + 1);
        dst = dr * rowlen + c;
    }
    dsth[dst] = __float2half(w[i]);
}

// ---------------------------------------------------------------------------
// K3: fused tensor-core attention, all-fp16 data path.
// 128 threads = 4 warps; warp w owns query rows 16w..16w+15.
// fp16 gather -> fp32 norm+RoPE in place -> HMMA S=QK^T -> fragment softmax ->
// HMMA O=PV -> fragment-direct fp16 store to g_oi.
// ---------------------------------------------------------------------------
#define AHP  72                                // fp16 row pad (halfs)
#define AQH  0
#define AKH  (64 * AHP * 2)                    // 9216
#define AVH  (2 * 64 * AHP * 2)                // 18432
#define ATT_SMEM (3 * 64 * AHP * 2)            // 27648

__global__ __launch_bounds__(128) void attn_kernel(const float* __restrict__ pos,
                                                   const float* __restrict__ attn_scale,
                                                   const float* __restrict__ rope_freqs)
{
    extern __shared__ __align__(16) char smc[];
    const uint32_t sb = smem_to_u32(smc);
    const uint32_t qh_b = sb + AQH, kh_b = sb + AKH, vh_b = sb + AVH;
    __half* qs = (__half*)(smc + AQH);
    __half* ks = (__half*)(smc + AKH);

    const int b   = blockIdx.x;
    const int rem = b % (NHEADS * 256);
    const int h   = rem >> 8;
    const int w   = rem & 255;
    const bool left = ((w & 15) == 0), top = ((w >> 4) == 0);
    const int tid = threadIdx.x, warp = tid >> 5, lane = tid & 31;

    // fp16 gather: q,k via token map; v contiguous
    const __half* vb = g_vwh + (size_t)b * 4096;
    for (int i = tid; i < 1024; i += 128) {
        int r = i >> 4, c4 = (i & 15) << 2;
        int t = win_token(b, r);
        const __half* qk = g_qkvh + (size_t)t * 1536 + h * DHEAD + c4;
        uint2 qv = *(const uint2*)qk;
        uint2 kv = *(const uint2*)(qk + DM);
        uint2 vv = *(const uint2*)(vb + (i << 2));
        *(uint2*)(smc + AQH + (r * AHP + c4) * 2) = qv;
        *(uint2*)(smc + AKH + (r * AHP + c4) * 2) = kv;
        *(uint2*)(smc + AVH + (r * AHP + c4) * 2) = vv;
    }
    __syncthreads();

    // per-row norm + RoPE in fp32 registers, write back fp16 (threads 0..63)
    if (tid < 64) {
        __half* qrow = qs + tid * AHP;
        __half* krow = ks + tid * AHP;
        float qv[64], kv[64];
        float sq = 0.f, sk = 0.f;
        #pragma unroll
        for (int e = 0; e < 64; e++) {
            qv[e] = __half2float(qrow[e]);
            kv[e] = __half2float(krow[e]);
            sq += qv[e] * qv[e];
            sk += kv[e] * kv[e];
        }
        float ssh = sqrtf(attn_scale[h]);
        float rq = ssh * rsqrtf(sq + EPSV);
        float rk = ssh * rsqrtf(sk + EPSV);

        int t = win_token(b, tid);
        float p0 = pos[(size_t)t * 2 + 0];
        float p1 = pos[(size_t)t * 2 + 1];
        #pragma unroll
        for (int e = 0; e < 16; e++) {
            float freq = rope_freqs[h * 8 + (e & 7)];
            float th = (e < 8 ? p0 : p1) * freq;
            float c = cosf(th), s = sinf(th);
            float q1 = qv[e] * rq, q2 = qv[e + 16] * rq;
            float k1 = kv[e] * rk, k2 = kv[e + 16] * rk;
            qrow[e]      = __float2half(q1 * c - q2 * s);
            qrow[e + 16] = __float2half(q2 * c + q1 * s);
            krow[e]      = __float2half(k1 * c - k2 * s);
            krow[e + 16] = __float2half(k2 * c + k1 * s);
        }
        #pragma unroll
        for (int e = 32; e < 64; e++) {
            qrow[e] = __float2half(qv[e] * rq);
            krow[e] = __float2half(kv[e] * rk);
        }
    }
    __syncthreads();

    // ---- scores: S = Q K^T (m16 x n64 x k64 per warp) ----
    const int a_r = lane & 15, a_h2 = (lane >> 4) << 3;
    const int b_r = (lane & 7) + ((lane & 16) >> 1);
    const int b_k = lane & 8;

    float sc[8][4];
    #pragma unroll
    for (int nt = 0; nt < 8; nt++)
        #pragma unroll
        for (int j = 0; j < 4; j++) sc[nt][j] = 0.f;

    uint32_t afr[4][4];
    #pragma unroll
    for (int kt = 0; kt < 4; kt++)
        ldsm_x4(afr[kt][0], afr[kt][1], afr[kt][2], afr[kt][3],
                qh_b + (uint32_t)(((warp * 16 + a_r) * AHP + kt * 16 + a_h2) * 2));

    #pragma unroll
    for (int kt = 0; kt < 4; kt++) {
        uint32_t bh[8][2];
        #pragma unroll
        for (int p = 0; p < 4; p++) {
            uint32_t r0, r1, r2, r3;
            ldsm_x4(r0, r1, r2, r3,
                    kh_b + (uint32_t)(((p * 16 + b_r) * AHP + kt * 16 + b_k) * 2));
            bh[p * 2][0] = r0; bh[p * 2][1] = r1;
            bh[p * 2 + 1][0] = r2; bh[p * 2 + 1][1] = r3;
        }
        #pragma unroll
        for (int nt = 0; nt < 8; nt++)
            mma_f16(sc[nt], afr[kt], bh[nt]);
    }

    // ---- fragment mask + softmax ----
    const int er = lane >> 2, ec = (lane & 3) * 2;
    const int r0 = warp * 16 + er, r1 = r0 + 8;
    const bool qa0 = ((r0 >> 3) < SHIFT), ql0 = ((r0 & 7) < SHIFT);
    const bool qa1 = ((r1 >> 3) < SHIFT), ql1 = ((r1 & 7) < SHIFT);

    float mx0 = -3.402823466e38f, mx1 = -3.402823466e38f;
    #pragma unroll
    for (int nt = 0; nt < 8; nt++) {
        bool ka = nt < SHIFT;
        #pragma unroll
        for (int j = 0; j < 2; j++) {
            bool kl = (ec + j) < SHIFT;
            bool m0 = (!left && !top)
                    || (left && top && (ql0 == kl) && (qa0 == ka))
                    || (left && !top && (ql0 == kl))
                    || (!left && top && (qa0 == ka));
            bool m1 = (!left && !top)
                    || (left && top && (ql1 == kl) && (qa1 == ka))
                    || (left && !top && (ql1 == kl))
                    || (!left && top && (qa1 == ka));
            if (!m0) sc[nt][j]     = -3.402823466e38f;
            if (!m1) sc[nt][2 + j] = -3.402823466e38f;
            mx0 = fmaxf(mx0, sc[nt][j]);
            mx1 = fmaxf(mx1, sc[nt][2 + j]);
        }
    }
    mx0 = fmaxf(mx0, __shfl_xor_sync(0xffffffffu, mx0, 1));
    mx0 = fmaxf(mx0, __shfl_xor_sync(0xffffffffu, mx0, 2));
    mx1 = fmaxf(mx1, __shfl_xor_sync(0xffffffffu, mx1, 1));
    mx1 = fmaxf(mx1, __shfl_xor_sync(0xffffffffu, mx1, 2));

    float s0 = 0.f, s1 = 0.f;
    #pragma unroll
    for (int nt = 0; nt < 8; nt++) {
        #pragma unroll
        for (int j = 0; j < 2; j++) {
            float p0v = __expf(sc[nt][j] - mx0);
            float p1v = __expf(sc[nt][2 + j] - mx1);
            sc[nt][j] = p0v; sc[nt][2 + j] = p1v;
            s0 += p0v; s1 += p1v;
        }
    }
    s0 += __shfl_xor_sync(0xffffffffu, s0, 1);
    s0 += __shfl_xor_sync(0xffffffffu, s0, 2);
    s1 += __shfl_xor_sync(0xffffffffu, s1, 1);
    s1 += __shfl_xor_sync(0xffffffffu, s1, 2);
    float inv0 = 1.0f / s0, inv1 = 1.0f / s1;

    // ---- pack P to fp16 A-fragments ----
    uint32_t pf[4][4];
    #pragma unroll
    for (int kt = 0; kt < 4; kt++) {
        pf[kt][0] = pack_h2(sc[2 * kt][0],     sc[2 * kt][1]);
        pf[kt][1] = pack_h2(sc[2 * kt][2],     sc[2 * kt][3]);
        pf[kt][2] = pack_h2(sc[2 * kt + 1][0], sc[2 * kt + 1][1]);
        pf[kt][3] = pack_h2(sc[2 * kt + 1][2], sc[2 * kt + 1][3]);
    }

    // ---- O = P V (m16 x n64 x k64) ----
    float oo[8][4];
    #pragma unroll
    for (int nt = 0; nt < 8; nt++)
        #pragma unroll
        for (int j = 0; j < 4; j++) oo[nt][j] = 0.f;

    const int v_r = lane & 15, v_c = (lane >> 4) << 3;
    #pragma unroll
    for (int kt = 0; kt < 4; kt++) {
        uint32_t bv[8][2];
        #pragma unroll
        for (int p = 0; p < 4; p++) {
            uint32_t r0v, r1v, r2v, r3v;
            ldsm_x4_t(r0v, r1v, r2v, r3v,
                      vh_b + (uint32_t)(((kt * 16 + v_r) * AHP + p * 16 + v_c) * 2));
            bv[p * 2][0] = r0v; bv[p * 2][1] = r1v;
            bv[p * 2 + 1][0] = r2v; bv[p * 2 + 1][1] = r3v;
        }
        #pragma unroll
        for (int nt = 0; nt < 8; nt++)
            mma_f16(oo[nt], pf[kt], bv[nt]);
    }

    // ---- fragment-direct store ----
    int t0 = win_token(b, r0), t1 = win_token(b, r1);
    #pragma unroll
    for (int nt = 0; nt < 8; nt++) {
        int col = h * DHEAD + nt * 8 + ec;
        uint32_t w0 = pack_h2(oo[nt][0] * inv0, oo[nt][1] * inv0);
        uint32_t w1 = pack_h2(oo[nt][2] * inv1, oo[nt][3] * inv1);
        *(uint32_t*)&g_oi[(size_t)t0 * DM + col] = w0;
        *(uint32_t*)&g_oi[(size_t)t1 * DM + col] = w1;
    }
}

// ---------------------------------------------------------------------------
// host
// ---------------------------------------------------------------------------
static void launch_hgemm(const __half* A, const __half* B,
                         const float* D, float* C, int M, int N, int K,
                         int ldc, int mode)
{
    dim3 grid(N / 256, M / 128);
    hgemm_kernel<<<grid, 256, GEMM_SMEM>>>(A, B, D, C, M, N, K, ldc, mode);
}

extern "C" void kernel_launch(void* const* d_in, const int* in_sizes, int n_in,
                              void* d_out, int out_size)
{
    const float* x          = (const float*)d_in[0];
    const float* pos        = (const float*)d_in[1];
    const float* cond       = (const float*)d_in[2];
    const float* ada1_w     = (const float*)d_in[3];
    const float* qkv_w      = (const float*)d_in[4];
    const float* attn_scale = (const float*)d_in[5];
    const float* rope_freqs = (const float*)d_in[6];
    const float* out_w      = (const float*)d_in[7];
    const float* ada2_w     = (const float*)d_in[8];
    const float* ff_up_w    = (const float*)d_in[9];
    const float* ff_down_w  = (const float*)d_in[10];
    float* out = (float*)d_out;

    cudaFuncSetAttribute(hgemm_kernel, cudaFuncAttributeMaxDynamicSharedMemorySize, GEMM_SMEM);
    cudaFuncSetAttribute(attn_kernel, cudaFuncAttributeMaxDynamicSharedMemorySize, ATT_SMEM);

    float *p_scale1, *p_scale2, *p_x2;
    __half *p_h, *p_oi, *p_a, *p_w;
    cudaGetSymbolAddress((void**)&p_scale1, g_scale1);
    cudaGetSymbolAddress((void**)&p_scale2, g_scale2);
    cudaGetSymbolAddress((void**)&p_x2,     g_x2);
    cudaGetSymbolAddress((void**)&p_h,      g_h);
    cudaGetSymbolAddress((void**)&p_oi,     g_oi);
    cudaGetSymbolAddress((void**)&p_a,      g_a);
    cudaGetSymbolAddress((void**)&p_w,      g_w);

    const int OQKV = 0;
    const int OOUT = OQKV + W_QKV_SZ;
    const int OUP  = OOUT + W_OUT_SZ;
    const int ODN  = OUP + W_UP_SZ;

    wconv_kernel<<<(W_QKV_SZ + 255) / 256, 256>>>(qkv_w,     p_w + OQKV, W_QKV_SZ, DM, 0);
    wconv_kernel<<<(W_OUT_SZ + 255) / 256, 256>>>(out_w,     p_w + OOUT, W_OUT_SZ, DM, 0);
    wconv_kernel<<<(W_UP_SZ  + 255) / 256, 256>>>(ff_up_w,   p_w + OUP,  W_UP_SZ,  DM, 1);
    wconv_kernel<<<(W_DN_SZ  + 255) / 256, 256>>>(ff_down_w, p_w + ODN,  W_DN_SZ,  DFF, 0);

    ada_kernel<<<768, 256>>>(cond, ada1_w, ada2_w);
    rmsnorm_kernel<<<TOKENS, 256>>>(x, p_scale1);
    // qkv: q,k -> g_qkvh fp16; v -> windowed fp16 g_vwh
    launch_hgemm(p_h, p_w + OQKV, nullptr, nullptr, TOKENS, 3 * DM, DM, 0, 2);
    // fused qk-transform + tensor-core attention + unwindow
    attn_kernel<<<NWIN, 128, ATT_SMEM>>>(pos, attn_scale, rope_freqs);
    launch_hgemm(p_oi, p_w + OOUT, x, p_x2, TOKENS, DM, DM, DM, 0);
    rmsnorm_kernel<<<TOKENS, 256>>>(p_x2, p_scale2);
    // ff_up with fused gated GELU (interleaved weights) -> g_a
    launch_hgemm(p_h, p_w + OUP, nullptr, nullptr, TOKENS, 2 * DFF, DM, 2 * DFF, 1);
    launch_hgemm(p_a, p_w + ODN, p_x2, out, TOKENS, DM, DFF, DM, 0);
}

// round 15
// speedup vs baseline: 2.6619x; 1.0333x over previous
#include <cuda_runtime.h>
#include <cuda_bf16.h>
#include <cuda_fp16.h>
#include <math.h>
#include <stdint.h>

// ---------------------------------------------------------------------------
// Problem constants
// ---------------------------------------------------------------------------
#define NBATCH   4
#define HDIM     128
#define WDIM     128
#define DM       768
#define NHEADS   12
#define DHEAD    64
#define DFF      2048
#define DC       768
#define WS       8
#define SHIFT    4
#define TOKENS   (NBATCH * HDIM * WDIM)          // 65536
#define NWIN     (NBATCH * NHEADS * 16 * 16)     // 12288
#define EPSV     1e-6f

// ---------------------------------------------------------------------------
// Scratch
// ---------------------------------------------------------------------------
#define W_QKV_SZ (3 * DM * DM)
#define W_OUT_SZ (DM * DM)
#define W_UP_SZ  (2 * DFF * DM)
#define W_DN_SZ  (DM * DFF)
#define W_TOTAL  (W_QKV_SZ + W_OUT_SZ + W_UP_SZ + W_DN_SZ)

__device__ float g_scale1[NBATCH * DM];
__device__ float g_scale2[NBATCH * DM];
__device__ float g_x2  [(size_t)TOKENS * DM];

__device__ __half g_qkvh[(size_t)TOKENS * 2 * DM];    // q,k fp16 (ld=1536)
__device__ __half g_vwh [(size_t)NWIN * 64 * 64];     // v windowed fp16
__device__ __half g_h   [(size_t)TOKENS * DM];        // activations fp16
__device__ __half g_oi  [(size_t)TOKENS * DM];
__device__ __half g_a   [(size_t)TOKENS * DFF];
__device__ __half g_w   [W_TOTAL];                    // weights fp16

// ---------------------------------------------------------------------------
// PTX helpers (sm_80+ features only; legal under compute_103)
// ---------------------------------------------------------------------------
__device__ __forceinline__ uint32_t smem_to_u32(const void* p) {
    uint32_t a;
    asm("{ .reg .u64 t; cvta.to.shared.u64 t, %1; cvt.u32.u64 %0, t; }" : "=r"(a) : "l"(p));
    return a;
}
#define CP_ASYNC16(sa, gp) \
    asm volatile("cp.async.cg.shared.global [%0], [%1], 16;" :: "r"(sa), "l"(gp))
#define CP_COMMIT() asm volatile("cp.async.commit_group;" ::: "memory")
#define CP_WAIT2()  asm volatile("cp.async.wait_group 2;" ::: "memory")
#define CP_WAIT1()  asm volatile("cp.async.wait_group 1;" ::: "memory")
#define CP_WAIT0()  asm volatile("cp.async.wait_group 0;" ::: "memory")

__device__ __forceinline__ void ldsm_x4(uint32_t& r0, uint32_t& r1, uint32_t& r2,
                                        uint32_t& r3, uint32_t addr) {
    asm volatile("ldmatrix.sync.aligned.m8n8.x4.shared.b16 {%0,%1,%2,%3}, [%4];"
                 : "=r"(r0), "=r"(r1), "=r"(r2), "=r"(r3) : "r"(addr));
}
__device__ __forceinline__ void ldsm_x4_t(uint32_t& r0, uint32_t& r1, uint32_t& r2,
                                          uint32_t& r3, uint32_t addr) {
    asm volatile("ldmatrix.sync.aligned.m8n8.x4.trans.shared.b16 {%0,%1,%2,%3}, [%4];"
                 : "=r"(r0), "=r"(r1), "=r"(r2), "=r"(r3) : "r"(addr));
}
__device__ __forceinline__ void mma_f16(float c[4], const uint32_t a[4],
                                        const uint32_t b[2]) {
    asm volatile("mma.sync.aligned.m16n8k16.row.col.f32.f16.f16.f32 "
                 "{%0,%1,%2,%3},{%4,%5,%6,%7},{%8,%9},{%0,%1,%2,%3};"
                 : "+f"(c[0]), "+f"(c[1]), "+f"(c[2]), "+f"(c[3])
                 : "r"(a[0]), "r"(a[1]), "r"(a[2]), "r"(a[3]),
                   "r"(b[0]), "r"(b[1]));
}
__device__ __forceinline__ uint32_t pack_h2(float a, float b) {
    __half2 h = __floats2half2_rn(a, b);
    return *(uint32_t*)&h;
}

// window-scatter address helper (roll +4,+4 then 8x8 windows)
__device__ __forceinline__ size_t win_addr(int t, int h, int e) {
    int n = t >> 14;
    int y = (t >> 7) & 127;
    int x = t & 127;
    int Y = (y + SHIFT) & 127, X = (x + SHIFT) & 127;
    int wyx  = ((Y >> 3) << 4) + (X >> 3);
    int spos = ((Y & 7) << 3) + (X & 7);
    return ((size_t)((n * NHEADS + h) * 256 + wyx)) * 4096 + (size_t)spos * 64 + e;
}

// inverse: window b, slot r -> token index
__device__ __forceinline__ int win_token(int b, int r) {
    int n   = b / (NHEADS * 256);
    int rem = b % (NHEADS * 256);
    int w   = rem & 255;
    int Y = ((w >> 4) << 3) + (r >> 3);
    int X = ((w & 15) << 3) + (r & 7);
    int y = (Y - SHIFT) & 127, x = (X - SHIFT) & 127;
    return (n << 14) + (y << 7) + x;
}

// ---------------------------------------------------------------------------
// GEMM (R12 proven): 128x256x64 tile, 8 warps, 4-stage ring, 1 sync/stage.
// mode 0: C fp32 = (D?D:0) + A@B^T
// mode 1: fused gated-GELU -> g_a (fp16)
// mode 2: qkv: cols<1536 -> g_qkvh fp16; cols>=1536 -> windowed V fp16
// ---------------------------------------------------------------------------
#define BKC      64
#define PADK     72
#define TILE_A_E (128 * PADK)
#define TILE_B_E (256 * PADK)
#define STAGE_E  (TILE_A_E + TILE_B_E)
#define NSTG     4
#define GEMM_SMEM (NSTG * STAGE_E * 2)       // 221184 bytes

__global__ __launch_bounds__(256) void hgemm_kernel(
    const __half* __restrict__ A, const __half* __restrict__ B,
    const float* __restrict__ Dres, float* __restrict__ C,
    int M, int N, int K, int ldc, int mode)
{
    extern __shared__ __align__(128) char smem[];
    const uint32_t sbase = smem_to_u32(smem);
    const int tid = threadIdx.x, lane = tid & 31, wid = tid >> 5;
    const int wm = wid >> 2, wn = wid & 3;
    const size_t bm = (size_t)blockIdx.y * 128;
    const size_t bn = (size_t)blockIdx.x * 256;

    const __half* Ab = A + bm * (size_t)K;
    const __half* Bb = B + bn * (size_t)K;

    float acc[4][8][4];
    #pragma unroll
    for (int i = 0; i < 4; i++)
        #pragma unroll
        for (int j = 0; j < 8; j++)
            #pragma unroll
            for (int l = 0; l < 4; l++) acc[i][j][l] = 0.f;

    const int nstage = K / BKC;

    auto issue = [&](int st) {
        const int k0 = st * BKC;
        const uint32_t sb = sbase + (uint32_t)((st & (NSTG - 1)) * STAGE_E * 2);
        #pragma unroll
        for (int i = 0; i < 4; i++) {
            int idx = tid + i * 256;
            int row = idx >> 3, seg = (idx & 7) << 3;
            const __half* gp = Ab + (size_t)row * K + k0 + seg;
            uint32_t sa = sb + (uint32_t)((row * PADK + seg) * 2);
            CP_ASYNC16(sa, gp);
        }
        #pragma unroll
        for (int i = 0; i < 8; i++) {
            int idx = tid + i * 256;
            int row = idx >> 3, seg = (idx & 7) << 3;
            const __half* gp = Bb + (size_t)row * K + k0 + seg;
            uint32_t sa = sb + (uint32_t)((TILE_A_E + row * PADK + seg) * 2);
            CP_ASYNC16(sa, gp);
        }
        CP_COMMIT();
    };

    issue(0);
    if (nstage > 1) issue(1);
    if (nstage > 2) issue(2);

    const int a_r = lane & 15, a_h = (lane >> 4) << 3;
    const int b_r = (lane & 7) + ((lane & 16) >> 1);
    const int b_k = lane & 8;

    for (int st = 0; st < nstage; st++) {
        if (st < nstage - 2)       { CP_WAIT2(); }
        else if (st == nstage - 2) { CP_WAIT1(); }
        else                       { CP_WAIT0(); }
        __syncthreads();

        const uint32_t sb = sbase + (uint32_t)((st & (NSTG - 1)) * STAGE_E * 2);
        const uint32_t sA = sb;
        const uint32_t sB = sb + TILE_A_E * 2;

        #pragma unroll
        for (int kk = 0; kk < BKC; kk += 16) {
            uint32_t a[4][4], bh[8][2];
            #pragma unroll
            for (int mt = 0; mt < 4; mt++)
                ldsm_x4(a[mt][0], a[mt][1], a[mt][2], a[mt][3],
                        sA + (uint32_t)(((wm * 64 + mt * 16 + a_r) * PADK + kk + a_h) * 2));
            #pragma unroll
            for (int p = 0; p < 4; p++) {
                uint32_t r0, r1, r2, r3;
                ldsm_x4(r0, r1, r2, r3,
                        sB + (uint32_t)(((wn * 64 + p * 16 + b_r) * PADK + kk + b_k) * 2));
                bh[p * 2][0] = r0; bh[p * 2][1] = r1;
                bh[p * 2 + 1][0] = r2; bh[p * 2 + 1][1] = r3;
            }
            #pragma unroll
            for (int mt = 0; mt < 4; mt++)
                #pragma unroll
                for (int nt = 0; nt < 8; nt++)
                    mma_f16(acc[mt][nt], a[mt], bh[nt]);
        }
        if (st + 3 < nstage) issue(st + 3);
    }

    const int er = lane >> 2, ec = (lane & 3) * 2;

    if (mode == 1) {
        #pragma unroll
        for (int mt = 0; mt < 4; mt++) {
            size_t r0 = bm + wm * 64 + mt * 16 + er;
            size_t r1 = r0 + 8;
            #pragma unroll
            for (int nt = 0; nt < 8; nt++) {
                int col = (int)bn + wn * 64 + nt * 8 + ec;
                int j = col >> 1;
                float a0 = acc[mt][nt][0], gg0 = acc[mt][nt][1];
                float a1 = acc[mt][nt][2], gg1 = acc[mt][nt][3];
                float v0 = a0 * (gg0 * 0.5f * (1.0f + erff(gg0 * 0.70710678118654752f)));
                float v1 = a1 * (gg1 * 0.5f * (1.0f + erff(gg1 * 0.70710678118654752f)));
                g_a[r0 * DFF + j] = __float2half(v0);
                g_a[r1 * DFF + j] = __float2half(v1);
            }
        }
        return;
    }

    if (mode == 2) {
        #pragma unroll
        for (int mt = 0; mt < 4; mt++) {
            int t0 = (int)bm + wm * 64 + mt * 16 + er;
            int t1 = t0 + 8;
            #pragma unroll
            for (int nt = 0; nt < 8; nt++) {
                int col = (int)bn + wn * 64 + nt * 8 + ec;
                uint32_t w0 = pack_h2(acc[mt][nt][0], acc[mt][nt][1]);
                uint32_t w1 = pack_h2(acc[mt][nt][2], acc[mt][nt][3]);
                if (col < 1536) {
                    *(uint32_t*)&g_qkvh[(size_t)t0 * 1536 + col] = w0;
                    *(uint32_t*)&g_qkvh[(size_t)t1 * 1536 + col] = w1;
                } else {
                    int h = (col - 1536) >> 6;
                    int e = col & 63;
                    *(uint32_t*)&g_vwh[win_addr(t0, h, e)] = w0;
                    *(uint32_t*)&g_vwh[win_addr(t1, h, e)] = w1;
                }
            }
        }
        return;
    }

    #pragma unroll
    for (int mt = 0; mt < 4; mt++) {
        size_t row0 = bm + wm * 64 + mt * 16 + er;
        #pragma unroll
        for (int nt = 0; nt < 8; nt++) {
            size_t col = bn + wn * 64 + nt * 8 + ec;
            float* p0 = C + row0 * (size_t)ldc + col;
            float* p1 = C + (row0 + 8) * (size_t)ldc + col;
            float2 v0 = make_float2(acc[mt][nt][0], acc[mt][nt][1]);
            float2 v1 = make_float2(acc[mt][nt][2], acc[mt][nt][3]);
            if (Dres) {
                const float2 d0 = *(const float2*)(Dres + row0 * (size_t)ldc + col);
                const float2 d1 = *(const float2*)(Dres + (row0 + 8) * (size_t)ldc + col);
                v0.x += d0.x; v0.y += d0.y; v1.x += d1.x; v1.y += d1.y;
            }
            *(float2*)p0 = v0;
            *(float2*)p1 = v1;
        }
    }
}

// ---------------------------------------------------------------------------
// K0: ada scales
// ---------------------------------------------------------------------------
__global__ void ada_kernel(const float* __restrict__ cond,
                           const float* __restrict__ w1,
                           const float* __restrict__ w2)
{
    int gw   = (blockIdx.x * blockDim.x + threadIdx.x) >> 5;
    int lane = threadIdx.x & 31;
    if (gw >= 2 * NBATCH * DM) return;
    int which = gw / (NBATCH * DM);
    int rem   = gw % (NBATCH * DM);
    int n = rem / DM, d = rem % DM;
    const float* w  = which ? w2 : w1;
    const float* cr = cond + n * DC;
    const float* wr = w + (size_t)d * DC;
    float s = 0.f;
    for (int i = lane; i < DC; i += 32) s += cr[i] * wr[i];
    #pragma unroll
    for (int o = 16; o; o >>= 1) s += __shfl_xor_sync(0xffffffffu, s, o);
    if (lane == 0) (which ? g_scale2 : g_scale1)[rem] = s + 1.0f;
}

// ---------------------------------------------------------------------------
// K1: RMSNorm * ada -> fp16
// ---------------------------------------------------------------------------
__global__ __launch_bounds__(256) void rmsnorm_kernel(const float* __restrict__ x,
                                                      const float* __restrict__ scale)
{
    int t = blockIdx.x;
    int n = t >> 14;
    const float* xr = x + (size_t)t * DM;
    float v[3]; float ss = 0.f;
    #pragma unroll
    for (int i = 0; i < 3; i++) { v[i] = xr[threadIdx.x + 256 * i]; ss += v[i] * v[i]; }
    __shared__ float red[8];
    #pragma unroll
    for (int o = 16; o; o >>= 1) ss += __shfl_xor_sync(0xffffffffu, ss, o);
    if ((threadIdx.x & 31) == 0) red[threadIdx.x >> 5] = ss;
    __syncthreads();
    if (threadIdx.x == 0) {
        float r = 0.f;
        #pragma unroll
        for (int i = 0; i < 8; i++) r += red[i];
        red[0] = r;
    }
    __syncthreads();
    float inv = rsqrtf(red[0] * (1.0f / DM) + EPSV);
    const float* sc = scale + (size_t)n * DM;
    #pragma unroll
    for (int i = 0; i < 3; i++) {
        int c = threadIdx.x + 256 * i;
        g_h[(size_t)t * DM + c] = __float2half(v[i] * sc[c] * inv);
    }
}

// ---------------------------------------------------------------------------
// K2: weight convert fp32 -> fp16 (optional row interleave for ff_up)
// ---------------------------------------------------------------------------
__global__ __launch_bounds__(256) void wconv_kernel(const float* __restrict__ w,
                                                    __half* __restrict__ dsth,
                                                    int n, int rowlen, int perm)
{
    int i = blockIdx.x * 256 + threadIdx.x;
    if (i >= n) return;
    int dst = i;
    if (perm) {
        int r = i / rowlen, c = i % rowlen;
        int dr = (r < DFF) ? (2 * r) : (2 * (r - DFF) + 1);
        dst = dr * rowlen + c;
    }
    dsth[dst] = __float2half(w[i]);
}

// ---------------------------------------------------------------------------
// K3: fused tensor-core attention, all-fp16 data path.
// 128 threads = 4 warps; warp w owns query rows 16w..16w+15.
// fp16 gather -> spill-free norm+RoPE (128 threads: q rows | k rows) ->
// HMMA S=QK^T -> fragment softmax -> HMMA O=PV -> fragment-direct store.
// ---------------------------------------------------------------------------
#define AHP  72                                // fp16 row pad (halfs)
#define AQH  0
#define AKH  (64 * AHP * 2)                    // 9216
#define AVH  (2 * 64 * AHP * 2)                // 18432
#define ATT_SMEM (3 * 64 * AHP * 2)            // 27648

__global__ __launch_bounds__(128) void attn_kernel(const float* __restrict__ pos,
                                                   const float* __restrict__ attn_scale,
                                                   const float* __restrict__ rope_freqs)
{
    extern __shared__ __align__(16) char smc[];
    const uint32_t sb = smem_to_u32(smc);
    const uint32_t qh_b = sb + AQH, kh_b = sb + AKH, vh_b = sb + AVH;
    __half* qs = (__half*)(smc + AQH);
    __half* ks = (__half*)(smc + AKH);

    const int b   = blockIdx.x;
    const int rem = b % (NHEADS * 256);
    const int h   = rem >> 8;
    const int w   = rem & 255;
    const bool left = ((w & 15) == 0), top = ((w >> 4) == 0);
    const int tid = threadIdx.x, warp = tid >> 5, lane = tid & 31;

    // fp16 gather: q,k via token map; v contiguous
    const __half* vb = g_vwh + (size_t)b * 4096;
    for (int i = tid; i < 1024; i += 128) {
        int r = i >> 4, c4 = (i & 15) << 2;
        int t = win_token(b, r);
        const __half* qk = g_qkvh + (size_t)t * 1536 + h * DHEAD + c4;
        uint2 qv = *(const uint2*)qk;
        uint2 kv = *(const uint2*)(qk + DM);
        uint2 vv = *(const uint2*)(vb + (i << 2));
        *(uint2*)(smc + AQH + (r * AHP + c4) * 2) = qv;
        *(uint2*)(smc + AKH + (r * AHP + c4) * 2) = kv;
        *(uint2*)(smc + AVH + (r * AHP + c4) * 2) = vv;
    }
    __syncthreads();

    // norm + RoPE, spill-free: threads 0..63 -> q rows, 64..127 -> k rows
    {
        int row = tid & 63;
        __half* prow = (tid < 64 ? qs : ks) + row * AHP;
        __half2* prow2 = (__half2*)prow;

        float ss = 0.f;
        #pragma unroll
        for (int e2 = 0; e2 < 32; e2++) {
            float2 f = __half22float2(prow2[e2]);
            ss += f.x * f.x + f.y * f.y;
        }
        float r = sqrtf(attn_scale[h]) * rsqrtf(ss + EPSV);

        int t = win_token(b, row);
        float p0 = pos[(size_t)t * 2 + 0];
        float p1 = pos[(size_t)t * 2 + 1];
        #pragma unroll
        for (int e = 0; e < 16; e++) {
            float freq = rope_freqs[h * 8 + (e & 7)];
            float th = (e < 8 ? p0 : p1) * freq;
            float c = cosf(th), s = sinf(th);
            float v1 = __half2float(prow[e]) * r;
            float v2 = __half2float(prow[e + 16]) * r;
            prow[e]      = __float2half(v1 * c - v2 * s);
            prow[e + 16] = __float2half(v2 * c + v1 * s);
        }
        #pragma unroll
        for (int e2 = 16; e2 < 32; e2++) {
            float2 f = __half22float2(prow2[e2]);
            prow2[e2] = __floats2half2_rn(f.x * r, f.y * r);
        }
    }
    __syncthreads();

    // ---- scores: S = Q K^T (m16 x n64 x k64 per warp) ----
    const int a_r = lane & 15, a_h2 = (lane >> 4) << 3;
    const int b_r = (lane & 7) + ((lane & 16) >> 1);
    const int b_k = lane & 8;

    float sc[8][4];
    #pragma unroll
    for (int nt = 0; nt < 8; nt++)
        #pragma unroll
        for (int j = 0; j < 4; j++) sc[nt][j] = 0.f;

    uint32_t afr[4][4];
    #pragma unroll
    for (int kt = 0; kt < 4; kt++)
        ldsm_x4(afr[kt][0], afr[kt][1], afr[kt][2], afr[kt][3],
                qh_b + (uint32_t)(((warp * 16 + a_r) * AHP + kt * 16 + a_h2) * 2));

    #pragma unroll
    for (int kt = 0; kt < 4; kt++) {
        uint32_t bh[8][2];
        #pragma unroll
        for (int p = 0; p < 4; p++) {
            uint32_t r0, r1, r2, r3;
            ldsm_x4(r0, r1, r2, r3,
                    kh_b + (uint32_t)(((p * 16 + b_r) * AHP + kt * 16 + b_k) * 2));
            bh[p * 2][0] = r0; bh[p * 2][1] = r1;
            bh[p * 2 + 1][0] = r2; bh[p * 2 + 1][1] = r3;
        }
        #pragma unroll
        for (int nt = 0; nt < 8; nt++)
            mma_f16(sc[nt], afr[kt], bh[nt]);
    }

    // ---- fragment mask + softmax ----
    const int er = lane >> 2, ec = (lane & 3) * 2;
    const int r0 = warp * 16 + er, r1 = r0 + 8;
    const bool qa0 = ((r0 >> 3) < SHIFT), ql0 = ((r0 & 7) < SHIFT);
    const bool qa1 = ((r1 >> 3) < SHIFT), ql1 = ((r1 & 7) < SHIFT);

    float mx0 = -3.402823466e38f, mx1 = -3.402823466e38f;
    #pragma unroll
    for (int nt = 0; nt < 8; nt++) {
        bool ka = nt < SHIFT;
        #pragma unroll
        for (int j = 0; j < 2; j++) {
            bool kl = (ec + j) < SHIFT;
            bool m0 = (!left && !top)
                    || (left && top && (ql0 == kl) && (qa0 == ka))
                    || (left && !top && (ql0 == kl))
                    || (!left && top && (qa0 == ka));
            bool m1 = (!left && !top)
                    || (left && top && (ql1 == kl) && (qa1 == ka))
                    || (left && !top && (ql1 == kl))
                    || (!left && top && (qa1 == ka));
            if (!m0) sc[nt][j]     = -3.402823466e38f;
            if (!m1) sc[nt][2 + j] = -3.402823466e38f;
            mx0 = fmaxf(mx0, sc[nt][j]);
            mx1 = fmaxf(mx1, sc[nt][2 + j]);
        }
    }
    mx0 = fmaxf(mx0, __shfl_xor_sync(0xffffffffu, mx0, 1));
    mx0 = fmaxf(mx0, __shfl_xor_sync(0xffffffffu, mx0, 2));
    mx1 = fmaxf(mx1, __shfl_xor_sync(0xffffffffu, mx1, 1));
    mx1 = fmaxf(mx1, __shfl_xor_sync(0xffffffffu, mx1, 2));

    float s0 = 0.f, s1 = 0.f;
    #pragma unroll
    for (int nt = 0; nt < 8; nt++) {
        #pragma unroll
        for (int j = 0; j < 2; j++) {
            float p0v = __expf(sc[nt][j] - mx0);
            float p1v = __expf(sc[nt][2 + j] - mx1);
            sc[nt][j] = p0v; sc[nt][2 + j] = p1v;
            s0 += p0v; s1 += p1v;
        }
    }
    s0 += __shfl_xor_sync(0xffffffffu, s0, 1);
    s0 += __shfl_xor_sync(0xffffffffu, s0, 2);
    s1 += __shfl_xor_sync(0xffffffffu, s1, 1);
    s1 += __shfl_xor_sync(0xffffffffu, s1, 2);
    float inv0 = 1.0f / s0, inv1 = 1.0f / s1;

    // ---- pack P to fp16 A-fragments ----
    uint32_t pf[4][4];
    #pragma unroll
    for (int kt = 0; kt < 4; kt++) {
        pf[kt][0] = pack_h2(sc[2 * kt][0],     sc[2 * kt][1]);
        pf[kt][1] = pack_h2(sc[2 * kt][2],     sc[2 * kt][3]);
        pf[kt][2] = pack_h2(sc[2 * kt + 1][0], sc[2 * kt + 1][1]);
        pf[kt][3] = pack_h2(sc[2 * kt + 1][2], sc[2 * kt + 1][3]);
    }

    // ---- O = P V (m16 x n64 x k64) ----
    float oo[8][4];
    #pragma unroll
    for (int nt = 0; nt < 8; nt++)
        #pragma unroll
        for (int j = 0; j < 4; j++) oo[nt][j] = 0.f;

    const int v_r = lane & 15, v_c = (lane >> 4) << 3;
    #pragma unroll
    for (int kt = 0; kt < 4; kt++) {
        uint32_t bv[8][2];
        #pragma unroll
        for (int p = 0; p < 4; p++) {
            uint32_t r0v, r1v, r2v, r3v;
            ldsm_x4_t(r0v, r1v, r2v, r3v,
                      vh_b + (uint32_t)(((kt * 16 + v_r) * AHP + p * 16 + v_c) * 2));
            bv[p * 2][0] = r0v; bv[p * 2][1] = r1v;
            bv[p * 2 + 1][0] = r2v; bv[p * 2 + 1][1] = r3v;
        }
        #pragma unroll
        for (int nt = 0; nt < 8; nt++)
            mma_f16(oo[nt], pf[kt], bv[nt]);
    }

    // ---- fragment-direct store ----
    int t0 = win_token(b, r0), t1 = win_token(b, r1);
    #pragma unroll
    for (int nt = 0; nt < 8; nt++) {
        int col = h * DHEAD + nt * 8 + ec;
        uint32_t w0 = pack_h2(oo[nt][0] * inv0, oo[nt][1] * inv0);
        uint32_t w1 = pack_h2(oo[nt][2] * inv1, oo[nt][3] * inv1);
        *(uint32_t*)&g_oi[(size_t)t0 * DM + col] = w0;
        *(uint32_t*)&g_oi[(size_t)t1 * DM + col] = w1;
    }
}

// ---------------------------------------------------------------------------
// host
// ---------------------------------------------------------------------------
static void launch_hgemm(const __half* A, const __half* B,
                         const float* D, float* C, int M, int N, int K,
                         int ldc, int mode)
{
    dim3 grid(N / 256, M / 128);
    hgemm_kernel<<<grid, 256, GEMM_SMEM>>>(A, B, D, C, M, N, K, ldc, mode);
}

extern "C" void kernel_launch(void* const* d_in, const int* in_sizes, int n_in,
                              void* d_out, int out_size)
{
    const float* x          = (const float*)d_in[0];
    const float* pos        = (const float*)d_in[1];
    const float* cond       = (const float*)d_in[2];
    const float* ada1_w     = (const float*)d_in[3];
    const float* qkv_w      = (const float*)d_in[4];
    const float* attn_scale = (const float*)d_in[5];
    const float* rope_freqs = (const float*)d_in[6];
    const float* out_w      = (const float*)d_in[7];
    const float* ada2_w     = (const float*)d_in[8];
    const float* ff_up_w    = (const float*)d_in[9];
    const float* ff_down_w  = (const float*)d_in[10];
    float* out = (float*)d_out;

    cudaFuncSetAttribute(hgemm_kernel, cudaFuncAttributeMaxDynamicSharedMemorySize, GEMM_SMEM);
    cudaFuncSetAttribute(attn_kernel, cudaFuncAttributeMaxDynamicSharedMemorySize, ATT_SMEM);

    float *p_scale1, *p_scale2, *p_x2;
    __half *p_h, *p_oi, *p_a, *p_w;
    cudaGetSymbolAddress((void**)&p_scale1, g_scale1);
    cudaGetSymbolAddress((void**)&p_scale2, g_scale2);
    cudaGetSymbolAddress((void**)&p_x2,     g_x2);
    cudaGetSymbolAddress((void**)&p_h,      g_h);
    cudaGetSymbolAddress((void**)&p_oi,     g_oi);
    cudaGetSymbolAddress((void**)&p_a,      g_a);
    cudaGetSymbolAddress((void**)&p_w,      g_w);

    const int OQKV = 0;
    const int OOUT = OQKV + W_QKV_SZ;
    const int OUP  = OOUT + W_OUT_SZ;
    const int ODN  = OUP + W_UP_SZ;

    wconv_kernel<<<(W_QKV_SZ + 255) / 256, 256>>>(qkv_w,     p_w + OQKV, W_QKV_SZ, DM, 0);
    wconv_kernel<<<(W_OUT_SZ + 255) / 256, 256>>>(out_w,     p_w + OOUT, W_OUT_SZ, DM, 0);
    wconv_kernel<<<(W_UP_SZ  + 255) / 256, 256>>>(ff_up_w,   p_w + OUP,  W_UP_SZ,  DM, 1);
    wconv_kernel<<<(W_DN_SZ  + 255) / 256, 256>>>(ff_down_w, p_w + ODN,  W_DN_SZ,  DFF, 0);

    ada_kernel<<<768, 256>>>(cond, ada1_w, ada2_w);
    rmsnorm_kernel<<<TOKENS, 256>>>(x, p_scale1);
    // qkv: q,k -> g_qkvh fp16; v -> windowed fp16 g_vwh
    launch_hgemm(p_h, p_w + OQKV, nullptr, nullptr, TOKENS, 3 * DM, DM, 0, 2);
    // fused qk-transform + tensor-core attention + unwindow
    attn_kernel<<<NWIN, 128, ATT_SMEM>>>(pos, attn_scale, rope_freqs);
    launch_hgemm(p_oi, p_w + OOUT, x, p_x2, TOKENS, DM, DM, DM, 0);
    rmsnorm_kernel<<<TOKENS, 256>>>(p_x2, p_scale2);
    // ff_up with fused gated GELU (interleaved weights) -> g_a
    launch_hgemm(p_h, p_w + OUP, nullptr, nullptr, TOKENS, 2 * DFF, DM, 2 * DFF, 1);
    launch_hgemm(p_a, p_w + ODN, p_x2, out, TOKENS, DM, DFF, DM, 0);
}

// round 16
// speedup vs baseline: 2.7043x; 1.0159x over previous
#include <cuda_runtime.h>
#include <cuda_bf16.h>
#include <cuda_fp16.h>
#include <math.h>
#include <stdint.h>

// ---------------------------------------------------------------------------
// Problem constants
// ---------------------------------------------------------------------------
#define NBATCH   4
#define HDIM     128
#define WDIM     128
#define DM       768
#define NHEADS   12
#define DHEAD    64
#define DFF      2048
#define DC       768
#define WS       8
#define SHIFT    4
#define TOKENS   (NBATCH * HDIM * WDIM)          // 65536
#define NWIN     (NBATCH * NHEADS * 16 * 16)     // 12288
#define EPSV     1e-6f

// ---------------------------------------------------------------------------
// Scratch
// ---------------------------------------------------------------------------
#define W_QKV_SZ (3 * DM * DM)
#define W_OUT_SZ (DM * DM)
#define W_UP_SZ  (2 * DFF * DM)
#define W_DN_SZ  (DM * DFF)
#define W_TOTAL  (W_QKV_SZ + W_OUT_SZ + W_UP_SZ + W_DN_SZ)

__device__ float g_scale1[NBATCH * DM];
__device__ float g_scale2[NBATCH * DM];
__device__ float g_x2  [(size_t)TOKENS * DM];

__device__ __half g_qkvh[(size_t)TOKENS * 2 * DM];    // q,k fp16 (ld=1536)
__device__ __half g_vwh [(size_t)NWIN * 64 * 64];     // v windowed fp16
__device__ __half g_h   [(size_t)TOKENS * DM];        // activations fp16
__device__ __half g_oi  [(size_t)TOKENS * DM];
__device__ __half g_a   [(size_t)TOKENS * DFF];
__device__ __half g_w   [W_TOTAL];                    // weights fp16

// ---------------------------------------------------------------------------
// PTX helpers (sm_80+ features only; legal under compute_103)
// ---------------------------------------------------------------------------
__device__ __forceinline__ uint32_t smem_to_u32(const void* p) {
    uint32_t a;
    asm("{ .reg .u64 t; cvta.to.shared.u64 t, %1; cvt.u32.u64 %0, t; }" : "=r"(a) : "l"(p));
    return a;
}
#define CP_ASYNC16(sa, gp) \
    asm volatile("cp.async.cg.shared.global [%0], [%1], 16;" :: "r"(sa), "l"(gp))
#define CP_COMMIT() asm volatile("cp.async.commit_group;" ::: "memory")
#define CP_WAIT2()  asm volatile("cp.async.wait_group 2;" ::: "memory")
#define CP_WAIT1()  asm volatile("cp.async.wait_group 1;" ::: "memory")
#define CP_WAIT0()  asm volatile("cp.async.wait_group 0;" ::: "memory")

__device__ __forceinline__ void ldsm_x4(uint32_t& r0, uint32_t& r1, uint32_t& r2,
                                        uint32_t& r3, uint32_t addr) {
    asm volatile("ldmatrix.sync.aligned.m8n8.x4.shared.b16 {%0,%1,%2,%3}, [%4];"
                 : "=r"(r0), "=r"(r1), "=r"(r2), "=r"(r3) : "r"(addr));
}
__device__ __forceinline__ void ldsm_x4_t(uint32_t& r0, uint32_t& r1, uint32_t& r2,
                                          uint32_t& r3, uint32_t addr) {
    asm volatile("ldmatrix.sync.aligned.m8n8.x4.trans.shared.b16 {%0,%1,%2,%3}, [%4];"
                 : "=r"(r0), "=r"(r1), "=r"(r2), "=r"(r3) : "r"(addr));
}
__device__ __forceinline__ void mma_f16(float c[4], const uint32_t a[4],
                                        const uint32_t b[2]) {
    asm volatile("mma.sync.aligned.m16n8k16.row.col.f32.f16.f16.f32 "
                 "{%0,%1,%2,%3},{%4,%5,%6,%7},{%8,%9},{%0,%1,%2,%3};"
                 : "+f"(c[0]), "+f"(c[1]), "+f"(c[2]), "+f"(c[3])
                 : "r"(a[0]), "r"(a[1]), "r"(a[2]), "r"(a[3]),
                   "r"(b[0]), "r"(b[1]));
}
__device__ __forceinline__ uint32_t pack_h2(float a, float b) {
    __half2 h = __floats2half2_rn(a, b);
    return *(uint32_t*)&h;
}

// window-scatter address helper (roll +4,+4 then 8x8 windows)
__device__ __forceinline__ size_t win_addr(int t, int h, int e) {
    int n = t >> 14;
    int y = (t >> 7) & 127;
    int x = t & 127;
    int Y = (y + SHIFT) & 127, X = (x + SHIFT) & 127;
    int wyx  = ((Y >> 3) << 4) + (X >> 3);
    int spos = ((Y & 7) << 3) + (X & 7);
    return ((size_t)((n * NHEADS + h) * 256 + wyx)) * 4096 + (size_t)spos * 64 + e;
}

// inverse: window b, slot r -> token index
__device__ __forceinline__ int win_token(int b, int r) {
    int n   = b / (NHEADS * 256);
    int rem = b % (NHEADS * 256);
    int w   = rem & 255;
    int Y = ((w >> 4) << 3) + (r >> 3);
    int X = ((w & 15) << 3) + (r & 7);
    int y = (Y - SHIFT) & 127, x = (X - SHIFT) & 127;
    return (n << 14) + (y << 7) + x;
}

// ---------------------------------------------------------------------------
// GEMM (R12 proven): 128x256x64 tile, 8 warps, 4-stage ring, 1 sync/stage.
// mode 0: C fp32 = (D?D:0) + A@B^T
// mode 1: fused gated-GELU -> g_a (fp16)
// mode 2: qkv: cols<1536 -> g_qkvh fp16; cols>=1536 -> windowed V fp16
// ---------------------------------------------------------------------------
#define BKC      64
#define PADK     72
#define TILE_A_E (128 * PADK)
#define TILE_B_E (256 * PADK)
#define STAGE_E  (TILE_A_E + TILE_B_E)
#define NSTG     4
#define GEMM_SMEM (NSTG * STAGE_E * 2)       // 221184 bytes

__global__ __launch_bounds__(256) void hgemm_kernel(
    const __half* __restrict__ A, const __half* __restrict__ B,
    const float* __restrict__ Dres, float* __restrict__ C,
    int M, int N, int K, int ldc, int mode)
{
    extern __shared__ __align__(128) char smem[];
    const uint32_t sbase = smem_to_u32(smem);
    const int tid = threadIdx.x, lane = tid & 31, wid = tid >> 5;
    const int wm = wid >> 2, wn = wid & 3;
    const size_t bm = (size_t)blockIdx.y * 128;
    const size_t bn = (size_t)blockIdx.x * 256;

    const __half* Ab = A + bm * (size_t)K;
    const __half* Bb = B + bn * (size_t)K;

    float acc[4][8][4];
    #pragma unroll
    for (int i = 0; i < 4; i++)
        #pragma unroll
        for (int j = 0; j < 8; j++)
            #pragma unroll
            for (int l = 0; l < 4; l++) acc[i][j][l] = 0.f;

    const int nstage = K / BKC;

    auto issue = [&](int st) {
        const int k0 = st * BKC;
        const uint32_t sb = sbase + (uint32_t)((st & (NSTG - 1)) * STAGE_E * 2);
        #pragma unroll
        for (int i = 0; i < 4; i++) {
            int idx = tid + i * 256;
            int row = idx >> 3, seg = (idx & 7) << 3;
            const __half* gp = Ab + (size_t)row * K + k0 + seg;
            uint32_t sa = sb + (uint32_t)((row * PADK + seg) * 2);
            CP_ASYNC16(sa, gp);
        }
        #pragma unroll
        for (int i = 0; i < 8; i++) {
            int idx = tid + i * 256;
            int row = idx >> 3, seg = (idx & 7) << 3;
            const __half* gp = Bb + (size_t)row * K + k0 + seg;
            uint32_t sa = sb + (uint32_t)((TILE_A_E + row * PADK + seg) * 2);
            CP_ASYNC16(sa, gp);
        }
        CP_COMMIT();
    };

    issue(0);
    if (nstage > 1) issue(1);
    if (nstage > 2) issue(2);

    const int a_r = lane & 15, a_h = (lane >> 4) << 3;
    const int b_r = (lane & 7) + ((lane & 16) >> 1);
    const int b_k = lane & 8;

    for (int st = 0; st < nstage; st++) {
        if (st < nstage - 2)       { CP_WAIT2(); }
        else if (st == nstage - 2) { CP_WAIT1(); }
        else                       { CP_WAIT0(); }
        __syncthreads();

        const uint32_t sb = sbase + (uint32_t)((st & (NSTG - 1)) * STAGE_E * 2);
        const uint32_t sA = sb;
        const uint32_t sB = sb + TILE_A_E * 2;

        #pragma unroll
        for (int kk = 0; kk < BKC; kk += 16) {
            uint32_t a[4][4], bh[8][2];
            #pragma unroll
            for (int mt = 0; mt < 4; mt++)
                ldsm_x4(a[mt][0], a[mt][1], a[mt][2], a[mt][3],
                        sA + (uint32_t)(((wm * 64 + mt * 16 + a_r) * PADK + kk + a_h) * 2));
            #pragma unroll
            for (int p = 0; p < 4; p++) {
                uint32_t r0, r1, r2, r3;
                ldsm_x4(r0, r1, r2, r3,
                        sB + (uint32_t)(((wn * 64 + p * 16 + b_r) * PADK + kk + b_k) * 2));
                bh[p * 2][0] = r0; bh[p * 2][1] = r1;
                bh[p * 2 + 1][0] = r2; bh[p * 2 + 1][1] = r3;
            }
            #pragma unroll
            for (int mt = 0; mt < 4; mt++)
                #pragma unroll
                for (int nt = 0; nt < 8; nt++)
                    mma_f16(acc[mt][nt], a[mt], bh[nt]);
        }
        if (st + 3 < nstage) issue(st + 3);
    }

    const int er = lane >> 2, ec = (lane & 3) * 2;

    if (mode == 1) {
        #pragma unroll
        for (int mt = 0; mt < 4; mt++) {
            size_t r0 = bm + wm * 64 + mt * 16 + er;
            size_t r1 = r0 + 8;
            #pragma unroll
            for (int nt = 0; nt < 8; nt++) {
                int col = (int)bn + wn * 64 + nt * 8 + ec;
                int j = col >> 1;
                float a0 = acc[mt][nt][0], gg0 = acc[mt][nt][1];
                float a1 = acc[mt][nt][2], gg1 = acc[mt][nt][3];
                float v0 = a0 * (gg0 * 0.5f * (1.0f + erff(gg0 * 0.70710678118654752f)));
                float v1 = a1 * (gg1 * 0.5f * (1.0f + erff(gg1 * 0.70710678118654752f)));
                g_a[r0 * DFF + j] = __float2half(v0);
                g_a[r1 * DFF + j] = __float2half(v1);
            }
        }
        return;
    }

    if (mode == 2) {
        #pragma unroll
        for (int mt = 0; mt < 4; mt++) {
            int t0 = (int)bm + wm * 64 + mt * 16 + er;
            int t1 = t0 + 8;
            #pragma unroll
            for (int nt = 0; nt < 8; nt++) {
                int col = (int)bn + wn * 64 + nt * 8 + ec;
                uint32_t w0 = pack_h2(acc[mt][nt][0], acc[mt][nt][1]);
                uint32_t w1 = pack_h2(acc[mt][nt][2], acc[mt][nt][3]);
                if (col < 1536) {
                    *(uint32_t*)&g_qkvh[(size_t)t0 * 1536 + col] = w0;
                    *(uint32_t*)&g_qkvh[(size_t)t1 * 1536 + col] = w1;
                } else {
                    int h = (col - 1536) >> 6;
                    int e = col & 63;
                    *(uint32_t*)&g_vwh[win_addr(t0, h, e)] = w0;
                    *(uint32_t*)&g_vwh[win_addr(t1, h, e)] = w1;
                }
            }
        }
        return;
    }

    #pragma unroll
    for (int mt = 0; mt < 4; mt++) {
        size_t row0 = bm + wm * 64 + mt * 16 + er;
        #pragma unroll
        for (int nt = 0; nt < 8; nt++) {
            size_t col = bn + wn * 64 + nt * 8 + ec;
            float* p0 = C + row0 * (size_t)ldc + col;
            float* p1 = C + (row0 + 8) * (size_t)ldc + col;
            float2 v0 = make_float2(acc[mt][nt][0], acc[mt][nt][1]);
            float2 v1 = make_float2(acc[mt][nt][2], acc[mt][nt][3]);
            if (Dres) {
                const float2 d0 = *(const float2*)(Dres + row0 * (size_t)ldc + col);
                const float2 d1 = *(const float2*)(Dres + (row0 + 8) * (size_t)ldc + col);
                v0.x += d0.x; v0.y += d0.y; v1.x += d1.x; v1.y += d1.y;
            }
            *(float2*)p0 = v0;
            *(float2*)p1 = v1;
        }
    }
}

// ---------------------------------------------------------------------------
// K0: ada scales
// ---------------------------------------------------------------------------
__global__ void ada_kernel(const float* __restrict__ cond,
                           const float* __restrict__ w1,
                           const float* __restrict__ w2)
{
    int gw   = (blockIdx.x * blockDim.x + threadIdx.x) >> 5;
    int lane = threadIdx.x & 31;
    if (gw >= 2 * NBATCH * DM) return;
    int which = gw / (NBATCH * DM);
    int rem   = gw % (NBATCH * DM);
    int n = rem / DM, d = rem % DM;
    const float* w  = which ? w2 : w1;
    const float* cr = cond + n * DC;
    const float* wr = w + (size_t)d * DC;
    float s = 0.f;
    for (int i = lane; i < DC; i += 32) s += cr[i] * wr[i];
    #pragma unroll
    for (int o = 16; o; o >>= 1) s += __shfl_xor_sync(0xffffffffu, s, o);
    if (lane == 0) (which ? g_scale2 : g_scale1)[rem] = s + 1.0f;
}

// ---------------------------------------------------------------------------
// K1: RMSNorm * ada -> fp16.  One WARP per token: no barriers, no smem.
// Lane holds 6 float4 (24 values); shfl reduction. grid = TOKENS/8.
// ---------------------------------------------------------------------------
__global__ __launch_bounds__(256) void rmsnorm_kernel(const float* __restrict__ x,
                                                      const float* __restrict__ scale)
{
    int t = blockIdx.x * 8 + (threadIdx.x >> 5);
    int lane = threadIdx.x & 31;
    int n = t >> 14;
    const float* xr = x + (size_t)t * DM;
    const float* sc = scale + (size_t)n * DM;

    float4 v[6];
    float ss = 0.f;
    #pragma unroll
    for (int j = 0; j < 6; j++) {
        v[j] = *(const float4*)(xr + (lane + j * 32) * 4);
        ss += v[j].x * v[j].x + v[j].y * v[j].y + v[j].z * v[j].z + v[j].w * v[j].w;
    }
    #pragma unroll
    for (int o = 16; o; o >>= 1) ss += __shfl_xor_sync(0xffffffffu, ss, o);
    float inv = rsqrtf(ss * (1.0f / DM) + EPSV);

    __half* orow = g_h + (size_t)t * DM;
    #pragma unroll
    for (int j = 0; j < 6; j++) {
        int c = (lane + j * 32) * 4;
        float4 s4 = *(const float4*)(sc + c);
        uint2 pk;
        pk.x = pack_h2(v[j].x * s4.x * inv, v[j].y * s4.y * inv);
        pk.y = pack_h2(v[j].z * s4.z * inv, v[j].w * s4.w * inv);
        *(uint2*)(orow + c) = pk;
    }
}

// ---------------------------------------------------------------------------
// K2: fused weight convert fp32 -> fp16 (all four weights, one launch)
// ---------------------------------------------------------------------------
__global__ __launch_bounds__(256) void wconv_all_kernel(const float* __restrict__ qkv_w,
                                                        const float* __restrict__ out_w,
                                                        const float* __restrict__ up_w,
                                                        const float* __restrict__ dn_w)
{
    const int OQKV = 0;
    const int OOUT = OQKV + W_QKV_SZ;
    const int OUP  = OOUT + W_OUT_SZ;
    const int ODN  = OUP + W_UP_SZ;

    for (int i = blockIdx.x * 256 + threadIdx.x; i < W_TOTAL; i += gridDim.x * 256) {
        float v; int dst;
        if (i < OOUT) {                       // qkv
            v = qkv_w[i - OQKV]; dst = i;
        } else if (i < OUP) {                 // out
            v = out_w[i - OOUT]; dst = i;
        } else if (i < ODN) {                 // ff_up with row interleave
            int li = i - OUP;
            v = up_w[li];
            int r = li / DM, c = li % DM;
            int dr = (r < DFF) ? (2 * r) : (2 * (r - DFF) + 1);
            dst = OUP + dr * DM + c;
        } else {                              // ff_down
            v = dn_w[i - ODN]; dst = i;
        }
        g_w[dst] = __float2half(v);
    }
}

// ---------------------------------------------------------------------------
// K3: fused tensor-core attention (R15 proven), all-fp16 data path.
// ---------------------------------------------------------------------------
#define AHP  72
#define AQH  0
#define AKH  (64 * AHP * 2)
#define AVH  (2 * 64 * AHP * 2)
#define ATT_SMEM (3 * 64 * AHP * 2)            // 27648

__global__ __launch_bounds__(128) void attn_kernel(const float* __restrict__ pos,
                                                   const float* __restrict__ attn_scale,
                                                   const float* __restrict__ rope_freqs)
{
    extern __shared__ __align__(16) char smc[];
    const uint32_t sb = smem_to_u32(smc);
    const uint32_t qh_b = sb + AQH, kh_b = sb + AKH, vh_b = sb + AVH;
    __half* qs = (__half*)(smc + AQH);
    __half* ks = (__half*)(smc + AKH);

    const int b   = blockIdx.x;
    const int rem = b % (NHEADS * 256);
    const int h   = rem >> 8;
    const int w   = rem & 255;
    const bool left = ((w & 15) == 0), top = ((w >> 4) == 0);
    const int tid = threadIdx.x, warp = tid >> 5, lane = tid & 31;

    const __half* vb = g_vwh + (size_t)b * 4096;
    for (int i = tid; i < 1024; i += 128) {
        int r = i >> 4, c4 = (i & 15) << 2;
        int t = win_token(b, r);
        const __half* qk = g_qkvh + (size_t)t * 1536 + h * DHEAD + c4;
        uint2 qv = *(const uint2*)qk;
        uint2 kv = *(const uint2*)(qk + DM);
        uint2 vv = *(const uint2*)(vb + (i << 2));
        *(uint2*)(smc + AQH + (r * AHP + c4) * 2) = qv;
        *(uint2*)(smc + AKH + (r * AHP + c4) * 2) = kv;
        *(uint2*)(smc + AVH + (r * AHP + c4) * 2) = vv;
    }
    __syncthreads();

    // norm + RoPE, spill-free: threads 0..63 -> q rows, 64..127 -> k rows
    {
        int row = tid & 63;
        __half* prow = (tid < 64 ? qs : ks) + row * AHP;
        __half2* prow2 = (__half2*)prow;

        float ss = 0.f;
        #pragma unroll
        for (int e2 = 0; e2 < 32; e2++) {
            float2 f = __half22float2(prow2[e2]);
            ss += f.x * f.x + f.y * f.y;
        }
        float r = sqrtf(attn_scale[h]) * rsqrtf(ss + EPSV);

        int t = win_token(b, row);
        float p0 = pos[(size_t)t * 2 + 0];
        float p1 = pos[(size_t)t * 2 + 1];
        #pragma unroll
        for (int e = 0; e < 16; e++) {
            float freq = rope_freqs[h * 8 + (e & 7)];
            float th = (e < 8 ? p0 : p1) * freq;
            float c = cosf(th), s = sinf(th);
            float v1 = __half2float(prow[e]) * r;
            float v2 = __half2float(prow[e + 16]) * r;
            prow[e]      = __float2half(v1 * c - v2 * s);
            prow[e + 16] = __float2half(v2 * c + v1 * s);
        }
        #pragma unroll
        for (int e2 = 16; e2 < 32; e2++) {
            float2 f = __half22float2(prow2[e2]);
            prow2[e2] = __floats2half2_rn(f.x * r, f.y * r);
        }
    }
    __syncthreads();

    const int a_r = lane & 15, a_h2 = (lane >> 4) << 3;
    const int b_r = (lane & 7) + ((lane & 16) >> 1);
    const int b_k = lane & 8;

    float sc[8][4];
    #pragma unroll
    for (int nt = 0; nt < 8; nt++)
        #pragma unroll
        for (int j = 0; j < 4; j++) sc[nt][j] = 0.f;

    uint32_t afr[4][4];
    #pragma unroll
    for (int kt = 0; kt < 4; kt++)
        ldsm_x4(afr[kt][0], afr[kt][1], afr[kt][2], afr[kt][3],
                qh_b + (uint32_t)(((warp * 16 + a_r) * AHP + kt * 16 + a_h2) * 2));

    #pragma unroll
    for (int kt = 0; kt < 4; kt++) {
        uint32_t bh[8][2];
        #pragma unroll
        for (int p = 0; p < 4; p++) {
            uint32_t r0, r1, r2, r3;
            ldsm_x4(r0, r1, r2, r3,
                    kh_b + (uint32_t)(((p * 16 + b_r) * AHP + kt * 16 + b_k) * 2));
            bh[p * 2][0] = r0; bh[p * 2][1] = r1;
            bh[p * 2 + 1][0] = r2; bh[p * 2 + 1][1] = r3;
        }
        #pragma unroll
        for (int nt = 0; nt < 8; nt++)
            mma_f16(sc[nt], afr[kt], bh[nt]);
    }

    const int er = lane >> 2, ec = (lane & 3) * 2;
    const int r0 = warp * 16 + er, r1 = r0 + 8;
    const bool qa0 = ((r0 >> 3) < SHIFT), ql0 = ((r0 & 7) < SHIFT);
    const bool qa1 = ((r1 >> 3) < SHIFT), ql1 = ((r1 & 7) < SHIFT);

    float mx0 = -3.402823466e38f, mx1 = -3.402823466e38f;
    #pragma unroll
    for (int nt = 0; nt < 8; nt++) {
        bool ka = nt < SHIFT;
        #pragma unroll
        for (int j = 0; j < 2; j++) {
            bool kl = (ec + j) < SHIFT;
            bool m0 = (!left && !top)
                    || (left && top && (ql0 == kl) && (qa0 == ka))
                    || (left && !top && (ql0 == kl))
                    || (!left && top && (qa0 == ka));
            bool m1 = (!left && !top)
                    || (left && top && (ql1 == kl) && (qa1 == ka))
                    || (left && !top && (ql1 == kl))
                    || (!left && top && (qa1 == ka));
            if (!m0) sc[nt][j]     = -3.402823466e38f;
            if (!m1) sc[nt][2 + j] = -3.402823466e38f;
            mx0 = fmaxf(mx0, sc[nt][j]);
            mx1 = fmaxf(mx1, sc[nt][2 + j]);
        }
    }
    mx0 = fmaxf(mx0, __shfl_xor_sync(0xffffffffu, mx0, 1));
    mx0 = fmaxf(mx0, __shfl_xor_sync(0xffffffffu, mx0, 2));
    mx1 = fmaxf(mx1, __shfl_xor_sync(0xffffffffu, mx1, 1));
    mx1 = fmaxf(mx1, __shfl_xor_sync(0xffffffffu, mx1, 2));

    float s0 = 0.f, s1 = 0.f;
    #pragma unroll
    for (int nt = 0; nt < 8; nt++) {
        #pragma unroll
        for (int j = 0; j < 2; j++) {
            float p0v = __expf(sc[nt][j] - mx0);
            float p1v = __expf(sc[nt][2 + j] - mx1);
            sc[nt][j] = p0v; sc[nt][2 + j] = p1v;
            s0 += p0v; s1 += p1v;
        }
    }
    s0 += __shfl_xor_sync(0xffffffffu, s0, 1);
    s0 += __shfl_xor_sync(0xffffffffu, s0, 2);
    s1 += __shfl_xor_sync(0xffffffffu, s1, 1);
    s1 += __shfl_xor_sync(0xffffffffu, s1, 2);
    float inv0 = 1.0f / s0, inv1 = 1.0f / s1;

    uint32_t pf[4][4];
    #pragma unroll
    for (int kt = 0; kt < 4; kt++) {
        pf[kt][0] = pack_h2(sc[2 * kt][0],     sc[2 * kt][1]);
        pf[kt][1] = pack_h2(sc[2 * kt][2],     sc[2 * kt][3]);
        pf[kt][2] = pack_h2(sc[2 * kt + 1][0], sc[2 * kt + 1][1]);
        pf[kt][3] = pack_h2(sc[2 * kt + 1][2], sc[2 * kt + 1][3]);
    }

    float oo[8][4];
    #pragma unroll
    for (int nt = 0; nt < 8; nt++)
        #pragma unroll
        for (int j = 0; j < 4; j++) oo[nt][j] = 0.f;

    const int v_r = lane & 15, v_c = (lane >> 4) << 3;
    #pragma unroll
    for (int kt = 0; kt < 4; kt++) {
        uint32_t bv[8][2];
        #pragma unroll
        for (int p = 0; p < 4; p++) {
            uint32_t r0v, r1v, r2v, r3v;
            ldsm_x4_t(r0v, r1v, r2v, r3v,
                      vh_b + (uint32_t)(((kt * 16 + v_r) * AHP + p * 16 + v_c) * 2));
            bv[p * 2][0] = r0v; bv[p * 2][1] = r1v;
            bv[p * 2 + 1][0] = r2v; bv[p * 2 + 1][1] = r3v;
        }
        #pragma unroll
        for (int nt = 0; nt < 8; nt++)
            mma_f16(oo[nt], pf[kt], bv[nt]);
    }

    int t0 = win_token(b, r0), t1 = win_token(b, r1);
    #pragma unroll
    for (int nt = 0; nt < 8; nt++) {
        int col = h * DHEAD + nt * 8 + ec;
        uint32_t w0 = pack_h2(oo[nt][0] * inv0, oo[nt][1] * inv0);
        uint32_t w1 = pack_h2(oo[nt][2] * inv1, oo[nt][3] * inv1);
        *(uint32_t*)&g_oi[(size_t)t0 * DM + col] = w0;
        *(uint32_t*)&g_oi[(size_t)t1 * DM + col] = w1;
    }
}

// ---------------------------------------------------------------------------
// host
// ---------------------------------------------------------------------------
static void launch_hgemm(const __half* A, const __half* B,
                         const float* D, float* C, int M, int N, int K,
                         int ldc, int mode)
{
    dim3 grid(N / 256, M / 128);
    hgemm_kernel<<<grid, 256, GEMM_SMEM>>>(A, B, D, C, M, N, K, ldc, mode);
}

extern "C" void kernel_launch(void* const* d_in, const int* in_sizes, int n_in,
                              void* d_out, int out_size)
{
    const float* x          = (const float*)d_in[0];
    const float* pos        = (const float*)d_in[1];
    const float* cond       = (const float*)d_in[2];
    const float* ada1_w     = (const float*)d_in[3];
    const float* qkv_w      = (const float*)d_in[4];
    const float* attn_scale = (const float*)d_in[5];
    const float* rope_freqs = (const float*)d_in[6];
    const float* out_w      = (const float*)d_in[7];
    const float* ada2_w     = (const float*)d_in[8];
    const float* ff_up_w    = (const float*)d_in[9];
    const float* ff_down_w  = (const float*)d_in[10];
    float* out = (float*)d_out;

    cudaFuncSetAttribute(hgemm_kernel, cudaFuncAttributeMaxDynamicSharedMemorySize, GEMM_SMEM);
    cudaFuncSetAttribute(attn_kernel, cudaFuncAttributeMaxDynamicSharedMemorySize, ATT_SMEM);

    float *p_scale1, *p_scale2, *p_x2;
    __half *p_h, *p_oi, *p_a, *p_w;
    cudaGetSymbolAddress((void**)&p_scale1, g_scale1);
    cudaGetSymbolAddress((void**)&p_scale2, g_scale2);
    cudaGetSymbolAddress((void**)&p_x2,     g_x2);
    cudaGetSymbolAddress((void**)&p_h,      g_h);
    cudaGetSymbolAddress((void**)&p_oi,     g_oi);
    cudaGetSymbolAddress((void**)&p_a,      g_a);
    cudaGetSymbolAddress((void**)&p_w,      g_w);

    const int OQKV = 0;
    const int OOUT = OQKV + W_QKV_SZ;
    const int OUP  = OOUT + W_OUT_SZ;
    const int ODN  = OUP + W_UP_SZ;

    // all four weight conversions in one launch
    wconv_all_kernel<<<2048, 256>>>(qkv_w, out_w, ff_up_w, ff_down_w);

    ada_kernel<<<768, 256>>>(cond, ada1_w, ada2_w);
    // warp-per-token rmsnorm
    rmsnorm_kernel<<<TOKENS / 8, 256>>>(x, p_scale1);
    // qkv: q,k -> g_qkvh fp16; v -> windowed fp16 g_vwh
    launch_hgemm(p_h, p_w + OQKV, nullptr, nullptr, TOKENS, 3 * DM, DM, 0, 2);
    // fused qk-transform + tensor-core attention + unwindow
    attn_kernel<<<NWIN, 128, ATT_SMEM>>>(pos, attn_scale, rope_freqs);
    launch_hgemm(p_oi, p_w + OOUT, x, p_x2, TOKENS, DM, DM, DM, 0);
    rmsnorm_kernel<<<TOKENS / 8, 256>>>(p_x2, p_scale2);
    // ff_up with fused gated GELU (interleaved weights) -> g_a
    launch_hgemm(p_h, p_w + OUP, nullptr, nullptr, TOKENS, 2 * DFF, DM, 2 * DFF, 1);
    launch_hgemm(p_a, p_w + ODN, p_x2, out, TOKENS, DM, DFF, DM, 0);
}

// round 17
// speedup vs baseline: 2.8279x; 1.0457x over previous
#include <cuda_runtime.h>
#include <cuda_bf16.h>
#include <cuda_fp16.h>
#include <math.h>
#include <stdint.h>

// ---------------------------------------------------------------------------
// Problem constants
// ---------------------------------------------------------------------------
#define NBATCH   4
#define HDIM     128
#define WDIM     128
#define DM       768
#define NHEADS   12
#define DHEAD    64
#define DFF      2048
#define DC       768
#define WS       8
#define SHIFT    4
#define TOKENS   (NBATCH * HDIM * WDIM)          // 65536
#define NWIN     (NBATCH * NHEADS * 16 * 16)     // 12288
#define EPSV     1e-6f

// ---------------------------------------------------------------------------
// Scratch
// ---------------------------------------------------------------------------
#define W_QKV_SZ (3 * DM * DM)
#define W_OUT_SZ (DM * DM)
#define W_UP_SZ  (2 * DFF * DM)
#define W_DN_SZ  (DM * DFF)
#define W_TOTAL  (W_QKV_SZ + W_OUT_SZ + W_UP_SZ + W_DN_SZ)

__device__ float g_scale1[NBATCH * DM];
__device__ float g_scale2[NBATCH * DM];
__device__ float g_x2  [(size_t)TOKENS * DM];

__device__ __half g_qkvh[(size_t)TOKENS * 2 * DM];    // q,k fp16 (ld=1536)
__device__ __half g_vwh [(size_t)NWIN * 64 * 64];     // v windowed fp16
__device__ __half g_h   [(size_t)TOKENS * DM];        // activations fp16
__device__ __half g_oi  [(size_t)TOKENS * DM];
__device__ __half g_a   [(size_t)TOKENS * DFF];
__device__ __half g_w   [W_TOTAL];                    // weights fp16

// ---------------------------------------------------------------------------
// PTX helpers (sm_80+ features only; legal under compute_103)
// ---------------------------------------------------------------------------
__device__ __forceinline__ uint32_t smem_to_u32(const void* p) {
    uint32_t a;
    asm("{ .reg .u64 t; cvta.to.shared.u64 t, %1; cvt.u32.u64 %0, t; }" : "=r"(a) : "l"(p));
    return a;
}
#define CP_ASYNC16(sa, gp) \
    asm volatile("cp.async.cg.shared.global [%0], [%1], 16;" :: "r"(sa), "l"(gp))
#define CP_COMMIT() asm volatile("cp.async.commit_group;" ::: "memory")
#define CP_WAIT1()  asm volatile("cp.async.wait_group 1;" ::: "memory")
#define CP_WAIT0()  asm volatile("cp.async.wait_group 0;" ::: "memory")

__device__ __forceinline__ void ldsm_x4(uint32_t& r0, uint32_t& r1, uint32_t& r2,
                                        uint32_t& r3, uint32_t addr) {
    asm volatile("ldmatrix.sync.aligned.m8n8.x4.shared.b16 {%0,%1,%2,%3}, [%4];"
                 : "=r"(r0), "=r"(r1), "=r"(r2), "=r"(r3) : "r"(addr));
}
__device__ __forceinline__ void ldsm_x4_t(uint32_t& r0, uint32_t& r1, uint32_t& r2,
                                          uint32_t& r3, uint32_t addr) {
    asm volatile("ldmatrix.sync.aligned.m8n8.x4.trans.shared.b16 {%0,%1,%2,%3}, [%4];"
                 : "=r"(r0), "=r"(r1), "=r"(r2), "=r"(r3) : "r"(addr));
}
__device__ __forceinline__ void mma_f16(float c[4], const uint32_t a[4],
                                        const uint32_t b[2]) {
    asm volatile("mma.sync.aligned.m16n8k16.row.col.f32.f16.f16.f32 "
                 "{%0,%1,%2,%3},{%4,%5,%6,%7},{%8,%9},{%0,%1,%2,%3};"
                 : "+f"(c[0]), "+f"(c[1]), "+f"(c[2]), "+f"(c[3])
                 : "r"(a[0]), "r"(a[1]), "r"(a[2]), "r"(a[3]),
                   "r"(b[0]), "r"(b[1]));
}
__device__ __forceinline__ uint32_t pack_h2(float a, float b) {
    __half2 h = __floats2half2_rn(a, b);
    return *(uint32_t*)&h;
}

// window-scatter address helper (roll +4,+4 then 8x8 windows)
__device__ __forceinline__ size_t win_addr(int t, int h, int e) {
    int n = t >> 14;
    int y = (t >> 7) & 127;
    int x = t & 127;
    int Y = (y + SHIFT) & 127, X = (x + SHIFT) & 127;
    int wyx  = ((Y >> 3) << 4) + (X >> 3);
    int spos = ((Y & 7) << 3) + (X & 7);
    return ((size_t)((n * NHEADS + h) * 256 + wyx)) * 4096 + (size_t)spos * 64 + e;
}

// inverse: window b, slot r -> token index
__device__ __forceinline__ int win_token(int b, int r) {
    int n   = b / (NHEADS * 256);
    int rem = b % (NHEADS * 256);
    int w   = rem & 255;
    int Y = ((w >> 4) << 3) + (r >> 3);
    int X = ((w & 15) << 3) + (r & 7);
    int y = (Y - SHIFT) & 127, x = (X - SHIFT) & 127;
    return (n << 14) + (y << 7) + x;
}

// ---------------------------------------------------------------------------
// GEMM: 128x128x64 CTA tile, 128 threads (4 warps, 2m x 2n), warp tile 64x64.
// 3-stage cp.async ring, ONE sync per stage. Small CTA -> 2 CTAs/SM so
// barriers/prologue of one CTA overlap with the other's compute.
// mode 0: C fp32 = (D?D:0) + A@B^T
// mode 1: fused gated-GELU -> g_a (fp16)
// mode 2: qkv: cols<1536 -> g_qkvh fp16; cols>=1536 -> windowed V fp16
// ---------------------------------------------------------------------------
#define BKC      64
#define PADK     72
#define TILE_A_E (128 * PADK)
#define TILE_B_E (128 * PADK)
#define STAGE_E  (TILE_A_E + TILE_B_E)       // 18432 elems = 36864 B
#define NSTG     3
#define GEMM_SMEM (NSTG * STAGE_E * 2)       // 110592 bytes

__global__ __launch_bounds__(128) void hgemm_kernel(
    const __half* __restrict__ A, const __half* __restrict__ B,
    const float* __restrict__ Dres, float* __restrict__ C,
    int M, int N, int K, int ldc, int mode)
{
    extern __shared__ __align__(128) char smem[];
    const uint32_t sbase = smem_to_u32(smem);
    const int tid = threadIdx.x, lane = tid & 31, wid = tid >> 5;
    const int wm = wid >> 1, wn = wid & 1;
    const size_t bm = (size_t)blockIdx.y * 128;
    const size_t bn = (size_t)blockIdx.x * 128;

    const __half* Ab = A + bm * (size_t)K;
    const __half* Bb = B + bn * (size_t)K;

    float acc[4][8][4];
    #pragma unroll
    for (int i = 0; i < 4; i++)
        #pragma unroll
        for (int j = 0; j < 8; j++)
            #pragma unroll
            for (int l = 0; l < 4; l++) acc[i][j][l] = 0.f;

    const int nstage = K / BKC;

    // A: 1024 16B-chunks (8 iters of 128 thr), B likewise
    auto issue = [&](int st) {
        const int k0 = st * BKC;
        int s3 = st % NSTG;
        const uint32_t sb = sbase + (uint32_t)(s3 * STAGE_E * 2);
        #pragma unroll
        for (int i = 0; i < 8; i++) {
            int idx = tid + i * 128;
            int row = idx >> 3, seg = (idx & 7) << 3;
            const __half* gp = Ab + (size_t)row * K + k0 + seg;
            uint32_t sa = sb + (uint32_t)((row * PADK + seg) * 2);
            CP_ASYNC16(sa, gp);
        }
        #pragma unroll
        for (int i = 0; i < 8; i++) {
            int idx = tid + i * 128;
            int row = idx >> 3, seg = (idx & 7) << 3;
            const __half* gp = Bb + (size_t)row * K + k0 + seg;
            uint32_t sa = sb + (uint32_t)((TILE_A_E + row * PADK + seg) * 2);
            CP_ASYNC16(sa, gp);
        }
        CP_COMMIT();
    };

    issue(0);
    if (nstage > 1) issue(1);

    const int a_r = lane & 15, a_h = (lane >> 4) << 3;
    const int b_r = (lane & 7) + ((lane & 16) >> 1);
    const int b_k = lane & 8;

    for (int st = 0; st < nstage; st++) {
        if (st < nstage - 1) { CP_WAIT1(); } else { CP_WAIT0(); }
        __syncthreads();

        int s3 = st % NSTG;
        const uint32_t sb = sbase + (uint32_t)(s3 * STAGE_E * 2);
        const uint32_t sA = sb;
        const uint32_t sB = sb + TILE_A_E * 2;

        #pragma unroll
        for (int kk = 0; kk < BKC; kk += 16) {
            uint32_t a[4][4], bh[8][2];
            #pragma unroll
            for (int mt = 0; mt < 4; mt++)
                ldsm_x4(a[mt][0], a[mt][1], a[mt][2], a[mt][3],
                        sA + (uint32_t)(((wm * 64 + mt * 16 + a_r) * PADK + kk + a_h) * 2));
            #pragma unroll
            for (int p = 0; p < 4; p++) {
                uint32_t r0, r1, r2, r3;
                ldsm_x4(r0, r1, r2, r3,
                        sB + (uint32_t)(((wn * 64 + p * 16 + b_r) * PADK + kk + b_k) * 2));
                bh[p * 2][0] = r0; bh[p * 2][1] = r1;
                bh[p * 2 + 1][0] = r2; bh[p * 2 + 1][1] = r3;
            }
            #pragma unroll
            for (int mt = 0; mt < 4; mt++)
                #pragma unroll
                for (int nt = 0; nt < 8; nt++)
                    mma_f16(acc[mt][nt], a[mt], bh[nt]);
        }
        // single sync per stage: issue into buf (st+2)%3 == (st-1)%3,
        // whose reads completed before this stage's top sync.
        if (st + 2 < nstage) issue(st + 2);
    }

    const int er = lane >> 2, ec = (lane & 3) * 2;

    if (mode == 1) {
        #pragma unroll
        for (int mt = 0; mt < 4; mt++) {
            size_t r0 = bm + wm * 64 + mt * 16 + er;
            size_t r1 = r0 + 8;
            #pragma unroll
            for (int nt = 0; nt < 8; nt++) {
                int col = (int)bn + wn * 64 + nt * 8 + ec;
                int j = col >> 1;
                float a0 = acc[mt][nt][0], gg0 = acc[mt][nt][1];
                float a1 = acc[mt][nt][2], gg1 = acc[mt][nt][3];
                float v0 = a0 * (gg0 * 0.5f * (1.0f + erff(gg0 * 0.70710678118654752f)));
                float v1 = a1 * (gg1 * 0.5f * (1.0f + erff(gg1 * 0.70710678118654752f)));
                g_a[r0 * DFF + j] = __float2half(v0);
                g_a[r1 * DFF + j] = __float2half(v1);
            }
        }
        return;
    }

    if (mode == 2) {
        #pragma unroll
        for (int mt = 0; mt < 4; mt++) {
            int t0 = (int)bm + wm * 64 + mt * 16 + er;
            int t1 = t0 + 8;
            #pragma unroll
            for (int nt = 0; nt < 8; nt++) {
                int col = (int)bn + wn * 64 + nt * 8 + ec;
                uint32_t w0 = pack_h2(acc[mt][nt][0], acc[mt][nt][1]);
                uint32_t w1 = pack_h2(acc[mt][nt][2], acc[mt][nt][3]);
                if (col < 1536) {
                    *(uint32_t*)&g_qkvh[(size_t)t0 * 1536 + col] = w0;
                    *(uint32_t*)&g_qkvh[(size_t)t1 * 1536 + col] = w1;
                } else {
                    int h = (col - 1536) >> 6;
                    int e = col & 63;
                    *(uint32_t*)&g_vwh[win_addr(t0, h, e)] = w0;
                    *(uint32_t*)&g_vwh[win_addr(t1, h, e)] = w1;
                }
            }
        }
        return;
    }

    #pragma unroll
    for (int mt = 0; mt < 4; mt++) {
        size_t row0 = bm + wm * 64 + mt * 16 + er;
        #pragma unroll
        for (int nt = 0; nt < 8; nt++) {
            size_t col = bn + wn * 64 + nt * 8 + ec;
            float* p0 = C + row0 * (size_t)ldc + col;
            float* p1 = C + (row0 + 8) * (size_t)ldc + col;
            float2 v0 = make_float2(acc[mt][nt][0], acc[mt][nt][1]);
            float2 v1 = make_float2(acc[mt][nt][2], acc[mt][nt][3]);
            if (Dres) {
                const float2 d0 = *(const float2*)(Dres + row0 * (size_t)ldc + col);
                const float2 d1 = *(const float2*)(Dres + (row0 + 8) * (size_t)ldc + col);
                v0.x += d0.x; v0.y += d0.y; v1.x += d1.x; v1.y += d1.y;
            }
            *(float2*)p0 = v0;
            *(float2*)p1 = v1;
        }
    }
}

// ---------------------------------------------------------------------------
// K0: ada scales
// ---------------------------------------------------------------------------
__global__ void ada_kernel(const float* __restrict__ cond,
                           const float* __restrict__ w1,
                           const float* __restrict__ w2)
{
    int gw   = (blockIdx.x * blockDim.x + threadIdx.x) >> 5;
    int lane = threadIdx.x & 31;
    if (gw >= 2 * NBATCH * DM) return;
    int which = gw / (NBATCH * DM);
    int rem   = gw % (NBATCH * DM);
    int n = rem / DM, d = rem % DM;
    const float* w  = which ? w2 : w1;
    const float* cr = cond + n * DC;
    const float* wr = w + (size_t)d * DC;
    float s = 0.f;
    for (int i = lane; i < DC; i += 32) s += cr[i] * wr[i];
    #pragma unroll
    for (int o = 16; o; o >>= 1) s += __shfl_xor_sync(0xffffffffu, s, o);
    if (lane == 0) (which ? g_scale2 : g_scale1)[rem] = s + 1.0f;
}

// ---------------------------------------------------------------------------
// K1: RMSNorm * ada -> fp16.  One WARP per token (R16 proven).
// ---------------------------------------------------------------------------
__global__ __launch_bounds__(256) void rmsnorm_kernel(const float* __restrict__ x,
                                                      const float* __restrict__ scale)
{
    int t = blockIdx.x * 8 + (threadIdx.x >> 5);
    int lane = threadIdx.x & 31;
    int n = t >> 14;
    const float* xr = x + (size_t)t * DM;
    const float* sc = scale + (size_t)n * DM;

    float4 v[6];
    float ss = 0.f;
    #pragma unroll
    for (int j = 0; j < 6; j++) {
        v[j] = *(const float4*)(xr + (lane + j * 32) * 4);
        ss += v[j].x * v[j].x + v[j].y * v[j].y + v[j].z * v[j].z + v[j].w * v[j].w;
    }
    #pragma unroll
    for (int o = 16; o; o >>= 1) ss += __shfl_xor_sync(0xffffffffu, ss, o);
    float inv = rsqrtf(ss * (1.0f / DM) + EPSV);

    __half* orow = g_h + (size_t)t * DM;
    #pragma unroll
    for (int j = 0; j < 6; j++) {
        int c = (lane + j * 32) * 4;
        float4 s4 = *(const float4*)(sc + c);
        uint2 pk;
        pk.x = pack_h2(v[j].x * s4.x * inv, v[j].y * s4.y * inv);
        pk.y = pack_h2(v[j].z * s4.z * inv, v[j].w * s4.w * inv);
        *(uint2*)(orow + c) = pk;
    }
}

// ---------------------------------------------------------------------------
// K2: fused weight convert fp32 -> fp16 (all four weights, one launch)
// ---------------------------------------------------------------------------
__global__ __launch_bounds__(256) void wconv_all_kernel(const float* __restrict__ qkv_w,
                                                        const float* __restrict__ out_w,
                                                        const float* __restrict__ up_w,
                                                        const float* __restrict__ dn_w)
{
    const int OQKV = 0;
    const int OOUT = OQKV + W_QKV_SZ;
    const int OUP  = OOUT + W_OUT_SZ;
    const int ODN  = OUP + W_UP_SZ;

    for (int i = blockIdx.x * 256 + threadIdx.x; i < W_TOTAL; i += gridDim.x * 256) {
        float v; int dst;
        if (i < OOUT) {
            v = qkv_w[i - OQKV]; dst = i;
        } else if (i < OUP) {
            v = out_w[i - OOUT]; dst = i;
        } else if (i < ODN) {
            int li = i - OUP;
            v = up_w[li];
            int r = li / DM, c = li % DM;
            int dr = (r < DFF) ? (2 * r) : (2 * (r - DFF) + 1);
            dst = OUP + dr * DM + c;
        } else {
            v = dn_w[i - ODN]; dst = i;
        }
        g_w[dst] = __float2half(v);
    }
}

// ---------------------------------------------------------------------------
// K3: fused tensor-core attention (R15/R16 proven), all-fp16 data path.
// ---------------------------------------------------------------------------
#define AHP  72
#define AQH  0
#define AKH  (64 * AHP * 2)
#define AVH  (2 * 64 * AHP * 2)
#define ATT_SMEM (3 * 64 * AHP * 2)            // 27648

__global__ __launch_bounds__(128) void attn_kernel(const float* __restrict__ pos,
                                                   const float* __restrict__ attn_scale,
                                                   const float* __restrict__ rope_freqs)
{
    extern __shared__ __align__(16) char smc[];
    const uint32_t sb = smem_to_u32(smc);
    const uint32_t qh_b = sb + AQH, kh_b = sb + AKH, vh_b = sb + AVH;
    __half* qs = (__half*)(smc + AQH);
    __half* ks = (__half*)(smc + AKH);

    const int b   = blockIdx.x;
    const int rem = b % (NHEADS * 256);
    const int h   = rem >> 8;
    const int w   = rem & 255;
    const bool left = ((w & 15) == 0), top = ((w >> 4) == 0);
    const int tid = threadIdx.x, warp = tid >> 5, lane = tid & 31;

    const __half* vb = g_vwh + (size_t)b * 4096;
    for (int i = tid; i < 1024; i += 128) {
        int r = i >> 4, c4 = (i & 15) << 2;
        int t = win_token(b, r);
        const __half* qk = g_qkvh + (size_t)t * 1536 + h * DHEAD + c4;
        uint2 qv = *(const uint2*)qk;
        uint2 kv = *(const uint2*)(qk + DM);
        uint2 vv = *(const uint2*)(vb + (i << 2));
        *(uint2*)(smc + AQH + (r * AHP + c4) * 2) = qv;
        *(uint2*)(smc + AKH + (r * AHP + c4) * 2) = kv;
        *(uint2*)(smc + AVH + (r * AHP + c4) * 2) = vv;
    }
    __syncthreads();

    {
        int row = tid & 63;
        __half* prow = (tid < 64 ? qs : ks) + row * AHP;
        __half2* prow2 = (__half2*)prow;

        float ss = 0.f;
        #pragma unroll
        for (int e2 = 0; e2 < 32; e2++) {
            float2 f = __half22float2(prow2[e2]);
            ss += f.x * f.x + f.y * f.y;
        }
        float r = sqrtf(attn_scale[h]) * rsqrtf(ss + EPSV);

        int t = win_token(b, row);
        float p0 = pos[(size_t)t * 2 + 0];
        float p1 = pos[(size_t)t * 2 + 1];
        #pragma unroll
        for (int e = 0; e < 16; e++) {
            float freq = rope_freqs[h * 8 + (e & 7)];
            float th = (e < 8 ? p0 : p1) * freq;
            float c = cosf(th), s = sinf(th);
            float v1 = __half2float(prow[e]) * r;
            float v2 = __half2float(prow[e + 16]) * r;
            prow[e]      = __float2half(v1 * c - v2 * s);
            prow[e + 16] = __float2half(v2 * c + v1 * s);
        }
        #pragma unroll
        for (int e2 = 16; e2 < 32; e2++) {
            float2 f = __half22float2(prow2[e2]);
            prow2[e2] = __floats2half2_rn(f.x * r, f.y * r);
        }
    }
    __syncthreads();

    const int a_r = lane & 15, a_h2 = (lane >> 4) << 3;
    const int b_r = (lane & 7) + ((lane & 16) >> 1);
    const int b_k = lane & 8;

    float sc[8][4];
    #pragma unroll
    for (int nt = 0; nt < 8; nt++)
        #pragma unroll
        for (int j = 0; j < 4; j++) sc[nt][j] = 0.f;

    uint32_t afr[4][4];
    #pragma unroll
    for (int kt = 0; kt < 4; kt++)
        ldsm_x4(afr[kt][0], afr[kt][1], afr[kt][2], afr[kt][3],
                qh_b + (uint32_t)(((warp * 16 + a_r) * AHP + kt * 16 + a_h2) * 2));

    #pragma unroll
    for (int kt = 0; kt < 4; kt++) {
        uint32_t bh[8][2];
        #pragma unroll
        for (int p = 0; p < 4; p++) {
            uint32_t r0, r1, r2, r3;
            ldsm_x4(r0, r1, r2, r3,
                    kh_b + (uint32_t)(((p * 16 + b_r) * AHP + kt * 16 + b_k) * 2));
            bh[p * 2][0] = r0; bh[p * 2][1] = r1;
            bh[p * 2 + 1][0] = r2; bh[p * 2 + 1][1] = r3;
        }
        #pragma unroll
        for (int nt = 0; nt < 8; nt++)
            mma_f16(sc[nt], afr[kt], bh[nt]);
    }

    const int er = lane >> 2, ec = (lane & 3) * 2;
    const int r0 = warp * 16 + er, r1 = r0 + 8;
    const bool qa0 = ((r0 >> 3) < SHIFT), ql0 = ((r0 & 7) < SHIFT);
    const bool qa1 = ((r1 >> 3) < SHIFT), ql1 = ((r1 & 7) < SHIFT);

    float mx0 = -3.402823466e38f, mx1 = -3.402823466e38f;
    #pragma unroll
    for (int nt = 0; nt < 8; nt++) {
        bool ka = nt < SHIFT;
        #pragma unroll
        for (int j = 0; j < 2; j++) {
            bool kl = (ec + j) < SHIFT;
            bool m0 = (!left && !top)
                    || (left && top && (ql0 == kl) && (qa0 == ka))
                    || (left && !top && (ql0 == kl))
                    || (!left && top && (qa0 == ka));
            bool m1 = (!left && !top)
                    || (left && top && (ql1 == kl) && (qa1 == ka))
                    || (left && !top && (ql1 == kl))
                    || (!left && top && (qa1 == ka));
            if (!m0) sc[nt][j]     = -3.402823466e38f;
            if (!m1) sc[nt][2 + j] = -3.402823466e38f;
            mx0 = fmaxf(mx0, sc[nt][j]);
            mx1 = fmaxf(mx1, sc[nt][2 + j]);
        }
    }
    mx0 = fmaxf(mx0, __shfl_xor_sync(0xffffffffu, mx0, 1));
    mx0 = fmaxf(mx0, __shfl_xor_sync(0xffffffffu, mx0, 2));
    mx1 = fmaxf(mx1, __shfl_xor_sync(0xffffffffu, mx1, 1));
    mx1 = fmaxf(mx1, __shfl_xor_sync(0xffffffffu, mx1, 2));

    float s0 = 0.f, s1 = 0.f;
    #pragma unroll
    for (int nt = 0; nt < 8; nt++) {
        #pragma unroll
        for (int j = 0; j < 2; j++) {
            float p0v = __expf(sc[nt][j] - mx0);
            float p1v = __expf(sc[nt][2 + j] - mx1);
            sc[nt][j] = p0v; sc[nt][2 + j] = p1v;
            s0 += p0v; s1 += p1v;
        }
    }
    s0 += __shfl_xor_sync(0xffffffffu, s0, 1);
    s0 += __shfl_xor_sync(0xffffffffu, s0, 2);
    s1 += __shfl_xor_sync(0xffffffffu, s1, 1);
    s1 += __shfl_xor_sync(0xffffffffu, s1, 2);
    float inv0 = 1.0f / s0, inv1 = 1.0f / s1;

    uint32_t pf[4][4];
    #pragma unroll
    for (int kt = 0; kt < 4; kt++) {
        pf[kt][0] = pack_h2(sc[2 * kt][0],     sc[2 * kt][1]);
        pf[kt][1] = pack_h2(sc[2 * kt][2],     sc[2 * kt][3]);
        pf[kt][2] = pack_h2(sc[2 * kt + 1][0], sc[2 * kt + 1][1]);
        pf[kt][3] = pack_h2(sc[2 * kt + 1][2], sc[2 * kt + 1][3]);
    }

    float oo[8][4];
    #pragma unroll
    for (int nt = 0; nt < 8; nt++)
        #pragma unroll
        for (int j = 0; j < 4; j++) oo[nt][j] = 0.f;

    const int v_r = lane & 15, v_c = (lane >> 4) << 3;
    #pragma unroll
    for (int kt = 0; kt < 4; kt++) {
        uint32_t bv[8][2];
        #pragma unroll
        for (int p = 0; p < 4; p++) {
            uint32_t r0v, r1v, r2v, r3v;
            ldsm_x4_t(r0v, r1v, r2v, r3v,
                      vh_b + (uint32_t)(((kt * 16 + v_r) * AHP + p * 16 + v_c) * 2));
            bv[p * 2][0] = r0v; bv[p * 2][1] = r1v;
            bv[p * 2 + 1][0] = r2v; bv[p * 2 + 1][1] = r3v;
        }
        #pragma unroll
        for (int nt = 0; nt < 8; nt++)
            mma_f16(oo[nt], pf[kt], bv[nt]);
    }

    int t0 = win_token(b, r0), t1 = win_token(b, r1);
    #pragma unroll
    for (int nt = 0; nt < 8; nt++) {
        int col = h * DHEAD + nt * 8 + ec;
        uint32_t w0 = pack_h2(oo[nt][0] * inv0, oo[nt][1] * inv0);
        uint32_t w1 = pack_h2(oo[nt][2] * inv1, oo[nt][3] * inv1);
        *(uint32_t*)&g_oi[(size_t)t0 * DM + col] = w0;
        *(uint32_t*)&g_oi[(size_t)t1 * DM + col] = w1;
    }
}

// ---------------------------------------------------------------------------
// host
// ---------------------------------------------------------------------------
static void launch_hgemm(const __half* A, const __half* B,
                         const float* D, float* C, int M, int N, int K,
                         int ldc, int mode)
{
    dim3 grid(N / 128, M / 128);
    hgemm_kernel<<<grid, 128, GEMM_SMEM>>>(A, B, D, C, M, N, K, ldc, mode);
}

extern "C" void kernel_launch(void* const* d_in, const int* in_sizes, int n_in,
                              void* d_out, int out_size)
{
    const float* x          = (const float*)d_in[0];
    const float* pos        = (const float*)d_in[1];
    const float* cond       = (const float*)d_in[2];
    const float* ada1_w     = (const float*)d_in[3];
    const float* qkv_w      = (const float*)d_in[4];
    const float* attn_scale = (const float*)d_in[5];
    const float* rope_freqs = (const float*)d_in[6];
    const float* out_w      = (const float*)d_in[7];
    const float* ada2_w     = (const float*)d_in[8];
    const float* ff_up_w    = (const float*)d_in[9];
    const float* ff_down_w  = (const float*)d_in[10];
    float* out = (float*)d_out;

    cudaFuncSetAttribute(hgemm_kernel, cudaFuncAttributeMaxDynamicSharedMemorySize, GEMM_SMEM);
    cudaFuncSetAttribute(attn_kernel, cudaFuncAttributeMaxDynamicSharedMemorySize, ATT_SMEM);

    float *p_scale1, *p_scale2, *p_x2;
    __half *p_h, *p_oi, *p_a, *p_w;
    cudaGetSymbolAddress((void**)&p_scale1, g_scale1);
    cudaGetSymbolAddress((void**)&p_scale2, g_scale2);
    cudaGetSymbolAddress((void**)&p_x2,     g_x2);
    cudaGetSymbolAddress((void**)&p_h,      g_h);
    cudaGetSymbolAddress((void**)&p_oi,     g_oi);
    cudaGetSymbolAddress((void**)&p_a,      g_a);
    cudaGetSymbolAddress((void**)&p_w,      g_w);

    const int OQKV = 0;
    const int OOUT = OQKV + W_QKV_SZ;
    const int OUP  = OOUT + W_OUT_SZ;
    const int ODN  = OUP + W_UP_SZ;

    wconv_all_kernel<<<2048, 256>>>(qkv_w, out_w, ff_up_w, ff_down_w);

    ada_kernel<<<768, 256>>>(cond, ada1_w, ada2_w);
    rmsnorm_kernel<<<TOKENS / 8, 256>>>(x, p_scale1);
    // qkv: q,k -> g_qkvh fp16; v -> windowed fp16 g_vwh
    launch_hgemm(p_h, p_w + OQKV, nullptr, nullptr, TOKENS, 3 * DM, DM, 0, 2);
    // fused qk-transform + tensor-core attention + unwindow
    attn_kernel<<<NWIN, 128, ATT_SMEM>>>(pos, attn_scale, rope_freqs);
    launch_hgemm(p_oi, p_w + OOUT, x, p_x2, TOKENS, DM, DM, DM, 0);
    rmsnorm_kernel<<<TOKENS / 8, 256>>>(p_x2, p_scale2);
    // ff_up with fused gated GELU (interleaved weights) -> g_a
    launch_hgemm(p_h, p_w + OUP, nullptr, nullptr, TOKENS, 2 * DFF, DM, 2 * DFF, 1);
    launch_hgemm(p_a, p_w + ODN, p_x2, out, TOKENS, DM, DFF, DM, 0);
}